// round 7
// baseline (speedup 1.0000x reference)
#include <cuda_runtime.h>
#include <math.h>

#define NS   2048
#define NBAT 2
#define ND   768
#define NH   12
#define NDH  64
static const float SCORE_SCALE = 0.125f;   // 1/sqrt(64) * smoothing

// ---------------- scratch ----------------
__device__ float g_W5[5][768 * 768];                       // permuted weights [k][h*64+d]
__device__ float g_Q [4096 * 768];
__device__ float g_K [4096 * 768];
__device__ float g_V [4096 * 768];
__device__ float g_Qp[2048 * 768];
__device__ float g_Kp[2048 * 768];
__device__ float g_Einp[(size_t)2 * 12 * 2048 * 2048];     // exp(scores), unnormalized
__device__ float g_Epos[(size_t)12 * 2048 * 2048];
__device__ float g_sumI[2 * 12 * 2048];                    // row sums
__device__ float g_sumP[12 * 2048];
__device__ float g_AO[4096 * 768];

// ---------------- helpers ----------------
__device__ __forceinline__ unsigned f2tf(float x) {
    unsigned r; asm("cvt.rna.tf32.f32 %0, %1;" : "=r"(r) : "f"(x)); return r;
}
__device__ __forceinline__ float f2tff(float x) { return __uint_as_float(f2tf(x)); }
__device__ __forceinline__ void mma8(float c[4], const unsigned a[4], const unsigned b[2]) {
    asm volatile(
        "mma.sync.aligned.m16n8k8.row.col.f32.tf32.tf32.f32 "
        "{%0,%1,%2,%3},{%4,%5,%6,%7},{%8,%9},{%0,%1,%2,%3};"
        : "+f"(c[0]), "+f"(c[1]), "+f"(c[2]), "+f"(c[3])
        : "r"(a[0]), "r"(a[1]), "r"(a[2]), "r"(a[3]), "r"(b[0]), "r"(b[1]));
}

// ---------------- weight permutation (all 5 weights, one launch) ----------------
__global__ void permW_all(const float* __restrict__ W0, const float* __restrict__ W1,
                          const float* __restrict__ W2, const float* __restrict__ W3,
                          const float* __restrict__ W4, float* __restrict__ Wp) {
    int idx = blockIdx.x * 256 + threadIdx.x;
    if (idx >= 768 * 768) return;
    int w = blockIdx.y;
    const float* W = (w == 0) ? W0 : (w == 1) ? W1 : (w == 2) ? W2 : (w == 3) ? W3 : W4;
    int k = idx / 768;
    int oc = idx - k * 768;
    int h = oc >> 6, d = oc & 63;
    Wp[(size_t)w * (768 * 768) + idx] = W[k * 768 + d * 12 + h];
}

// ---------------- tf32 MMA GEMM: C[M,N]=A[M,K]@B[K,N], BM=64 BN=128 BK=32 ----------------
__global__ void __launch_bounds__(256) gemm_tf32(const float* __restrict__ A,
                                                 const float* __restrict__ B,
                                                 float* __restrict__ C,
                                                 int M, int N, int K) {
    __shared__ float As[64 * 36];
    __shared__ float Bs[32 * 132];
    int tid = threadIdx.x;
    int lane = tid & 31, wid = tid >> 5;
    int g = lane >> 2, t = lane & 3;
    int warpM = wid >> 2, warpN = wid & 3;        // 2 x 4 warps, 32x32 tiles
    int row0 = blockIdx.x * 64, col0 = blockIdx.y * 128;

    float c[2][4][4] = {};
    int ar = tid >> 3, ac = (tid & 7) * 4;
    int br = tid >> 5, bc = (tid & 31) * 4;

    for (int k0 = 0; k0 < K; k0 += 32) {
        float4 a0 = *(const float4*)(A + (size_t)(row0 + ar) * K + k0 + ac);
        float4 a1 = *(const float4*)(A + (size_t)(row0 + ar + 32) * K + k0 + ac);
        float* d0 = &As[ar * 36 + ac];
        d0[0] = f2tff(a0.x); d0[1] = f2tff(a0.y); d0[2] = f2tff(a0.z); d0[3] = f2tff(a0.w);
        float* d1 = &As[(ar + 32) * 36 + ac];
        d1[0] = f2tff(a1.x); d1[1] = f2tff(a1.y); d1[2] = f2tff(a1.z); d1[3] = f2tff(a1.w);
#pragma unroll
        for (int rr = 0; rr < 4; rr++) {
            int r = br + rr * 8;
            float4 bv = *(const float4*)(B + (size_t)(k0 + r) * N + col0 + bc);
            float* db = &Bs[r * 132 + bc];
            db[0] = f2tff(bv.x); db[1] = f2tff(bv.y); db[2] = f2tff(bv.z); db[3] = f2tff(bv.w);
        }
        __syncthreads();
        const unsigned* Au = (const unsigned*)As;
        const unsigned* Bu = (const unsigned*)Bs;
#pragma unroll
        for (int kk = 0; kk < 4; kk++) {
            int k8 = kk * 8;
            unsigned a[2][4], b[4][2];
#pragma unroll
            for (int mi = 0; mi < 2; mi++) {
                int m = warpM * 32 + mi * 16;
                a[mi][0] = Au[(m + g) * 36 + k8 + t];
                a[mi][1] = Au[(m + g + 8) * 36 + k8 + t];
                a[mi][2] = Au[(m + g) * 36 + k8 + t + 4];
                a[mi][3] = Au[(m + g + 8) * 36 + k8 + t + 4];
            }
#pragma unroll
            for (int ni = 0; ni < 4; ni++) {
                int n = warpN * 32 + ni * 8;
                b[ni][0] = Bu[(k8 + t) * 132 + n + g];
                b[ni][1] = Bu[(k8 + t + 4) * 132 + n + g];
            }
#pragma unroll
            for (int mi = 0; mi < 2; mi++)
#pragma unroll
                for (int ni = 0; ni < 4; ni++)
                    mma8(c[mi][ni], a[mi], b[ni]);
        }
        __syncthreads();
    }
#pragma unroll
    for (int mi = 0; mi < 2; mi++) {
#pragma unroll
        for (int ni = 0; ni < 4; ni++) {
            int row = row0 + warpM * 32 + mi * 16 + g;
            int col = col0 + warpN * 32 + ni * 8 + 2 * t;
            *(float2*)(C + (size_t)row * N + col) = make_float2(c[mi][ni][0], c[mi][ni][1]);
            *(float2*)(C + (size_t)(row + 8) * N + col) = make_float2(c[mi][ni][2], c[mi][ni][3]);
        }
    }
}

// ---------------- scores: E = exp(scale * Q K^T), plus row sums ----------------
__global__ void __launch_bounds__(256) score_exp(const float* __restrict__ Q,
                                                 const float* __restrict__ Km,
                                                 float* __restrict__ E,
                                                 float* __restrict__ sums) {
    extern __shared__ float sm[];
    float* Qs = sm;                 // 128*68
    float* Ks = sm + 128 * 68;      // 64*68
    float* rbuf = Ks + 64 * 68;     // 256
    int tid = threadIdx.x;
    int lane = tid & 31, wid = tid >> 5;
    int g = lane >> 2, t = lane & 3;
    int warpM = wid >> 1, warpN = wid & 1;      // 4 x 2, warp tile 32x32
    int i0 = blockIdx.x * 128;
    int h = blockIdx.y, b = blockIdx.z;
    int plane = b * NH + h;

    const float* qb = Q + ((size_t)b * NS + i0) * ND + h * NDH;
    const float* kb = Km + (size_t)b * NS * ND + h * NDH;
    float* Ep = E + (size_t)plane * NS * NS;

#pragma unroll
    for (int l = 0; l < 8; l++) {
        int idx = tid + l * 256;
        int r = idx >> 4, c = (idx & 15) * 4;
        float4 v = *(const float4*)(qb + (size_t)r * ND + c);
        float* d = &Qs[r * 68 + c];
        d[0] = f2tff(v.x); d[1] = f2tff(v.y); d[2] = f2tff(v.z); d[3] = f2tff(v.w);
    }

    float rs[2][2] = {};

    for (int jt = 0; jt < NS; jt += 64) {
#pragma unroll
        for (int l = 0; l < 4; l++) {
            int idx = tid + l * 256;
            int r = idx >> 4, c = (idx & 15) * 4;
            float4 v = *(const float4*)(kb + (size_t)(jt + r) * ND + c);
            float* d = &Ks[r * 68 + c];
            d[0] = f2tff(v.x); d[1] = f2tff(v.y); d[2] = f2tff(v.z); d[3] = f2tff(v.w);
        }
        __syncthreads();

        float c4[2][4][4] = {};
        const unsigned* Qu = (const unsigned*)Qs;
        const unsigned* Ku = (const unsigned*)Ks;
#pragma unroll
        for (int kk = 0; kk < 8; kk++) {
            int k8 = kk * 8;
            unsigned a[2][4], bfr[4][2];
#pragma unroll
            for (int mi = 0; mi < 2; mi++) {
                int m = warpM * 32 + mi * 16;
                a[mi][0] = Qu[(m + g) * 68 + k8 + t];
                a[mi][1] = Qu[(m + g + 8) * 68 + k8 + t];
                a[mi][2] = Qu[(m + g) * 68 + k8 + t + 4];
                a[mi][3] = Qu[(m + g + 8) * 68 + k8 + t + 4];
            }
#pragma unroll
            for (int ni = 0; ni < 4; ni++) {
                int n = warpN * 32 + ni * 8;
                bfr[ni][0] = Ku[(n + g) * 68 + k8 + t];
                bfr[ni][1] = Ku[(n + g) * 68 + k8 + t + 4];
            }
#pragma unroll
            for (int mi = 0; mi < 2; mi++)
#pragma unroll
                for (int ni = 0; ni < 4; ni++)
                    mma8(c4[mi][ni], a[mi], bfr[ni]);
        }
#pragma unroll
        for (int mi = 0; mi < 2; mi++) {
#pragma unroll
            for (int ni = 0; ni < 4; ni++) {
                float e0 = __expf(c4[mi][ni][0] * SCORE_SCALE);
                float e1 = __expf(c4[mi][ni][1] * SCORE_SCALE);
                float e2 = __expf(c4[mi][ni][2] * SCORE_SCALE);
                float e3 = __expf(c4[mi][ni][3] * SCORE_SCALE);
                rs[mi][0] += e0 + e1;
                rs[mi][1] += e2 + e3;
                int row = i0 + warpM * 32 + mi * 16 + g;
                int col = jt + warpN * 32 + ni * 8 + 2 * t;
                *(float2*)(Ep + (size_t)row * NS + col) = make_float2(e0, e1);
                *(float2*)(Ep + (size_t)(row + 8) * NS + col) = make_float2(e2, e3);
            }
        }
        __syncthreads();
    }

#pragma unroll
    for (int mi = 0; mi < 2; mi++)
#pragma unroll
        for (int hf = 0; hf < 2; hf++) {
            float v = rs[mi][hf];
            v += __shfl_xor_sync(0xffffffffu, v, 1);
            v += __shfl_xor_sync(0xffffffffu, v, 2);
            rs[mi][hf] = v;
        }
    if (t == 0) {
#pragma unroll
        for (int mi = 0; mi < 2; mi++)
#pragma unroll
            for (int hf = 0; hf < 2; hf++) {
                int r = warpM * 32 + mi * 16 + hf * 8 + g;
                rbuf[r * 2 + warpN] = rs[mi][hf];
            }
    }
    __syncthreads();
    if (tid < 128)
        sums[(size_t)plane * NS + i0 + tid] = rbuf[tid * 2] + rbuf[tid * 2 + 1];
}

// ---------------- fused blend + out_prob write + PV MMA ----------------
// grid (NS/32, NBAT), 256 thr. Per CTA: 32 i-rows, all 12 heads.
// smem: Vs[32][776] + Ps[12][1153] (per-head 32 x stride 36) + invI/invP[12*32]
#define PS_HSTRIDE 1153
#define VS_STRIDE  776
__global__ void __launch_bounds__(256) pv_blend(float* __restrict__ outP) {
    extern __shared__ float sm[];
    float* Vs    = sm;                        // 32*776 = 24832
    float* Ps    = Vs + 32 * VS_STRIDE;       // 12*1153 = 13836
    float* invIs = Ps + 12 * PS_HSTRIDE;      // 384
    float* invPs = invIs + 12 * 32;           // 384

    int tid = threadIdx.x;
    int lane = tid & 31, wid = tid >> 5;
    int g = lane >> 2, t = lane & 3;
    int warpM = wid >> 2, warpN = wid & 3;    // 2(m16) x 4(n16)
    int i0 = blockIdx.x * 32;
    int b = blockIdx.y;

    for (int f = tid; f < 12 * 32; f += 256) {
        int h = f >> 5, r = f & 31;
        invIs[f] = 0.5f / g_sumI[(size_t)(b * NH + h) * NS + i0 + r];
        invPs[f] = 0.5f / g_sumP[(size_t)h * NS + i0 + r];
    }
    __syncthreads();

    float acc[12][2][4];
#pragma unroll
    for (int h = 0; h < 12; h++)
#pragma unroll
        for (int ni = 0; ni < 2; ni++)
#pragma unroll
            for (int q = 0; q < 4; q++) acc[h][ni][q] = 0.f;

    int er = tid >> 3, ec4 = (tid & 7) * 4;   // E loader coords (per head)

    for (int jt = 0; jt < NS; jt += 32) {
        // V tile: rows jt..jt+32, all 768 cols (covers all 12 heads)
#pragma unroll
        for (int l = 0; l < 24; l++) {
            int f = tid + l * 256;
            int r = f / 192, cq = (f % 192) * 4;
            float4 v = *(const float4*)(g_V + ((size_t)(b * NS) + jt + r) * ND + cq);
            float4 o = make_float4(f2tff(v.x), f2tff(v.y), f2tff(v.z), f2tff(v.w));
            *(float4*)(Vs + r * VS_STRIDE + cq) = o;
        }
        // blend E tiles (one head per iteration; each thread one float4)
#pragma unroll
        for (int h = 0; h < 12; h++) {
            size_t offI = ((size_t)(b * NH + h) * NS + i0 + er) * NS + jt + ec4;
            size_t offP = ((size_t)h * NS + i0 + er) * NS + jt + ec4;
            float4 e1 = *(const float4*)(g_Einp + offI);
            float4 e2 = *(const float4*)(g_Epos + offP);
            float si = invIs[h * 32 + er], sp = invPs[h * 32 + er];
            float* d = Ps + h * PS_HSTRIDE + er * 36 + ec4;
            d[0] = f2tff(e1.x * si + e2.x * sp);
            d[1] = f2tff(e1.y * si + e2.y * sp);
            d[2] = f2tff(e1.z * si + e2.z * sp);
            d[3] = f2tff(e1.w * si + e2.w * sp);
        }
        __syncthreads();

        // write out_prob [b][i][j][h]: 32 rows x 384 contiguous floats
        {
            size_t base = ((size_t)(b * NS + i0)) * ((size_t)NS * NH) + (size_t)jt * NH;
#pragma unroll
            for (int l = 0; l < 48; l++) {
                int f = tid + l * 256;        // 0..12287
                int i = f / 384;
                int rem = f - i * 384;
                int jj = rem / 12;
                int h = rem - jj * 12;
                outP[base + (size_t)i * (NS * NH) + rem] =
                    Ps[h * PS_HSTRIDE + i * 36 + jj];
            }
        }

        // PV MMA: per head, warp does (m16 warpM) x (n16 warpN) over k=32
        const unsigned* Vu = (const unsigned*)Vs;
#pragma unroll
        for (int h = 0; h < 12; h++) {
            const unsigned* Au = (const unsigned*)(Ps + h * PS_HSTRIDE);
#pragma unroll
            for (int kk = 0; kk < 4; kk++) {
                int k8 = kk * 8;
                unsigned a[4];
                int m = warpM * 16;
                a[0] = Au[(m + g) * 36 + k8 + t];
                a[1] = Au[(m + g + 8) * 36 + k8 + t];
                a[2] = Au[(m + g) * 36 + k8 + t + 4];
                a[3] = Au[(m + g + 8) * 36 + k8 + t + 4];
#pragma unroll
                for (int ni = 0; ni < 2; ni++) {
                    int n = h * 64 + warpN * 16 + ni * 8;
                    unsigned bf[2];
                    bf[0] = Vu[(k8 + t) * VS_STRIDE + n + g];
                    bf[1] = Vu[(k8 + t + 4) * VS_STRIDE + n + g];
                    mma8(acc[h][ni], a, bf);
                }
            }
        }
        __syncthreads();
    }

    // epilogue: AO[b*NS + i][h*64 + d]
#pragma unroll
    for (int h = 0; h < 12; h++) {
#pragma unroll
        for (int ni = 0; ni < 2; ni++) {
            int row = i0 + warpM * 16 + g;
            int col = h * 64 + warpN * 16 + ni * 8 + 2 * t;
            float* dst = g_AO + ((size_t)(b * NS) + row) * ND + col;
            *(float2*)dst = make_float2(acc[h][ni][0], acc[h][ni][1]);
            *(float2*)(dst + (size_t)8 * ND) = make_float2(acc[h][ni][2], acc[h][ni][3]);
        }
    }
}

// ---------------- launch ----------------
extern "C" void kernel_launch(void* const* d_in, const int* in_sizes, int n_in,
                              void* d_out, int out_size) {
    (void)in_sizes; (void)n_in; (void)out_size;
    const float* inp    = (const float*)d_in[0];
    const float* pos    = (const float*)d_in[1];
    const float* Wq_inp = (const float*)d_in[2];
    const float* Wk_inp = (const float*)d_in[3];
    const float* Wq_pos = (const float*)d_in[4];
    const float* Wk_pos = (const float*)d_in[5];
    const float* Wv     = (const float*)d_in[6];
    const float* Wo     = (const float*)d_in[7];

    float* out      = (float*)d_out;
    float* out_attn = out;
    float* out_prob = out + (size_t)NBAT * NS * ND;

    float *pW5, *pQ, *pK, *pV, *pQp, *pKp, *pEi, *pEp, *pSi, *pSp, *pAO;
    cudaGetSymbolAddress((void**)&pW5, g_W5);
    cudaGetSymbolAddress((void**)&pQ,  g_Q);
    cudaGetSymbolAddress((void**)&pK,  g_K);
    cudaGetSymbolAddress((void**)&pV,  g_V);
    cudaGetSymbolAddress((void**)&pQp, g_Qp);
    cudaGetSymbolAddress((void**)&pKp, g_Kp);
    cudaGetSymbolAddress((void**)&pEi, g_Einp);
    cudaGetSymbolAddress((void**)&pEp, g_Epos);
    cudaGetSymbolAddress((void**)&pSi, g_sumI);
    cudaGetSymbolAddress((void**)&pSp, g_sumP);
    cudaGetSymbolAddress((void**)&pAO, g_AO);

    const int WELEM = 768 * 768;
    {
        dim3 g((WELEM + 255) / 256, 5);
        permW_all<<<g, 256>>>(Wq_inp, Wk_inp, Wq_pos, Wk_pos, Wv, pW5);
    }

    {
        dim3 gI(4096 / 64, 768 / 128);
        gemm_tf32<<<gI, 256>>>(inp, pW5 + 0 * WELEM, pQ, 4096, 768, 768);
        gemm_tf32<<<gI, 256>>>(inp, pW5 + 1 * WELEM, pK, 4096, 768, 768);
        gemm_tf32<<<gI, 256>>>(inp, pW5 + 4 * WELEM, pV, 4096, 768, 768);
        dim3 gP(2048 / 64, 768 / 128);
        gemm_tf32<<<gP, 256>>>(pos, pW5 + 2 * WELEM, pQp, 2048, 768, 768);
        gemm_tf32<<<gP, 256>>>(pos, pW5 + 3 * WELEM, pKp, 2048, 768, 768);
    }

    {
        int dynBytes = (128 * 68 + 64 * 68 + 256) * (int)sizeof(float);   // 53248
        cudaFuncSetAttribute(score_exp, cudaFuncAttributeMaxDynamicSharedMemorySize, dynBytes);
        dim3 gInp(NS / 128, NH, NBAT);
        score_exp<<<gInp, 256, dynBytes>>>(pQ, pK, pEi, pSi);
        dim3 gPos(NS / 128, NH, 1);
        score_exp<<<gPos, 256, dynBytes>>>(pQp, pKp, pEp, pSp);
    }

    {
        int dynBytes = (32 * VS_STRIDE + 12 * PS_HSTRIDE + 2 * 12 * 32) * (int)sizeof(float);
        cudaFuncSetAttribute(pv_blend, cudaFuncAttributeMaxDynamicSharedMemorySize, dynBytes);
        dim3 g(NS / 32, NBAT);
        pv_blend<<<g, 256, dynBytes>>>(out_prob);
    }

    {
        dim3 g(4096 / 64, 768 / 128);
        gemm_tf32<<<g, 256>>>(pAO, Wo, out_attn, 4096, 768, 768);
    }
}

// round 8
// speedup vs baseline: 1.1997x; 1.1997x over previous
#include <cuda_runtime.h>
#include <math.h>

#define NS   2048
#define NBAT 2
#define ND   768
#define NH   12
#define NDH  64
static const float SCORE_SCALE = 0.125f;   // 1/sqrt(64) * smoothing

// ---------------- scratch ----------------
__device__ float g_W5[5][768 * 768];                       // permuted weights [k][h*64+d]
__device__ float g_Q [4096 * 768];
__device__ float g_K [4096 * 768];
__device__ float g_V [4096 * 768];
__device__ float g_Qp[2048 * 768];
__device__ float g_Kp[2048 * 768];
__device__ float g_Einp[(size_t)2 * 12 * 2048 * 2048];     // exp(scores), unnormalized
__device__ float g_Epos[(size_t)12 * 2048 * 2048];
__device__ float g_sumI[2 * 12 * 2048];                    // row sums
__device__ float g_sumP[12 * 2048];
__device__ float g_AO[4096 * 768];

// ---------------- helpers ----------------
__device__ __forceinline__ unsigned f2tf(float x) {
    unsigned r; asm("cvt.rna.tf32.f32 %0, %1;" : "=r"(r) : "f"(x)); return r;
}
__device__ __forceinline__ float f2tff(float x) { return __uint_as_float(f2tf(x)); }
__device__ __forceinline__ void mma8(float c[4], const unsigned a[4], const unsigned b[2]) {
    asm volatile(
        "mma.sync.aligned.m16n8k8.row.col.f32.tf32.tf32.f32 "
        "{%0,%1,%2,%3},{%4,%5,%6,%7},{%8,%9},{%0,%1,%2,%3};"
        : "+f"(c[0]), "+f"(c[1]), "+f"(c[2]), "+f"(c[3])
        : "r"(a[0]), "r"(a[1]), "r"(a[2]), "r"(a[3]), "r"(b[0]), "r"(b[1]));
}

// ---------------- weight permutation (all 5 weights, one launch) ----------------
__global__ void permW_all(const float* __restrict__ W0, const float* __restrict__ W1,
                          const float* __restrict__ W2, const float* __restrict__ W3,
                          const float* __restrict__ W4, float* __restrict__ Wp) {
    int idx = blockIdx.x * 256 + threadIdx.x;
    if (idx >= 768 * 768) return;
    int w = blockIdx.y;
    const float* W = (w == 0) ? W0 : (w == 1) ? W1 : (w == 2) ? W2 : (w == 3) ? W3 : W4;
    int k = idx / 768;
    int oc = idx - k * 768;
    int h = oc >> 6, d = oc & 63;
    Wp[(size_t)w * (768 * 768) + idx] = W[k * 768 + d * 12 + h];
}

// ---------------- tf32 MMA GEMM with register-prefetch pipelining ----------------
// C[M,N]=A[M,K]@B[K,N], BM=64 BN=128 BK=32, 256 threads.
__global__ void __launch_bounds__(256) gemm_tf32(const float* __restrict__ A,
                                                 const float* __restrict__ B,
                                                 float* __restrict__ C,
                                                 int M, int N, int K) {
    __shared__ float As[64 * 36];
    __shared__ float Bs[32 * 132];
    int tid = threadIdx.x;
    int lane = tid & 31, wid = tid >> 5;
    int g = lane >> 2, t = lane & 3;
    int warpM = wid >> 2, warpN = wid & 3;        // 2 x 4 warps, 32x32 tiles
    int row0 = blockIdx.x * 64, col0 = blockIdx.y * 128;

    float c[2][4][4] = {};
    int ar = tid >> 3, ac = (tid & 7) * 4;
    int br = tid >> 5, bc = (tid & 31) * 4;

    const float* Ap0 = A + (size_t)(row0 + ar) * K + ac;
    const float* Ap1 = A + (size_t)(row0 + ar + 32) * K + ac;

    // prefetch k0 = 0
    float4 pa0 = *(const float4*)(Ap0);
    float4 pa1 = *(const float4*)(Ap1);
    float4 pb[4];
#pragma unroll
    for (int rr = 0; rr < 4; rr++)
        pb[rr] = *(const float4*)(B + (size_t)(br + rr * 8) * N + col0 + bc);

    for (int k0 = 0; k0 < K; k0 += 32) {
        // STS current tile (with tf32 rounding)
        float* d0 = &As[ar * 36 + ac];
        d0[0] = f2tff(pa0.x); d0[1] = f2tff(pa0.y); d0[2] = f2tff(pa0.z); d0[3] = f2tff(pa0.w);
        float* d1 = &As[(ar + 32) * 36 + ac];
        d1[0] = f2tff(pa1.x); d1[1] = f2tff(pa1.y); d1[2] = f2tff(pa1.z); d1[3] = f2tff(pa1.w);
#pragma unroll
        for (int rr = 0; rr < 4; rr++) {
            float* db = &Bs[(br + rr * 8) * 132 + bc];
            db[0] = f2tff(pb[rr].x); db[1] = f2tff(pb[rr].y);
            db[2] = f2tff(pb[rr].z); db[3] = f2tff(pb[rr].w);
        }
        __syncthreads();

        // prefetch next tile (overlaps with MMA below)
        if (k0 + 32 < K) {
            pa0 = *(const float4*)(Ap0 + k0 + 32);
            pa1 = *(const float4*)(Ap1 + k0 + 32);
#pragma unroll
            for (int rr = 0; rr < 4; rr++)
                pb[rr] = *(const float4*)(B + (size_t)(k0 + 32 + br + rr * 8) * N + col0 + bc);
        }

        const unsigned* Au = (const unsigned*)As;
        const unsigned* Bu = (const unsigned*)Bs;
#pragma unroll
        for (int kk = 0; kk < 4; kk++) {
            int k8 = kk * 8;
            unsigned a[2][4], b[4][2];
#pragma unroll
            for (int mi = 0; mi < 2; mi++) {
                int m = warpM * 32 + mi * 16;
                a[mi][0] = Au[(m + g) * 36 + k8 + t];
                a[mi][1] = Au[(m + g + 8) * 36 + k8 + t];
                a[mi][2] = Au[(m + g) * 36 + k8 + t + 4];
                a[mi][3] = Au[(m + g + 8) * 36 + k8 + t + 4];
            }
#pragma unroll
            for (int ni = 0; ni < 4; ni++) {
                int n = warpN * 32 + ni * 8;
                b[ni][0] = Bu[(k8 + t) * 132 + n + g];
                b[ni][1] = Bu[(k8 + t + 4) * 132 + n + g];
            }
#pragma unroll
            for (int mi = 0; mi < 2; mi++)
#pragma unroll
                for (int ni = 0; ni < 4; ni++)
                    mma8(c[mi][ni], a[mi], b[ni]);
        }
        __syncthreads();
    }
#pragma unroll
    for (int mi = 0; mi < 2; mi++) {
#pragma unroll
        for (int ni = 0; ni < 4; ni++) {
            int row = row0 + warpM * 32 + mi * 16 + g;
            int col = col0 + warpN * 32 + ni * 8 + 2 * t;
            *(float2*)(C + (size_t)row * N + col) = make_float2(c[mi][ni][0], c[mi][ni][1]);
            *(float2*)(C + (size_t)(row + 8) * N + col) = make_float2(c[mi][ni][2], c[mi][ni][3]);
        }
    }
}

// ---------------- scores: E = exp(scale * Q K^T), plus row sums (prefetched) ----------------
__global__ void __launch_bounds__(256) score_exp(const float* __restrict__ Q,
                                                 const float* __restrict__ Km,
                                                 float* __restrict__ E,
                                                 float* __restrict__ sums) {
    extern __shared__ float sm[];
    float* Qs = sm;                 // 128*68
    float* Ks = sm + 128 * 68;      // 64*68
    float* rbuf = Ks + 64 * 68;     // 256
    int tid = threadIdx.x;
    int lane = tid & 31, wid = tid >> 5;
    int g = lane >> 2, t = lane & 3;
    int warpM = wid >> 1, warpN = wid & 1;      // 4 x 2, warp tile 32x32
    int i0 = blockIdx.x * 128;
    int h = blockIdx.y, b = blockIdx.z;
    int plane = b * NH + h;

    const float* qb = Q + ((size_t)b * NS + i0) * ND + h * NDH;
    const float* kb = Km + (size_t)b * NS * ND + h * NDH;
    float* Ep = E + (size_t)plane * NS * NS;

    // load Q tile 128x64 (covered by first __syncthreads in loop)
#pragma unroll
    for (int l = 0; l < 8; l++) {
        int idx = tid + l * 256;
        int r = idx >> 4, c = (idx & 15) * 4;
        float4 v = *(const float4*)(qb + (size_t)r * ND + c);
        float* d = &Qs[r * 68 + c];
        d[0] = f2tff(v.x); d[1] = f2tff(v.y); d[2] = f2tff(v.z); d[3] = f2tff(v.w);
    }

    float rs[2][2] = {};
    int kr = tid >> 4, kc = (tid & 15) * 4;   // K loader coords (per l: row kr + l*16... see below)

    // prefetch K tile jt=0: 4 float4 per thread
    float4 pk[4];
#pragma unroll
    for (int l = 0; l < 4; l++) {
        int idx = tid + l * 256;
        int r = idx >> 4, c = (idx & 15) * 4;
        pk[l] = *(const float4*)(kb + (size_t)r * ND + c);
    }
    (void)kr; (void)kc;

    for (int jt = 0; jt < NS; jt += 64) {
#pragma unroll
        for (int l = 0; l < 4; l++) {
            int idx = tid + l * 256;
            int r = idx >> 4, c = (idx & 15) * 4;
            float* d = &Ks[r * 68 + c];
            d[0] = f2tff(pk[l].x); d[1] = f2tff(pk[l].y); d[2] = f2tff(pk[l].z); d[3] = f2tff(pk[l].w);
        }
        __syncthreads();

        if (jt + 64 < NS) {
#pragma unroll
            for (int l = 0; l < 4; l++) {
                int idx = tid + l * 256;
                int r = idx >> 4, c = (idx & 15) * 4;
                pk[l] = *(const float4*)(kb + (size_t)(jt + 64 + r) * ND + c);
            }
        }

        float c4[2][4][4] = {};
        const unsigned* Qu = (const unsigned*)Qs;
        const unsigned* Ku = (const unsigned*)Ks;
#pragma unroll
        for (int kk = 0; kk < 8; kk++) {
            int k8 = kk * 8;
            unsigned a[2][4], bfr[4][2];
#pragma unroll
            for (int mi = 0; mi < 2; mi++) {
                int m = warpM * 32 + mi * 16;
                a[mi][0] = Qu[(m + g) * 68 + k8 + t];
                a[mi][1] = Qu[(m + g + 8) * 68 + k8 + t];
                a[mi][2] = Qu[(m + g) * 68 + k8 + t + 4];
                a[mi][3] = Qu[(m + g + 8) * 68 + k8 + t + 4];
            }
#pragma unroll
            for (int ni = 0; ni < 4; ni++) {
                int n = warpN * 32 + ni * 8;
                bfr[ni][0] = Ku[(n + g) * 68 + k8 + t];
                bfr[ni][1] = Ku[(n + g) * 68 + k8 + t + 4];
            }
#pragma unroll
            for (int mi = 0; mi < 2; mi++)
#pragma unroll
                for (int ni = 0; ni < 4; ni++)
                    mma8(c4[mi][ni], a[mi], bfr[ni]);
        }
#pragma unroll
        for (int mi = 0; mi < 2; mi++) {
#pragma unroll
            for (int ni = 0; ni < 4; ni++) {
                float e0 = __expf(c4[mi][ni][0] * SCORE_SCALE);
                float e1 = __expf(c4[mi][ni][1] * SCORE_SCALE);
                float e2 = __expf(c4[mi][ni][2] * SCORE_SCALE);
                float e3 = __expf(c4[mi][ni][3] * SCORE_SCALE);
                rs[mi][0] += e0 + e1;
                rs[mi][1] += e2 + e3;
                int row = i0 + warpM * 32 + mi * 16 + g;
                int col = jt + warpN * 32 + ni * 8 + 2 * t;
                *(float2*)(Ep + (size_t)row * NS + col) = make_float2(e0, e1);
                *(float2*)(Ep + (size_t)(row + 8) * NS + col) = make_float2(e2, e3);
            }
        }
        __syncthreads();
    }

#pragma unroll
    for (int mi = 0; mi < 2; mi++)
#pragma unroll
        for (int hf = 0; hf < 2; hf++) {
            float v = rs[mi][hf];
            v += __shfl_xor_sync(0xffffffffu, v, 1);
            v += __shfl_xor_sync(0xffffffffu, v, 2);
            rs[mi][hf] = v;
        }
    if (t == 0) {
#pragma unroll
        for (int mi = 0; mi < 2; mi++)
#pragma unroll
            for (int hf = 0; hf < 2; hf++) {
                int r = warpM * 32 + mi * 16 + hf * 8 + g;
                rbuf[r * 2 + warpN] = rs[mi][hf];
            }
    }
    __syncthreads();
    if (tid < 128)
        sums[(size_t)plane * NS + i0 + tid] = rbuf[tid * 2] + rbuf[tid * 2 + 1];
}

// ---------------- blend + interleave into [b][i][j][h] ----------------
__global__ void __launch_bounds__(256) blend_kernel(float* __restrict__ outP) {
    __shared__ float sb[12 * 515];
    __shared__ float sIs[12], sPs[12];
    int b = blockIdx.x, i = blockIdx.y;
    int tid = threadIdx.x;
    if (tid < 12) sIs[tid] = 0.5f / g_sumI[(b * 12 + tid) * NS + i];
    else if (tid < 24) sPs[tid - 12] = 0.5f / g_sumP[(tid - 12) * NS + i];
    __syncthreads();
    size_t outBase = ((size_t)(b * NS + i)) * ((size_t)NS * NH);
    for (int jt = 0; jt < NS; jt += 512) {
#pragma unroll
        for (int l = 0; l < 24; l++) {
            int e = tid + l * 256;
            int h = e >> 9, j = e & 511;
            size_t idxI = ((size_t)(b * NH + h) * NS + i) * NS + jt + j;
            size_t idxP = ((size_t)h * NS + i) * NS + jt + j;
            sb[h * 515 + j] = g_Einp[idxI] * sIs[h] + g_Epos[idxP] * sPs[h];
        }
        __syncthreads();
#pragma unroll
        for (int l = 0; l < 24; l++) {
            int e = tid + l * 256;
            int j = e / 12, h = e - j * 12;
            outP[outBase + (size_t)jt * NH + e] = sb[h * 515 + j];
        }
        __syncthreads();
    }
}

// ---------------- PV (tf32 MMA, prefetched): AO = blend(P) @ V ----------------
// grid: (NS/64, NBAT, NH). CTA tile 64(i) x 64(d), K loop over j in 32-chunks.
__global__ void __launch_bounds__(256) pv_mma() {
    __shared__ float As[64 * 36];
    __shared__ float Vs[32 * 68];
    __shared__ float invI[64], invP[64];
    int tid = threadIdx.x;
    int lane = tid & 31, wid = tid >> 5;
    int g = lane >> 2, t = lane & 3;
    int warpM = wid >> 1, warpN = wid & 1;       // 4 x 2, warp tile 16x32
    int i0 = blockIdx.x * 64;
    int b = blockIdx.y, h = blockIdx.z;
    int plane = b * NH + h;

    const float* Ei = g_Einp + (size_t)plane * NS * NS;
    const float* Epp = g_Epos + (size_t)h * NS * NS;
    const float* Vb = g_V + (size_t)b * NS * ND + h * NDH;

    if (tid < 64) invI[tid] = 0.5f / g_sumI[(size_t)plane * NS + i0 + tid];
    else if (tid < 128) invP[tid - 64] = 0.5f / g_sumP[(size_t)h * NS + i0 + tid - 64];
    __syncthreads();

    float c4[4][4] = {};
    int ar = tid >> 3, ac = (tid & 7) * 4;   // A loader rows ar, ar+32 (i), cols j

    // prefetch k0 = 0
    float4 pe1[2], pe2[2], pv[2];
#pragma unroll
    for (int rr = 0; rr < 2; rr++) {
        size_t off = (size_t)(i0 + ar + rr * 32) * NS + ac;
        pe1[rr] = *(const float4*)(Ei + off);
        pe2[rr] = *(const float4*)(Epp + off);
    }
#pragma unroll
    for (int l = 0; l < 2; l++) {
        int f = tid + l * 256;
        int r = f >> 4, c = (f & 15) * 4;
        pv[l] = *(const float4*)(Vb + (size_t)r * ND + c);
    }

    for (int k0 = 0; k0 < NS; k0 += 32) {
        // STS current
#pragma unroll
        for (int rr = 0; rr < 2; rr++) {
            int r = ar + rr * 32;
            float si = invI[r], sp = invP[r];
            float* d = &As[r * 36 + ac];
            d[0] = f2tff(pe1[rr].x * si + pe2[rr].x * sp);
            d[1] = f2tff(pe1[rr].y * si + pe2[rr].y * sp);
            d[2] = f2tff(pe1[rr].z * si + pe2[rr].z * sp);
            d[3] = f2tff(pe1[rr].w * si + pe2[rr].w * sp);
        }
#pragma unroll
        for (int l = 0; l < 2; l++) {
            int f = tid + l * 256;
            int r = f >> 4, c = (f & 15) * 4;
            float* dv = &Vs[r * 68 + c];
            dv[0] = f2tff(pv[l].x); dv[1] = f2tff(pv[l].y);
            dv[2] = f2tff(pv[l].z); dv[3] = f2tff(pv[l].w);
        }
        __syncthreads();

        // prefetch next
        if (k0 + 32 < NS) {
#pragma unroll
            for (int rr = 0; rr < 2; rr++) {
                size_t off = (size_t)(i0 + ar + rr * 32) * NS + k0 + 32 + ac;
                pe1[rr] = *(const float4*)(Ei + off);
                pe2[rr] = *(const float4*)(Epp + off);
            }
#pragma unroll
            for (int l = 0; l < 2; l++) {
                int f = tid + l * 256;
                int r = f >> 4, c = (f & 15) * 4;
                pv[l] = *(const float4*)(Vb + (size_t)(k0 + 32 + r) * ND + c);
            }
        }

        const unsigned* Au = (const unsigned*)As;
        const unsigned* Vu = (const unsigned*)Vs;
#pragma unroll
        for (int kk = 0; kk < 4; kk++) {
            int k8 = kk * 8;
            unsigned a[4], bfr[4][2];
            int m = warpM * 16;
            a[0] = Au[(m + g) * 36 + k8 + t];
            a[1] = Au[(m + g + 8) * 36 + k8 + t];
            a[2] = Au[(m + g) * 36 + k8 + t + 4];
            a[3] = Au[(m + g + 8) * 36 + k8 + t + 4];
#pragma unroll
            for (int ni = 0; ni < 4; ni++) {
                int n = warpN * 32 + ni * 8;
                bfr[ni][0] = Vu[(k8 + t) * 68 + n + g];
                bfr[ni][1] = Vu[(k8 + t + 4) * 68 + n + g];
            }
#pragma unroll
            for (int ni = 0; ni < 4; ni++)
                mma8(c4[ni], a, bfr[ni]);
        }
        __syncthreads();
    }
#pragma unroll
    for (int ni = 0; ni < 4; ni++) {
        int row = i0 + warpM * 16 + g;
        int col = warpN * 32 + ni * 8 + 2 * t;
        float* dst = g_AO + (size_t)(b * NS + row) * ND + h * NDH + col;
        *(float2*)dst = make_float2(c4[ni][0], c4[ni][1]);
        *(float2*)(dst + (size_t)8 * ND) = make_float2(c4[ni][2], c4[ni][3]);
    }
}

// ---------------- launch ----------------
extern "C" void kernel_launch(void* const* d_in, const int* in_sizes, int n_in,
                              void* d_out, int out_size) {
    (void)in_sizes; (void)n_in; (void)out_size;
    const float* inp    = (const float*)d_in[0];
    const float* pos    = (const float*)d_in[1];
    const float* Wq_inp = (const float*)d_in[2];
    const float* Wk_inp = (const float*)d_in[3];
    const float* Wq_pos = (const float*)d_in[4];
    const float* Wk_pos = (const float*)d_in[5];
    const float* Wv     = (const float*)d_in[6];
    const float* Wo     = (const float*)d_in[7];

    float* out      = (float*)d_out;
    float* out_attn = out;
    float* out_prob = out + (size_t)NBAT * NS * ND;

    float *pW5, *pQ, *pK, *pV, *pQp, *pKp, *pEi, *pEp, *pSi, *pSp, *pAO;
    cudaGetSymbolAddress((void**)&pW5, g_W5);
    cudaGetSymbolAddress((void**)&pQ,  g_Q);
    cudaGetSymbolAddress((void**)&pK,  g_K);
    cudaGetSymbolAddress((void**)&pV,  g_V);
    cudaGetSymbolAddress((void**)&pQp, g_Qp);
    cudaGetSymbolAddress((void**)&pKp, g_Kp);
    cudaGetSymbolAddress((void**)&pEi, g_Einp);
    cudaGetSymbolAddress((void**)&pEp, g_Epos);
    cudaGetSymbolAddress((void**)&pSi, g_sumI);
    cudaGetSymbolAddress((void**)&pSp, g_sumP);
    cudaGetSymbolAddress((void**)&pAO, g_AO);

    const int WELEM = 768 * 768;
    {
        dim3 g((WELEM + 255) / 256, 5);
        permW_all<<<g, 256>>>(Wq_inp, Wk_inp, Wq_pos, Wk_pos, Wv, pW5);
    }

    {
        dim3 gI(4096 / 64, 768 / 128);
        gemm_tf32<<<gI, 256>>>(inp, pW5 + 0 * WELEM, pQ, 4096, 768, 768);
        gemm_tf32<<<gI, 256>>>(inp, pW5 + 1 * WELEM, pK, 4096, 768, 768);
        gemm_tf32<<<gI, 256>>>(inp, pW5 + 4 * WELEM, pV, 4096, 768, 768);
        dim3 gP(2048 / 64, 768 / 128);
        gemm_tf32<<<gP, 256>>>(pos, pW5 + 2 * WELEM, pQp, 2048, 768, 768);
        gemm_tf32<<<gP, 256>>>(pos, pW5 + 3 * WELEM, pKp, 2048, 768, 768);
    }

    {
        int dynBytes = (128 * 68 + 64 * 68 + 256) * (int)sizeof(float);   // 53248
        cudaFuncSetAttribute(score_exp, cudaFuncAttributeMaxDynamicSharedMemorySize, dynBytes);
        dim3 gInp(NS / 128, NH, NBAT);
        score_exp<<<gInp, 256, dynBytes>>>(pQ, pK, pEi, pSi);
        dim3 gPos(NS / 128, NH, 1);
        score_exp<<<gPos, 256, dynBytes>>>(pQp, pKp, pEp, pSp);
    }

    {
        dim3 g(NBAT, NS);
        blend_kernel<<<g, 256>>>(out_prob);
    }

    {
        dim3 g(NS / 64, NBAT, NH);
        pv_mma<<<g, 256>>>();
    }

    {
        dim3 g(4096 / 64, 768 / 128);
        gemm_tf32<<<g, 256>>>(pAO, Wo, out_attn, 4096, 768, 768);
    }
}

// round 9
// speedup vs baseline: 1.2127x; 1.0108x over previous
#include <cuda_runtime.h>
#include <math.h>

#define NS   2048
#define NBAT 2
#define ND   768
#define NH   12
#define NDH  64
static const float SCORE_SCALE = 0.125f;   // 1/sqrt(64) * smoothing

// ---------------- scratch ----------------
__device__ float g_W5[5][768 * 768];                       // permuted weights, tf32-rounded
__device__ float g_Ain[4096 * 768];                        // tf32-rounded inp
__device__ float g_Pin[2048 * 768];                        // tf32-rounded pos_emb
__device__ float g_WoR[768 * 768];                         // tf32-rounded Wo
__device__ float g_Q [4096 * 768];                         // tf32-rounded
__device__ float g_K [4096 * 768];
__device__ float g_V [4096 * 768];
__device__ float g_Qp[2048 * 768];
__device__ float g_Kp[2048 * 768];
__device__ float g_Einp[(size_t)2 * 12 * 2048 * 2048];     // exp(scores), fp32
__device__ float g_Epos[(size_t)12 * 2048 * 2048];
__device__ float g_sumI[2 * 12 * 2048];
__device__ float g_sumP[12 * 2048];
__device__ float g_AO[4096 * 768];                         // tf32-rounded

// ---------------- helpers ----------------
__device__ __forceinline__ unsigned f2tf(float x) {
    unsigned r; asm("cvt.rna.tf32.f32 %0, %1;" : "=r"(r) : "f"(x)); return r;
}
__device__ __forceinline__ float f2tff(float x) { return __uint_as_float(f2tf(x)); }
__device__ __forceinline__ void mma8(float c[4], const unsigned a[4], const unsigned b[2]) {
    asm volatile(
        "mma.sync.aligned.m16n8k8.row.col.f32.tf32.tf32.f32 "
        "{%0,%1,%2,%3},{%4,%5,%6,%7},{%8,%9},{%0,%1,%2,%3};"
        : "+f"(c[0]), "+f"(c[1]), "+f"(c[2]), "+f"(c[3])
        : "r"(a[0]), "r"(a[1]), "r"(a[2]), "r"(a[3]), "r"(b[0]), "r"(b[1]));
}
__device__ __forceinline__ void cpa16(unsigned s, const void* g) {
    asm volatile("cp.async.ca.shared.global [%0], [%1], 16;" :: "r"(s), "l"(g));
}
#define CPA_COMMIT asm volatile("cp.async.commit_group;")
#define CPA_WAIT0  asm volatile("cp.async.wait_group 0;")

// ---------------- elementwise tf32 round-copy ----------------
__global__ void round_copy(const float* __restrict__ src, float* __restrict__ dst, int n4) {
    int i = blockIdx.x * 256 + threadIdx.x;
    if (i >= n4) return;
    float4 v = ((const float4*)src)[i];
    float4 o = make_float4(f2tff(v.x), f2tff(v.y), f2tff(v.z), f2tff(v.w));
    ((float4*)dst)[i] = o;
}

// ---------------- weight permutation (all 5 weights, tf32-rounded) ----------------
__global__ void permW_all(const float* __restrict__ W0, const float* __restrict__ W1,
                          const float* __restrict__ W2, const float* __restrict__ W3,
                          const float* __restrict__ W4, float* __restrict__ Wp) {
    int idx = blockIdx.x * 256 + threadIdx.x;
    if (idx >= 768 * 768) return;
    int w = blockIdx.y;
    const float* W = (w == 0) ? W0 : (w == 1) ? W1 : (w == 2) ? W2 : (w == 3) ? W3 : W4;
    int k = idx / 768;
    int oc = idx - k * 768;
    int h = oc >> 6, d = oc & 63;
    Wp[(size_t)w * (768 * 768) + idx] = f2tff(W[k * 768 + d * 12 + h]);
}

// ---------------- tf32 MMA GEMM, cp.async double-buffered ----------------
// C[M,N]=A[M,K]@B[K,N], BM=64 BN=128 BK=32, 256 threads. A,B pre-rounded tf32.
// dyn smem: As[2][64*36] + Bs[2][32*132] = 52224 B
template <bool RND>
__global__ void __launch_bounds__(256) gemm_tf32(const float* __restrict__ A,
                                                 const float* __restrict__ B,
                                                 float* __restrict__ C,
                                                 int M, int N, int K) {
    extern __shared__ float sm[];
    float* As = sm;                 // 2 x 64*36
    float* Bs = sm + 2 * 64 * 36;   // 2 x 32*132
    int tid = threadIdx.x;
    int lane = tid & 31, wid = tid >> 5;
    int g = lane >> 2, t = lane & 3;
    int warpM = wid >> 2, warpN = wid & 3;        // 2 x 4 warps, 32x32 tiles
    int row0 = blockIdx.x * 64, col0 = blockIdx.y * 128;

    float c[2][4][4] = {};
    int ar = tid >> 3, ac = (tid & 7) * 4;
    int br = tid >> 5, bc = (tid & 31) * 4;

    const float* Ap0 = A + (size_t)(row0 + ar) * K + ac;
    const float* Ap1 = A + (size_t)(row0 + ar + 32) * K + ac;
    const float* Bp  = B + col0 + bc;

    unsigned sA = (unsigned)__cvta_generic_to_shared(As);
    unsigned sB = (unsigned)__cvta_generic_to_shared(Bs);
    unsigned aOff0 = (ar * 36 + ac) * 4, aOff1 = ((ar + 32) * 36 + ac) * 4;
    unsigned bOff  = (br * 132 + bc) * 4;

    // prefetch tile 0 into buffer 0
    cpa16(sA + aOff0, Ap0);
    cpa16(sA + aOff1, Ap1);
#pragma unroll
    for (int rr = 0; rr < 4; rr++)
        cpa16(sB + bOff + rr * (8 * 132 * 4), Bp + (size_t)(br + rr * 8) * N);
    CPA_COMMIT;

    int buf = 0;
    for (int k0 = 0; k0 < K; k0 += 32, buf ^= 1) {
        CPA_WAIT0;
        __syncthreads();
        if (k0 + 32 < K) {
            unsigned o = (buf ^ 1) ? (unsigned)(64 * 36 * 4) : 0u;
            unsigned ob = (buf ^ 1) ? (unsigned)(32 * 132 * 4) : 0u;
            cpa16(sA + o + aOff0, Ap0 + k0 + 32);
            cpa16(sA + o + aOff1, Ap1 + k0 + 32);
#pragma unroll
            for (int rr = 0; rr < 4; rr++)
                cpa16(sB + ob + bOff + rr * (8 * 132 * 4),
                      Bp + (size_t)(k0 + 32 + br + rr * 8) * N);
            CPA_COMMIT;
        }
        const unsigned* Au = (const unsigned*)(As + buf * (64 * 36));
        const unsigned* Bu = (const unsigned*)(Bs + buf * (32 * 132));
#pragma unroll
        for (int kk = 0; kk < 4; kk++) {
            int k8 = kk * 8;
            unsigned a[2][4], b[4][2];
#pragma unroll
            for (int mi = 0; mi < 2; mi++) {
                int m = warpM * 32 + mi * 16;
                a[mi][0] = Au[(m + g) * 36 + k8 + t];
                a[mi][1] = Au[(m + g + 8) * 36 + k8 + t];
                a[mi][2] = Au[(m + g) * 36 + k8 + t + 4];
                a[mi][3] = Au[(m + g + 8) * 36 + k8 + t + 4];
            }
#pragma unroll
            for (int ni = 0; ni < 4; ni++) {
                int n = warpN * 32 + ni * 8;
                b[ni][0] = Bu[(k8 + t) * 132 + n + g];
                b[ni][1] = Bu[(k8 + t + 4) * 132 + n + g];
            }
#pragma unroll
            for (int mi = 0; mi < 2; mi++)
#pragma unroll
                for (int ni = 0; ni < 4; ni++)
                    mma8(c[mi][ni], a[mi], b[ni]);
        }
        __syncthreads();
    }
#pragma unroll
    for (int mi = 0; mi < 2; mi++) {
#pragma unroll
        for (int ni = 0; ni < 4; ni++) {
            int row = row0 + warpM * 32 + mi * 16 + g;
            int col = col0 + warpN * 32 + ni * 8 + 2 * t;
            float2 v0, v1;
            if (RND) {
                v0 = make_float2(f2tff(c[mi][ni][0]), f2tff(c[mi][ni][1]));
                v1 = make_float2(f2tff(c[mi][ni][2]), f2tff(c[mi][ni][3]));
            } else {
                v0 = make_float2(c[mi][ni][0], c[mi][ni][1]);
                v1 = make_float2(c[mi][ni][2], c[mi][ni][3]);
            }
            *(float2*)(C + (size_t)row * N + col) = v0;
            *(float2*)(C + (size_t)(row + 8) * N + col) = v1;
        }
    }
}

// ---------------- scores: E = exp(scale * Q K^T) + row sums, cp.async K stream ----------------
// Q/K pre-rounded tf32. dyn smem: Qs[128*68] + Ks[2][64*68] + rbuf[256] = 70656 B
__global__ void __launch_bounds__(256) score_exp(const float* __restrict__ Q,
                                                 const float* __restrict__ Km,
                                                 float* __restrict__ E,
                                                 float* __restrict__ sums) {
    extern __shared__ float sm[];
    float* Qs = sm;                      // 128*68
    float* Ks = sm + 128 * 68;           // 2 x 64*68
    float* rbuf = Ks + 2 * 64 * 68;      // 256
    int tid = threadIdx.x;
    int lane = tid & 31, wid = tid >> 5;
    int g = lane >> 2, t = lane & 3;
    int warpM = wid >> 1, warpN = wid & 1;      // 4 x 2, warp tile 32x32
    int i0 = blockIdx.x * 128;
    int h = blockIdx.y, b = blockIdx.z;
    int plane = b * NH + h;

    const float* qb = Q + ((size_t)b * NS + i0) * ND + h * NDH;
    const float* kb = Km + (size_t)b * NS * ND + h * NDH;
    float* Ep = E + (size_t)plane * NS * NS;

    // Q tile 128x64: plain vector copy (pre-rounded)
#pragma unroll
    for (int l = 0; l < 8; l++) {
        int idx = tid + l * 256;
        int r = idx >> 4, c = (idx & 15) * 4;
        *(float4*)(Qs + r * 68 + c) = *(const float4*)(qb + (size_t)r * ND + c);
    }

    unsigned sK = (unsigned)__cvta_generic_to_shared(Ks);
    int krr = tid >> 4, kcc = (tid & 15) * 4;
    unsigned kOff = (krr * 68 + kcc) * 4;

    // prefetch K tile jt=0 into buffer 0 (4 x 16B per thread)
#pragma unroll
    for (int l = 0; l < 4; l++)
        cpa16(sK + kOff + l * (16 * 68 * 4), kb + (size_t)(krr + l * 16) * ND + kcc);
    CPA_COMMIT;

    float rs[2][2] = {};
    int buf = 0;
    for (int jt = 0; jt < NS; jt += 64, buf ^= 1) {
        CPA_WAIT0;
        __syncthreads();
        if (jt + 64 < NS) {
            unsigned o = (buf ^ 1) ? (unsigned)(64 * 68 * 4) : 0u;
#pragma unroll
            for (int l = 0; l < 4; l++)
                cpa16(sK + o + kOff + l * (16 * 68 * 4),
                      kb + (size_t)(jt + 64 + krr + l * 16) * ND + kcc);
            CPA_COMMIT;
        }

        float c4[2][4][4] = {};
        const unsigned* Qu = (const unsigned*)Qs;
        const unsigned* Ku = (const unsigned*)(Ks + buf * (64 * 68));
#pragma unroll
        for (int kk = 0; kk < 8; kk++) {
            int k8 = kk * 8;
            unsigned a[2][4], bfr[4][2];
#pragma unroll
            for (int mi = 0; mi < 2; mi++) {
                int m = warpM * 32 + mi * 16;
                a[mi][0] = Qu[(m + g) * 68 + k8 + t];
                a[mi][1] = Qu[(m + g + 8) * 68 + k8 + t];
                a[mi][2] = Qu[(m + g) * 68 + k8 + t + 4];
                a[mi][3] = Qu[(m + g + 8) * 68 + k8 + t + 4];
            }
#pragma unroll
            for (int ni = 0; ni < 4; ni++) {
                int n = warpN * 32 + ni * 8;
                bfr[ni][0] = Ku[(n + g) * 68 + k8 + t];
                bfr[ni][1] = Ku[(n + g) * 68 + k8 + t + 4];
            }
#pragma unroll
            for (int mi = 0; mi < 2; mi++)
#pragma unroll
                for (int ni = 0; ni < 4; ni++)
                    mma8(c4[mi][ni], a[mi], bfr[ni]);
        }
#pragma unroll
        for (int mi = 0; mi < 2; mi++) {
#pragma unroll
            for (int ni = 0; ni < 4; ni++) {
                float e0 = __expf(c4[mi][ni][0] * SCORE_SCALE);
                float e1 = __expf(c4[mi][ni][1] * SCORE_SCALE);
                float e2 = __expf(c4[mi][ni][2] * SCORE_SCALE);
                float e3 = __expf(c4[mi][ni][3] * SCORE_SCALE);
                rs[mi][0] += e0 + e1;
                rs[mi][1] += e2 + e3;
                int row = i0 + warpM * 32 + mi * 16 + g;
                int col = jt + warpN * 32 + ni * 8 + 2 * t;
                *(float2*)(Ep + (size_t)row * NS + col) = make_float2(e0, e1);
                *(float2*)(Ep + (size_t)(row + 8) * NS + col) = make_float2(e2, e3);
            }
        }
        __syncthreads();
    }

#pragma unroll
    for (int mi = 0; mi < 2; mi++)
#pragma unroll
        for (int hf = 0; hf < 2; hf++) {
            float v = rs[mi][hf];
            v += __shfl_xor_sync(0xffffffffu, v, 1);
            v += __shfl_xor_sync(0xffffffffu, v, 2);
            rs[mi][hf] = v;
        }
    if (t == 0) {
#pragma unroll
        for (int mi = 0; mi < 2; mi++)
#pragma unroll
            for (int hf = 0; hf < 2; hf++) {
                int r = warpM * 32 + mi * 16 + hf * 8 + g;
                rbuf[r * 2 + warpN] = rs[mi][hf];
            }
    }
    __syncthreads();
    if (tid < 128)
        sums[(size_t)plane * NS + i0 + tid] = rbuf[tid * 2] + rbuf[tid * 2 + 1];
}

// ---------------- blend + interleave into [b][i][j][h] ----------------
__global__ void __launch_bounds__(256) blend_kernel(float* __restrict__ outP) {
    __shared__ float sb[12 * 515];
    __shared__ float sIs[12], sPs[12];
    int b = blockIdx.x, i = blockIdx.y;
    int tid = threadIdx.x;
    if (tid < 12) sIs[tid] = 0.5f / g_sumI[(b * 12 + tid) * NS + i];
    else if (tid < 24) sPs[tid - 12] = 0.5f / g_sumP[(tid - 12) * NS + i];
    __syncthreads();
    size_t outBase = ((size_t)(b * NS + i)) * ((size_t)NS * NH);
    for (int jt = 0; jt < NS; jt += 512) {
#pragma unroll
        for (int l = 0; l < 24; l++) {
            int e = tid + l * 256;
            int h = e >> 9, j = e & 511;
            size_t idxI = ((size_t)(b * NH + h) * NS + i) * NS + jt + j;
            size_t idxP = ((size_t)h * NS + i) * NS + jt + j;
            sb[h * 515 + j] = g_Einp[idxI] * sIs[h] + g_Epos[idxP] * sPs[h];
        }
        __syncthreads();
#pragma unroll
        for (int l = 0; l < 24; l++) {
            int e = tid + l * 256;
            int j = e / 12, h = e - j * 12;
            outP[outBase + (size_t)jt * NH + e] = sb[h * 515 + j];
        }
        __syncthreads();
    }
}

// ---------------- PV (tf32 MMA, reg-prefetched): AO = blend(P) @ V ----------------
__global__ void __launch_bounds__(256) pv_mma() {
    __shared__ float As[64 * 36];
    __shared__ float Vs[32 * 68];
    __shared__ float invI[64], invP[64];
    int tid = threadIdx.x;
    int lane = tid & 31, wid = tid >> 5;
    int g = lane >> 2, t = lane & 3;
    int warpM = wid >> 1, warpN = wid & 1;       // 4 x 2, warp tile 16x32
    int i0 = blockIdx.x * 64;
    int b = blockIdx.y, h = blockIdx.z;
    int plane = b * NH + h;

    const float* Ei = g_Einp + (size_t)plane * NS * NS;
    const float* Epp = g_Epos + (size_t)h * NS * NS;
    const float* Vb = g_V + (size_t)b * NS * ND + h * NDH;

    if (tid < 64) invI[tid] = 0.5f / g_sumI[(size_t)plane * NS + i0 + tid];
    else if (tid < 128) invP[tid - 64] = 0.5f / g_sumP[(size_t)h * NS + i0 + tid - 64];
    __syncthreads();

    float c4[4][4] = {};
    int ar = tid >> 3, ac = (tid & 7) * 4;

    float4 pe1[2], pe2[2], pv[2];
#pragma unroll
    for (int rr = 0; rr < 2; rr++) {
        size_t off = (size_t)(i0 + ar + rr * 32) * NS + ac;
        pe1[rr] = *(const float4*)(Ei + off);
        pe2[rr] = *(const float4*)(Epp + off);
    }
#pragma unroll
    for (int l = 0; l < 2; l++) {
        int f = tid + l * 256;
        int r = f >> 4, c = (f & 15) * 4;
        pv[l] = *(const float4*)(Vb + (size_t)r * ND + c);
    }

    for (int k0 = 0; k0 < NS; k0 += 32) {
#pragma unroll
        for (int rr = 0; rr < 2; rr++) {
            int r = ar + rr * 32;
            float si = invI[r], sp = invP[r];
            float* d = &As[r * 36 + ac];
            d[0] = f2tff(pe1[rr].x * si + pe2[rr].x * sp);
            d[1] = f2tff(pe1[rr].y * si + pe2[rr].y * sp);
            d[2] = f2tff(pe1[rr].z * si + pe2[rr].z * sp);
            d[3] = f2tff(pe1[rr].w * si + pe2[rr].w * sp);
        }
#pragma unroll
        for (int l = 0; l < 2; l++) {
            int f = tid + l * 256;
            int r = f >> 4, c = (f & 15) * 4;
            *(float4*)(Vs + r * 68 + c) = pv[l];   // V pre-rounded
        }
        __syncthreads();

        if (k0 + 32 < NS) {
#pragma unroll
            for (int rr = 0; rr < 2; rr++) {
                size_t off = (size_t)(i0 + ar + rr * 32) * NS + k0 + 32 + ac;
                pe1[rr] = *(const float4*)(Ei + off);
                pe2[rr] = *(const float4*)(Epp + off);
            }
#pragma unroll
            for (int l = 0; l < 2; l++) {
                int f = tid + l * 256;
                int r = f >> 4, c = (f & 15) * 4;
                pv[l] = *(const float4*)(Vb + (size_t)(k0 + 32 + r) * ND + c);
            }
        }

        const unsigned* Au = (const unsigned*)As;
        const unsigned* Vu = (const unsigned*)Vs;
#pragma unroll
        for (int kk = 0; kk < 4; kk++) {
            int k8 = kk * 8;
            unsigned a[4], bfr[4][2];
            int m = warpM * 16;
            a[0] = Au[(m + g) * 36 + k8 + t];
            a[1] = Au[(m + g + 8) * 36 + k8 + t];
            a[2] = Au[(m + g) * 36 + k8 + t + 4];
            a[3] = Au[(m + g + 8) * 36 + k8 + t + 4];
#pragma unroll
            for (int ni = 0; ni < 4; ni++) {
                int n = warpN * 32 + ni * 8;
                bfr[ni][0] = Vu[(k8 + t) * 68 + n + g];
                bfr[ni][1] = Vu[(k8 + t + 4) * 68 + n + g];
            }
#pragma unroll
            for (int ni = 0; ni < 4; ni++)
                mma8(c4[ni], a, bfr[ni]);
        }
        __syncthreads();
    }
#pragma unroll
    for (int ni = 0; ni < 4; ni++) {
        int row = i0 + warpM * 16 + g;
        int col = warpN * 32 + ni * 8 + 2 * t;
        float* dst = g_AO + (size_t)(b * NS + row) * ND + h * NDH + col;
        *(float2*)dst = make_float2(f2tff(c4[ni][0]), f2tff(c4[ni][1]));
        *(float2*)(dst + (size_t)8 * ND) = make_float2(f2tff(c4[ni][2]), f2tff(c4[ni][3]));
    }
}

// ---------------- launch ----------------
extern "C" void kernel_launch(void* const* d_in, const int* in_sizes, int n_in,
                              void* d_out, int out_size) {
    (void)in_sizes; (void)n_in; (void)out_size;
    const float* inp    = (const float*)d_in[0];
    const float* pos    = (const float*)d_in[1];
    const float* Wq_inp = (const float*)d_in[2];
    const float* Wk_inp = (const float*)d_in[3];
    const float* Wq_pos = (const float*)d_in[4];
    const float* Wk_pos = (const float*)d_in[5];
    const float* Wv     = (const float*)d_in[6];
    const float* Wo     = (const float*)d_in[7];

    float* out      = (float*)d_out;
    float* out_attn = out;
    float* out_prob = out + (size_t)NBAT * NS * ND;

    float *pW5, *pAin, *pPin, *pWoR, *pQ, *pK, *pV, *pQp, *pKp, *pEi, *pEp, *pSi, *pSp, *pAO;
    cudaGetSymbolAddress((void**)&pW5,  g_W5);
    cudaGetSymbolAddress((void**)&pAin, g_Ain);
    cudaGetSymbolAddress((void**)&pPin, g_Pin);
    cudaGetSymbolAddress((void**)&pWoR, g_WoR);
    cudaGetSymbolAddress((void**)&pQ,   g_Q);
    cudaGetSymbolAddress((void**)&pK,   g_K);
    cudaGetSymbolAddress((void**)&pV,   g_V);
    cudaGetSymbolAddress((void**)&pQp,  g_Qp);
    cudaGetSymbolAddress((void**)&pKp,  g_Kp);
    cudaGetSymbolAddress((void**)&pEi,  g_Einp);
    cudaGetSymbolAddress((void**)&pEp,  g_Epos);
    cudaGetSymbolAddress((void**)&pSi,  g_sumI);
    cudaGetSymbolAddress((void**)&pSp,  g_sumP);
    cudaGetSymbolAddress((void**)&pAO,  g_AO);

    const int WELEM = 768 * 768;

    // tf32 pre-rounding of raw inputs
    round_copy<<<(4096 * 768 / 4 + 255) / 256, 256>>>(inp, pAin, 4096 * 768 / 4);
    round_copy<<<(2048 * 768 / 4 + 255) / 256, 256>>>(pos, pPin, 2048 * 768 / 4);
    round_copy<<<(WELEM / 4 + 255) / 256, 256>>>(Wo, pWoR, WELEM / 4);
    {
        dim3 g((WELEM + 255) / 256, 5);
        permW_all<<<g, 256>>>(Wq_inp, Wk_inp, Wq_pos, Wk_pos, Wv, pW5);
    }

    int gemmSmem = (2 * 64 * 36 + 2 * 32 * 132) * (int)sizeof(float);   // 52224
    cudaFuncSetAttribute(gemm_tf32<true>,  cudaFuncAttributeMaxDynamicSharedMemorySize, gemmSmem);
    cudaFuncSetAttribute(gemm_tf32<false>, cudaFuncAttributeMaxDynamicSharedMemorySize, gemmSmem);

    {
        dim3 gI(4096 / 64, 768 / 128);
        gemm_tf32<true><<<gI, 256, gemmSmem>>>(pAin, pW5 + 0 * WELEM, pQ, 4096, 768, 768);
        gemm_tf32<true><<<gI, 256, gemmSmem>>>(pAin, pW5 + 1 * WELEM, pK, 4096, 768, 768);
        gemm_tf32<true><<<gI, 256, gemmSmem>>>(pAin, pW5 + 4 * WELEM, pV, 4096, 768, 768);
        dim3 gP(2048 / 64, 768 / 128);
        gemm_tf32<true><<<gP, 256, gemmSmem>>>(pPin, pW5 + 2 * WELEM, pQp, 2048, 768, 768);
        gemm_tf32<true><<<gP, 256, gemmSmem>>>(pPin, pW5 + 3 * WELEM, pKp, 2048, 768, 768);
    }

    {
        int dynBytes = (128 * 68 + 2 * 64 * 68 + 256) * (int)sizeof(float);   // 70656
        cudaFuncSetAttribute(score_exp, cudaFuncAttributeMaxDynamicSharedMemorySize, dynBytes);
        dim3 gInp(NS / 128, NH, NBAT);
        score_exp<<<gInp, 256, dynBytes>>>(pQ, pK, pEi, pSi);
        dim3 gPos(NS / 128, NH, 1);
        score_exp<<<gPos, 256, dynBytes>>>(pQp, pKp, pEp, pSp);
    }

    {
        dim3 g(NBAT, NS);
        blend_kernel<<<g, 256>>>(out_prob);
    }

    {
        dim3 g(NS / 64, NBAT, NH);
        pv_mma<<<g, 256>>>();
    }

    {
        dim3 g(4096 / 64, 768 / 128);
        gemm_tf32<false><<<g, 256, gemmSmem>>>(pAO, pWoR, out_attn, 4096, 768, 768);
    }
}

// round 10
// speedup vs baseline: 1.2355x; 1.0188x over previous
#include <cuda_runtime.h>
#include <math.h>

#define NS   2048
#define NBAT 2
#define ND   768
#define NH   12
#define NDH  64
static const float SCORE_SCALE = 0.125f;   // 1/sqrt(64) * smoothing

// ---------------- scratch ----------------
__device__ float g_W5[5][768 * 768];                       // permuted weights, tf32-rounded
__device__ float g_Ain[4096 * 768];                        // tf32-rounded inp
__device__ float g_Pin[2048 * 768];                        // tf32-rounded pos_emb
__device__ float g_WoR[768 * 768];                         // tf32-rounded Wo
__device__ float g_Q [4096 * 768];                         // tf32-rounded
__device__ float g_K [4096 * 768];
__device__ float g_V [4096 * 768];
__device__ float g_Qp[2048 * 768];
__device__ float g_Kp[2048 * 768];
__device__ float g_Einp[(size_t)2 * 12 * 2048 * 2048];     // exp(scores), fp32
__device__ float g_Epos[(size_t)12 * 2048 * 2048];
__device__ float g_sumI[2 * 12 * 2048];
__device__ float g_sumP[12 * 2048];
__device__ float g_AO[4096 * 768];                         // tf32-rounded

// ---------------- helpers ----------------
__device__ __forceinline__ unsigned f2tf(float x) {
    unsigned r; asm("cvt.rna.tf32.f32 %0, %1;" : "=r"(r) : "f"(x)); return r;
}
__device__ __forceinline__ float f2tff(float x) { return __uint_as_float(f2tf(x)); }
__device__ __forceinline__ void mma8(float c[4], const unsigned a[4], const unsigned b[2]) {
    asm volatile(
        "mma.sync.aligned.m16n8k8.row.col.f32.tf32.tf32.f32 "
        "{%0,%1,%2,%3},{%4,%5,%6,%7},{%8,%9},{%0,%1,%2,%3};"
        : "+f"(c[0]), "+f"(c[1]), "+f"(c[2]), "+f"(c[3])
        : "r"(a[0]), "r"(a[1]), "r"(a[2]), "r"(a[3]), "r"(b[0]), "r"(b[1]));
}
__device__ __forceinline__ void cpa16(unsigned s, const void* g) {
    asm volatile("cp.async.ca.shared.global [%0], [%1], 16;" :: "r"(s), "l"(g));
}
#define CPA_COMMIT asm volatile("cp.async.commit_group;")
#define CPA_WAIT0  asm volatile("cp.async.wait_group 0;")

// ---------------- elementwise tf32 round-copy ----------------
__global__ void round_copy(const float* __restrict__ src, float* __restrict__ dst, int n4) {
    int i = blockIdx.x * 256 + threadIdx.x;
    if (i >= n4) return;
    float4 v = ((const float4*)src)[i];
    float4 o = make_float4(f2tff(v.x), f2tff(v.y), f2tff(v.z), f2tff(v.w));
    ((float4*)dst)[i] = o;
}

// ---------------- weight permutation (all 5 weights, tf32-rounded) ----------------
__global__ void permW_all(const float* __restrict__ W0, const float* __restrict__ W1,
                          const float* __restrict__ W2, const float* __restrict__ W3,
                          const float* __restrict__ W4, float* __restrict__ Wp) {
    int idx = blockIdx.x * 256 + threadIdx.x;
    if (idx >= 768 * 768) return;
    int w = blockIdx.y;
    const float* W = (w == 0) ? W0 : (w == 1) ? W1 : (w == 2) ? W2 : (w == 3) ? W3 : W4;
    int k = idx / 768;
    int oc = idx - k * 768;
    int h = oc >> 6, d = oc & 63;
    Wp[(size_t)w * (768 * 768) + idx] = f2tff(W[k * 768 + d * 12 + h]);
}

// ---------------- tf32 MMA GEMM, 128x128 CTA tile, cp.async double-buffered ----------------
// C[M,N]=A[M,K]@B[K,N], BM=128 BN=128 BK=32, 256 threads (8 warps, 2x4, warp tile 64x32).
// dyn smem: As[2][128*36] + Bs[2][32*132] = 70656 B
template <bool RND>
__global__ void __launch_bounds__(256, 2) gemm_tf32(const float* __restrict__ A,
                                                    const float* __restrict__ B,
                                                    float* __restrict__ C,
                                                    int M, int N, int K) {
    extern __shared__ float sm[];
    float* As = sm;                  // 2 x 128*36
    float* Bs = sm + 2 * 128 * 36;   // 2 x 32*132
    int tid = threadIdx.x;
    int lane = tid & 31, wid = tid >> 5;
    int g = lane >> 2, t = lane & 3;
    int warpM = wid >> 2, warpN = wid & 3;        // 2 x 4 warps, 64x32 warp tiles
    int row0 = blockIdx.x * 128, col0 = blockIdx.y * 128;

    float c[4][4][4] = {};
    int ar = tid >> 3, ac = (tid & 7) * 4;        // A: rows ar + 32*rr
    int br = tid >> 5, bc = (tid & 31) * 4;       // B: rows br + 8*rr

    const float* ApB = A + (size_t)(row0 + ar) * K + ac;
    const float* Bp  = B + col0 + bc;

    unsigned sA = (unsigned)__cvta_generic_to_shared(As);
    unsigned sB = (unsigned)__cvta_generic_to_shared(Bs);
    unsigned aOff = (ar * 36 + ac) * 4;
    unsigned bOff = (br * 132 + bc) * 4;
    const unsigned aBuf = 128 * 36 * 4, bBuf = 32 * 132 * 4;

    // prefetch tile 0 into buffer 0
#pragma unroll
    for (int rr = 0; rr < 4; rr++)
        cpa16(sA + aOff + rr * (32 * 36 * 4), ApB + (size_t)(rr * 32) * K);
#pragma unroll
    for (int rr = 0; rr < 4; rr++)
        cpa16(sB + bOff + rr * (8 * 132 * 4), Bp + (size_t)(br + rr * 8) * N - (size_t)br * N + (size_t)br * N);
    CPA_COMMIT;

    int buf = 0;
    for (int k0 = 0; k0 < K; k0 += 32, buf ^= 1) {
        CPA_WAIT0;
        __syncthreads();
        if (k0 + 32 < K) {
            unsigned oa = (buf ^ 1) ? aBuf : 0u;
            unsigned ob = (buf ^ 1) ? bBuf : 0u;
#pragma unroll
            for (int rr = 0; rr < 4; rr++)
                cpa16(sA + oa + aOff + rr * (32 * 36 * 4), ApB + (size_t)(rr * 32) * K + k0 + 32);
#pragma unroll
            for (int rr = 0; rr < 4; rr++)
                cpa16(sB + ob + bOff + rr * (8 * 132 * 4),
                      Bp + (size_t)(k0 + 32 + br + rr * 8) * N);
            CPA_COMMIT;
        }
        const unsigned* Au = (const unsigned*)(As + buf * (128 * 36));
        const unsigned* Bu = (const unsigned*)(Bs + buf * (32 * 132));
#pragma unroll
        for (int kk = 0; kk < 4; kk++) {
            int k8 = kk * 8;
            unsigned a[4][4], b[4][2];
#pragma unroll
            for (int mi = 0; mi < 4; mi++) {
                int m = warpM * 64 + mi * 16;
                a[mi][0] = Au[(m + g) * 36 + k8 + t];
                a[mi][1] = Au[(m + g + 8) * 36 + k8 + t];
                a[mi][2] = Au[(m + g) * 36 + k8 + t + 4];
                a[mi][3] = Au[(m + g + 8) * 36 + k8 + t + 4];
            }
#pragma unroll
            for (int ni = 0; ni < 4; ni++) {
                int n = warpN * 32 + ni * 8;
                b[ni][0] = Bu[(k8 + t) * 132 + n + g];
                b[ni][1] = Bu[(k8 + t + 4) * 132 + n + g];
            }
#pragma unroll
            for (int mi = 0; mi < 4; mi++)
#pragma unroll
                for (int ni = 0; ni < 4; ni++)
                    mma8(c[mi][ni], a[mi], b[ni]);
        }
        __syncthreads();
    }
#pragma unroll
    for (int mi = 0; mi < 4; mi++) {
#pragma unroll
        for (int ni = 0; ni < 4; ni++) {
            int row = row0 + warpM * 64 + mi * 16 + g;
            int col = col0 + warpN * 32 + ni * 8 + 2 * t;
            float2 v0, v1;
            if (RND) {
                v0 = make_float2(f2tff(c[mi][ni][0]), f2tff(c[mi][ni][1]));
                v1 = make_float2(f2tff(c[mi][ni][2]), f2tff(c[mi][ni][3]));
            } else {
                v0 = make_float2(c[mi][ni][0], c[mi][ni][1]);
                v1 = make_float2(c[mi][ni][2], c[mi][ni][3]);
            }
            *(float2*)(C + (size_t)row * N + col) = v0;
            *(float2*)(C + (size_t)(row + 8) * N + col) = v1;
        }
    }
}

// ---------------- scores: E = exp(scale * Q K^T) + row sums, cp.async K stream ----------------
// Q/K pre-rounded tf32. dyn smem: Qs[128*68] + Ks[2][64*68] + rbuf[256] = 70656 B
__global__ void __launch_bounds__(256) score_exp(const float* __restrict__ Q,
                                                 const float* __restrict__ Km,
                                                 float* __restrict__ E,
                                                 float* __restrict__ sums) {
    extern __shared__ float sm[];
    float* Qs = sm;                      // 128*68
    float* Ks = sm + 128 * 68;           // 2 x 64*68
    float* rbuf = Ks + 2 * 64 * 68;      // 256
    int tid = threadIdx.x;
    int lane = tid & 31, wid = tid >> 5;
    int g = lane >> 2, t = lane & 3;
    int warpM = wid >> 1, warpN = wid & 1;      // 4 x 2, warp tile 32x32
    int i0 = blockIdx.x * 128;
    int h = blockIdx.y, b = blockIdx.z;
    int plane = b * NH + h;

    const float* qb = Q + ((size_t)b * NS + i0) * ND + h * NDH;
    const float* kb = Km + (size_t)b * NS * ND + h * NDH;
    float* Ep = E + (size_t)plane * NS * NS;

#pragma unroll
    for (int l = 0; l < 8; l++) {
        int idx = tid + l * 256;
        int r = idx >> 4, c = (idx & 15) * 4;
        *(float4*)(Qs + r * 68 + c) = *(const float4*)(qb + (size_t)r * ND + c);
    }

    unsigned sK = (unsigned)__cvta_generic_to_shared(Ks);
    int krr = tid >> 4, kcc = (tid & 15) * 4;
    unsigned kOff = (krr * 68 + kcc) * 4;

#pragma unroll
    for (int l = 0; l < 4; l++)
        cpa16(sK + kOff + l * (16 * 68 * 4), kb + (size_t)(krr + l * 16) * ND + kcc);
    CPA_COMMIT;

    float rs[2][2] = {};
    int buf = 0;
    for (int jt = 0; jt < NS; jt += 64, buf ^= 1) {
        CPA_WAIT0;
        __syncthreads();
        if (jt + 64 < NS) {
            unsigned o = (buf ^ 1) ? (unsigned)(64 * 68 * 4) : 0u;
#pragma unroll
            for (int l = 0; l < 4; l++)
                cpa16(sK + o + kOff + l * (16 * 68 * 4),
                      kb + (size_t)(jt + 64 + krr + l * 16) * ND + kcc);
            CPA_COMMIT;
        }

        float c4[2][4][4] = {};
        const unsigned* Qu = (const unsigned*)Qs;
        const unsigned* Ku = (const unsigned*)(Ks + buf * (64 * 68));
#pragma unroll
        for (int kk = 0; kk < 8; kk++) {
            int k8 = kk * 8;
            unsigned a[2][4], bfr[4][2];
#pragma unroll
            for (int mi = 0; mi < 2; mi++) {
                int m = warpM * 32 + mi * 16;
                a[mi][0] = Qu[(m + g) * 68 + k8 + t];
                a[mi][1] = Qu[(m + g + 8) * 68 + k8 + t];
                a[mi][2] = Qu[(m + g) * 68 + k8 + t + 4];
                a[mi][3] = Qu[(m + g + 8) * 68 + k8 + t + 4];
            }
#pragma unroll
            for (int ni = 0; ni < 4; ni++) {
                int n = warpN * 32 + ni * 8;
                bfr[ni][0] = Ku[(n + g) * 68 + k8 + t];
                bfr[ni][1] = Ku[(n + g) * 68 + k8 + t + 4];
            }
#pragma unroll
            for (int mi = 0; mi < 2; mi++)
#pragma unroll
                for (int ni = 0; ni < 4; ni++)
                    mma8(c4[mi][ni], a[mi], bfr[ni]);
        }
#pragma unroll
        for (int mi = 0; mi < 2; mi++) {
#pragma unroll
            for (int ni = 0; ni < 4; ni++) {
                float e0 = __expf(c4[mi][ni][0] * SCORE_SCALE);
                float e1 = __expf(c4[mi][ni][1] * SCORE_SCALE);
                float e2 = __expf(c4[mi][ni][2] * SCORE_SCALE);
                float e3 = __expf(c4[mi][ni][3] * SCORE_SCALE);
                rs[mi][0] += e0 + e1;
                rs[mi][1] += e2 + e3;
                int row = i0 + warpM * 32 + mi * 16 + g;
                int col = jt + warpN * 32 + ni * 8 + 2 * t;
                *(float2*)(Ep + (size_t)row * NS + col) = make_float2(e0, e1);
                *(float2*)(Ep + (size_t)(row + 8) * NS + col) = make_float2(e2, e3);
            }
        }
        __syncthreads();
    }

#pragma unroll
    for (int mi = 0; mi < 2; mi++)
#pragma unroll
        for (int hf = 0; hf < 2; hf++) {
            float v = rs[mi][hf];
            v += __shfl_xor_sync(0xffffffffu, v, 1);
            v += __shfl_xor_sync(0xffffffffu, v, 2);
            rs[mi][hf] = v;
        }
    if (t == 0) {
#pragma unroll
        for (int mi = 0; mi < 2; mi++)
#pragma unroll
            for (int hf = 0; hf < 2; hf++) {
                int r = warpM * 32 + mi * 16 + hf * 8 + g;
                rbuf[r * 2 + warpN] = rs[mi][hf];
            }
    }
    __syncthreads();
    if (tid < 128)
        sums[(size_t)plane * NS + i0 + tid] = rbuf[tid * 2] + rbuf[tid * 2 + 1];
}

// ---------------- blend + interleave into [b][i][j][h] ----------------
__global__ void __launch_bounds__(256) blend_kernel(float* __restrict__ outP) {
    __shared__ float sb[12 * 515];
    __shared__ float sIs[12], sPs[12];
    int b = blockIdx.x, i = blockIdx.y;
    int tid = threadIdx.x;
    if (tid < 12) sIs[tid] = 0.5f / g_sumI[(b * 12 + tid) * NS + i];
    else if (tid < 24) sPs[tid - 12] = 0.5f / g_sumP[(tid - 12) * NS + i];
    __syncthreads();
    size_t outBase = ((size_t)(b * NS + i)) * ((size_t)NS * NH);
    for (int jt = 0; jt < NS; jt += 512) {
#pragma unroll
        for (int l = 0; l < 24; l++) {
            int e = tid + l * 256;
            int h = e >> 9, j = e & 511;
            size_t idxI = ((size_t)(b * NH + h) * NS + i) * NS + jt + j;
            size_t idxP = ((size_t)h * NS + i) * NS + jt + j;
            sb[h * 515 + j] = g_Einp[idxI] * sIs[h] + g_Epos[idxP] * sPs[h];
        }
        __syncthreads();
#pragma unroll
        for (int l = 0; l < 24; l++) {
            int e = tid + l * 256;
            int j = e / 12, h = e - j * 12;
            outP[outBase + (size_t)jt * NH + e] = sb[h * 515 + j];
        }
        __syncthreads();
    }
}

// ---------------- PV (tf32 MMA, reg-prefetched): AO = blend(P) @ V ----------------
__global__ void __launch_bounds__(256) pv_mma() {
    __shared__ float As[64 * 36];
    __shared__ float Vs[32 * 68];
    __shared__ float invI[64], invP[64];
    int tid = threadIdx.x;
    int lane = tid & 31, wid = tid >> 5;
    int g = lane >> 2, t = lane & 3;
    int warpM = wid >> 1, warpN = wid & 1;       // 4 x 2, warp tile 16x32
    int i0 = blockIdx.x * 64;
    int b = blockIdx.y, h = blockIdx.z;
    int plane = b * NH + h;

    const float* Ei = g_Einp + (size_t)plane * NS * NS;
    const float* Epp = g_Epos + (size_t)h * NS * NS;
    const float* Vb = g_V + (size_t)b * NS * ND + h * NDH;

    if (tid < 64) invI[tid] = 0.5f / g_sumI[(size_t)plane * NS + i0 + tid];
    else if (tid < 128) invP[tid - 64] = 0.5f / g_sumP[(size_t)h * NS + i0 + tid - 64];
    __syncthreads();

    float c4[4][4] = {};
    int ar = tid >> 3, ac = (tid & 7) * 4;

    float4 pe1[2], pe2[2], pv[2];
#pragma unroll
    for (int rr = 0; rr < 2; rr++) {
        size_t off = (size_t)(i0 + ar + rr * 32) * NS + ac;
        pe1[rr] = *(const float4*)(Ei + off);
        pe2[rr] = *(const float4*)(Epp + off);
    }
#pragma unroll
    for (int l = 0; l < 2; l++) {
        int f = tid + l * 256;
        int r = f >> 4, c = (f & 15) * 4;
        pv[l] = *(const float4*)(Vb + (size_t)r * ND + c);
    }

    for (int k0 = 0; k0 < NS; k0 += 32) {
#pragma unroll
        for (int rr = 0; rr < 2; rr++) {
            int r = ar + rr * 32;
            float si = invI[r], sp = invP[r];
            float* d = &As[r * 36 + ac];
            d[0] = f2tff(pe1[rr].x * si + pe2[rr].x * sp);
            d[1] = f2tff(pe1[rr].y * si + pe2[rr].y * sp);
            d[2] = f2tff(pe1[rr].z * si + pe2[rr].z * sp);
            d[3] = f2tff(pe1[rr].w * si + pe2[rr].w * sp);
        }
#pragma unroll
        for (int l = 0; l < 2; l++) {
            int f = tid + l * 256;
            int r = f >> 4, c = (f & 15) * 4;
            *(float4*)(Vs + r * 68 + c) = pv[l];   // V pre-rounded
        }
        __syncthreads();

        if (k0 + 32 < NS) {
#pragma unroll
            for (int rr = 0; rr < 2; rr++) {
                size_t off = (size_t)(i0 + ar + rr * 32) * NS + k0 + 32 + ac;
                pe1[rr] = *(const float4*)(Ei + off);
                pe2[rr] = *(const float4*)(Epp + off);
            }
#pragma unroll
            for (int l = 0; l < 2; l++) {
                int f = tid + l * 256;
                int r = f >> 4, c = (f & 15) * 4;
                pv[l] = *(const float4*)(Vb + (size_t)(k0 + 32 + r) * ND + c);
            }
        }

        const unsigned* Au = (const unsigned*)As;
        const unsigned* Vu = (const unsigned*)Vs;
#pragma unroll
        for (int kk = 0; kk < 4; kk++) {
            int k8 = kk * 8;
            unsigned a[4], bfr[4][2];
            int m = warpM * 16;
            a[0] = Au[(m + g) * 36 + k8 + t];
            a[1] = Au[(m + g + 8) * 36 + k8 + t];
            a[2] = Au[(m + g) * 36 + k8 + t + 4];
            a[3] = Au[(m + g + 8) * 36 + k8 + t + 4];
#pragma unroll
            for (int ni = 0; ni < 4; ni++) {
                int n = warpN * 32 + ni * 8;
                bfr[ni][0] = Vu[(k8 + t) * 68 + n + g];
                bfr[ni][1] = Vu[(k8 + t + 4) * 68 + n + g];
            }
#pragma unroll
            for (int ni = 0; ni < 4; ni++)
                mma8(c4[ni], a, bfr[ni]);
        }
        __syncthreads();
    }
#pragma unroll
    for (int ni = 0; ni < 4; ni++) {
        int row = i0 + warpM * 16 + g;
        int col = warpN * 32 + ni * 8 + 2 * t;
        float* dst = g_AO + (size_t)(b * NS + row) * ND + h * NDH + col;
        *(float2*)dst = make_float2(f2tff(c4[ni][0]), f2tff(c4[ni][1]));
        *(float2*)(dst + (size_t)8 * ND) = make_float2(f2tff(c4[ni][2]), f2tff(c4[ni][3]));
    }
}

// ---------------- launch ----------------
extern "C" void kernel_launch(void* const* d_in, const int* in_sizes, int n_in,
                              void* d_out, int out_size) {
    (void)in_sizes; (void)n_in; (void)out_size;
    const float* inp    = (const float*)d_in[0];
    const float* pos    = (const float*)d_in[1];
    const float* Wq_inp = (const float*)d_in[2];
    const float* Wk_inp = (const float*)d_in[3];
    const float* Wq_pos = (const float*)d_in[4];
    const float* Wk_pos = (const float*)d_in[5];
    const float* Wv     = (const float*)d_in[6];
    const float* Wo     = (const float*)d_in[7];

    float* out      = (float*)d_out;
    float* out_attn = out;
    float* out_prob = out + (size_t)NBAT * NS * ND;

    float *pW5, *pAin, *pPin, *pWoR, *pQ, *pK, *pV, *pQp, *pKp, *pEi, *pEp, *pSi, *pSp, *pAO;
    cudaGetSymbolAddress((void**)&pW5,  g_W5);
    cudaGetSymbolAddress((void**)&pAin, g_Ain);
    cudaGetSymbolAddress((void**)&pPin, g_Pin);
    cudaGetSymbolAddress((void**)&pWoR, g_WoR);
    cudaGetSymbolAddress((void**)&pQ,   g_Q);
    cudaGetSymbolAddress((void**)&pK,   g_K);
    cudaGetSymbolAddress((void**)&pV,   g_V);
    cudaGetSymbolAddress((void**)&pQp,  g_Qp);
    cudaGetSymbolAddress((void**)&pKp,  g_Kp);
    cudaGetSymbolAddress((void**)&pEi,  g_Einp);
    cudaGetSymbolAddress((void**)&pEp,  g_Epos);
    cudaGetSymbolAddress((void**)&pSi,  g_sumI);
    cudaGetSymbolAddress((void**)&pSp,  g_sumP);
    cudaGetSymbolAddress((void**)&pAO,  g_AO);

    const int WELEM = 768 * 768;

    // tf32 pre-rounding of raw inputs
    round_copy<<<(4096 * 768 / 4 + 255) / 256, 256>>>(inp, pAin, 4096 * 768 / 4);
    round_copy<<<(2048 * 768 / 4 + 255) / 256, 256>>>(pos, pPin, 2048 * 768 / 4);
    round_copy<<<(WELEM / 4 + 255) / 256, 256>>>(Wo, pWoR, WELEM / 4);
    {
        dim3 g((WELEM + 255) / 256, 5);
        permW_all<<<g, 256>>>(Wq_inp, Wk_inp, Wq_pos, Wk_pos, Wv, pW5);
    }

    int gemmSmem = (2 * 128 * 36 + 2 * 32 * 132) * (int)sizeof(float);   // 70656
    cudaFuncSetAttribute(gemm_tf32<true>,  cudaFuncAttributeMaxDynamicSharedMemorySize, gemmSmem);
    cudaFuncSetAttribute(gemm_tf32<false>, cudaFuncAttributeMaxDynamicSharedMemorySize, gemmSmem);

    {
        dim3 gI(4096 / 128, 768 / 128);
        gemm_tf32<true><<<gI, 256, gemmSmem>>>(pAin, pW5 + 0 * WELEM, pQ, 4096, 768, 768);
        gemm_tf32<true><<<gI, 256, gemmSmem>>>(pAin, pW5 + 1 * WELEM, pK, 4096, 768, 768);
        gemm_tf32<true><<<gI, 256, gemmSmem>>>(pAin, pW5 + 4 * WELEM, pV, 4096, 768, 768);
        dim3 gP(2048 / 128, 768 / 128);
        gemm_tf32<true><<<gP, 256, gemmSmem>>>(pPin, pW5 + 2 * WELEM, pQp, 2048, 768, 768);
        gemm_tf32<true><<<gP, 256, gemmSmem>>>(pPin, pW5 + 3 * WELEM, pKp, 2048, 768, 768);
    }

    {
        int dynBytes = (128 * 68 + 2 * 64 * 68 + 256) * (int)sizeof(float);   // 70656
        cudaFuncSetAttribute(score_exp, cudaFuncAttributeMaxDynamicSharedMemorySize, dynBytes);
        dim3 gInp(NS / 128, NH, NBAT);
        score_exp<<<gInp, 256, dynBytes>>>(pQ, pK, pEi, pSi);
        dim3 gPos(NS / 128, NH, 1);
        score_exp<<<gPos, 256, dynBytes>>>(pQp, pKp, pEp, pSp);
    }

    {
        dim3 g(NBAT, NS);
        blend_kernel<<<g, 256>>>(out_prob);
    }

    {
        dim3 g(NS / 64, NBAT, NH);
        pv_mma<<<g, 256>>>();
    }

    {
        dim3 g(4096 / 128, 768 / 128);
        gemm_tf32<false><<<g, 256, gemmSmem>>>(pAO, pWoR, out_attn, 4096, 768, 768);
    }
}

// round 11
// speedup vs baseline: 1.3725x; 1.1109x over previous
#include <cuda_runtime.h>
#include <cuda_fp16.h>
#include <math.h>

#define NS   2048
#define NBAT 2
#define ND   768
#define NH   12
#define NDH  64
static const float SCORE_SCALE = 0.125f;   // 1/sqrt(64) * smoothing

// ---------------- scratch ----------------
__device__ float g_W5[5][768 * 768];                       // permuted weights, tf32-rounded
__device__ float g_Ain[4096 * 768];                        // tf32-rounded inp
__device__ float g_Pin[2048 * 768];                        // tf32-rounded pos_emb
__device__ float g_WoR[768 * 768];                         // tf32-rounded Wo
__device__ float g_Q [4096 * 768];                         // tf32-rounded
__device__ float g_K [4096 * 768];
__device__ float g_V [4096 * 768];
__device__ float g_Qp[2048 * 768];
__device__ float g_Kp[2048 * 768];
__device__ __half g_Einp[(size_t)2 * 12 * 2048 * 2048];    // exp(scores), fp16
__device__ __half g_Epos[(size_t)12 * 2048 * 2048];
__device__ float g_sumI[2 * 12 * 2048];                    // fp32 row sums (pre-quantization)
__device__ float g_sumP[12 * 2048];
__device__ float g_AO[4096 * 768];                         // tf32-rounded

// ---------------- helpers ----------------
__device__ __forceinline__ unsigned f2tf(float x) {
    unsigned r; asm("cvt.rna.tf32.f32 %0, %1;" : "=r"(r) : "f"(x)); return r;
}
__device__ __forceinline__ float f2tff(float x) { return __uint_as_float(f2tf(x)); }
__device__ __forceinline__ void mma8(float c[4], const unsigned a[4], const unsigned b[2]) {
    asm volatile(
        "mma.sync.aligned.m16n8k8.row.col.f32.tf32.tf32.f32 "
        "{%0,%1,%2,%3},{%4,%5,%6,%7},{%8,%9},{%0,%1,%2,%3};"
        : "+f"(c[0]), "+f"(c[1]), "+f"(c[2]), "+f"(c[3])
        : "r"(a[0]), "r"(a[1]), "r"(a[2]), "r"(a[3]), "r"(b[0]), "r"(b[1]));
}
__device__ __forceinline__ void cpa16(unsigned s, const void* g) {
    asm volatile("cp.async.ca.shared.global [%0], [%1], 16;" :: "r"(s), "l"(g));
}
#define CPA_COMMIT asm volatile("cp.async.commit_group;")
#define CPA_WAIT0  asm volatile("cp.async.wait_group 0;")

// ---------------- elementwise tf32 round-copy ----------------
__global__ void round_copy(const float* __restrict__ src, float* __restrict__ dst, int n4) {
    int i = blockIdx.x * 256 + threadIdx.x;
    if (i >= n4) return;
    float4 v = ((const float4*)src)[i];
    float4 o = make_float4(f2tff(v.x), f2tff(v.y), f2tff(v.z), f2tff(v.w));
    ((float4*)dst)[i] = o;
}

// ---------------- weight permutation (all 5 weights, tf32-rounded) ----------------
__global__ void permW_all(const float* __restrict__ W0, const float* __restrict__ W1,
                          const float* __restrict__ W2, const float* __restrict__ W3,
                          const float* __restrict__ W4, float* __restrict__ Wp) {
    int idx = blockIdx.x * 256 + threadIdx.x;
    if (idx >= 768 * 768) return;
    int w = blockIdx.y;
    const float* W = (w == 0) ? W0 : (w == 1) ? W1 : (w == 2) ? W2 : (w == 3) ? W3 : W4;
    int k = idx / 768;
    int oc = idx - k * 768;
    int h = oc >> 6, d = oc & 63;
    Wp[(size_t)w * (768 * 768) + idx] = f2tff(W[k * 768 + d * 12 + h]);
}

// ---------------- tf32 MMA GEMM, 128x128 CTA tile, cp.async double-buffered ----------------
template <bool RND>
__global__ void __launch_bounds__(256, 2) gemm_tf32(const float* __restrict__ A,
                                                    const float* __restrict__ B,
                                                    float* __restrict__ C,
                                                    int M, int N, int K) {
    extern __shared__ float sm[];
    float* As = sm;                  // 2 x 128*36
    float* Bs = sm + 2 * 128 * 36;   // 2 x 32*132
    int tid = threadIdx.x;
    int lane = tid & 31, wid = tid >> 5;
    int g = lane >> 2, t = lane & 3;
    int warpM = wid >> 2, warpN = wid & 3;        // 2 x 4 warps, 64x32 warp tiles
    int row0 = blockIdx.x * 128, col0 = blockIdx.y * 128;

    float c[4][4][4] = {};
    int ar = tid >> 3, ac = (tid & 7) * 4;
    int br = tid >> 5, bc = (tid & 31) * 4;

    const float* ApB = A + (size_t)(row0 + ar) * K + ac;
    const float* Bp  = B + col0 + bc;

    unsigned sA = (unsigned)__cvta_generic_to_shared(As);
    unsigned sB = (unsigned)__cvta_generic_to_shared(Bs);
    unsigned aOff = (ar * 36 + ac) * 4;
    unsigned bOff = (br * 132 + bc) * 4;
    const unsigned aBuf = 128 * 36 * 4, bBuf = 32 * 132 * 4;

#pragma unroll
    for (int rr = 0; rr < 4; rr++)
        cpa16(sA + aOff + rr * (32 * 36 * 4), ApB + (size_t)(rr * 32) * K);
#pragma unroll
    for (int rr = 0; rr < 4; rr++)
        cpa16(sB + bOff + rr * (8 * 132 * 4), Bp + (size_t)(br + rr * 8) * N - (size_t)br * N + (size_t)br * N);
    CPA_COMMIT;

    int buf = 0;
    for (int k0 = 0; k0 < K; k0 += 32, buf ^= 1) {
        CPA_WAIT0;
        __syncthreads();
        if (k0 + 32 < K) {
            unsigned oa = (buf ^ 1) ? aBuf : 0u;
            unsigned ob = (buf ^ 1) ? bBuf : 0u;
#pragma unroll
            for (int rr = 0; rr < 4; rr++)
                cpa16(sA + oa + aOff + rr * (32 * 36 * 4), ApB + (size_t)(rr * 32) * K + k0 + 32);
#pragma unroll
            for (int rr = 0; rr < 4; rr++)
                cpa16(sB + ob + bOff + rr * (8 * 132 * 4),
                      Bp + (size_t)(k0 + 32 + br + rr * 8) * N);
            CPA_COMMIT;
        }
        const unsigned* Au = (const unsigned*)(As + buf * (128 * 36));
        const unsigned* Bu = (const unsigned*)(Bs + buf * (32 * 132));
#pragma unroll
        for (int kk = 0; kk < 4; kk++) {
            int k8 = kk * 8;
            unsigned a[4][4], b[4][2];
#pragma unroll
            for (int mi = 0; mi < 4; mi++) {
                int m = warpM * 64 + mi * 16;
                a[mi][0] = Au[(m + g) * 36 + k8 + t];
                a[mi][1] = Au[(m + g + 8) * 36 + k8 + t];
                a[mi][2] = Au[(m + g) * 36 + k8 + t + 4];
                a[mi][3] = Au[(m + g + 8) * 36 + k8 + t + 4];
            }
#pragma unroll
            for (int ni = 0; ni < 4; ni++) {
                int n = warpN * 32 + ni * 8;
                b[ni][0] = Bu[(k8 + t) * 132 + n + g];
                b[ni][1] = Bu[(k8 + t + 4) * 132 + n + g];
            }
#pragma unroll
            for (int mi = 0; mi < 4; mi++)
#pragma unroll
                for (int ni = 0; ni < 4; ni++)
                    mma8(c[mi][ni], a[mi], b[ni]);
        }
        __syncthreads();
    }
#pragma unroll
    for (int mi = 0; mi < 4; mi++) {
#pragma unroll
        for (int ni = 0; ni < 4; ni++) {
            int row = row0 + warpM * 64 + mi * 16 + g;
            int col = col0 + warpN * 32 + ni * 8 + 2 * t;
            float2 v0, v1;
            if (RND) {
                v0 = make_float2(f2tff(c[mi][ni][0]), f2tff(c[mi][ni][1]));
                v1 = make_float2(f2tff(c[mi][ni][2]), f2tff(c[mi][ni][3]));
            } else {
                v0 = make_float2(c[mi][ni][0], c[mi][ni][1]);
                v1 = make_float2(c[mi][ni][2], c[mi][ni][3]);
            }
            *(float2*)(C + (size_t)row * N + col) = v0;
            *(float2*)(C + (size_t)(row + 8) * N + col) = v1;
        }
    }
}

// ---------------- scores: E(fp16) = exp(scale * Q K^T) + fp32 row sums ----------------
__global__ void __launch_bounds__(256) score_exp(const float* __restrict__ Q,
                                                 const float* __restrict__ Km,
                                                 __half* __restrict__ E,
                                                 float* __restrict__ sums) {
    extern __shared__ float sm[];
    float* Qs = sm;                      // 128*68
    float* Ks = sm + 128 * 68;           // 2 x 64*68
    float* rbuf = Ks + 2 * 64 * 68;      // 256
    int tid = threadIdx.x;
    int lane = tid & 31, wid = tid >> 5;
    int g = lane >> 2, t = lane & 3;
    int warpM = wid >> 1, warpN = wid & 1;      // 4 x 2, warp tile 32x32
    int i0 = blockIdx.x * 128;
    int h = blockIdx.y, b = blockIdx.z;
    int plane = b * NH + h;

    const float* qb = Q + ((size_t)b * NS + i0) * ND + h * NDH;
    const float* kb = Km + (size_t)b * NS * ND + h * NDH;
    __half* Ep = E + (size_t)plane * NS * NS;

#pragma unroll
    for (int l = 0; l < 8; l++) {
        int idx = tid + l * 256;
        int r = idx >> 4, c = (idx & 15) * 4;
        *(float4*)(Qs + r * 68 + c) = *(const float4*)(qb + (size_t)r * ND + c);
    }

    unsigned sK = (unsigned)__cvta_generic_to_shared(Ks);
    int krr = tid >> 4, kcc = (tid & 15) * 4;
    unsigned kOff = (krr * 68 + kcc) * 4;

#pragma unroll
    for (int l = 0; l < 4; l++)
        cpa16(sK + kOff + l * (16 * 68 * 4), kb + (size_t)(krr + l * 16) * ND + kcc);
    CPA_COMMIT;

    float rs[2][2] = {};
    int buf = 0;
    for (int jt = 0; jt < NS; jt += 64, buf ^= 1) {
        CPA_WAIT0;
        __syncthreads();
        if (jt + 64 < NS) {
            unsigned o = (buf ^ 1) ? (unsigned)(64 * 68 * 4) : 0u;
#pragma unroll
            for (int l = 0; l < 4; l++)
                cpa16(sK + o + kOff + l * (16 * 68 * 4),
                      kb + (size_t)(jt + 64 + krr + l * 16) * ND + kcc);
            CPA_COMMIT;
        }

        float c4[2][4][4] = {};
        const unsigned* Qu = (const unsigned*)Qs;
        const unsigned* Ku = (const unsigned*)(Ks + buf * (64 * 68));
#pragma unroll
        for (int kk = 0; kk < 8; kk++) {
            int k8 = kk * 8;
            unsigned a[2][4], bfr[4][2];
#pragma unroll
            for (int mi = 0; mi < 2; mi++) {
                int m = warpM * 32 + mi * 16;
                a[mi][0] = Qu[(m + g) * 68 + k8 + t];
                a[mi][1] = Qu[(m + g + 8) * 68 + k8 + t];
                a[mi][2] = Qu[(m + g) * 68 + k8 + t + 4];
                a[mi][3] = Qu[(m + g + 8) * 68 + k8 + t + 4];
            }
#pragma unroll
            for (int ni = 0; ni < 4; ni++) {
                int n = warpN * 32 + ni * 8;
                bfr[ni][0] = Ku[(n + g) * 68 + k8 + t];
                bfr[ni][1] = Ku[(n + g) * 68 + k8 + t + 4];
            }
#pragma unroll
            for (int mi = 0; mi < 2; mi++)
#pragma unroll
                for (int ni = 0; ni < 4; ni++)
                    mma8(c4[mi][ni], a[mi], bfr[ni]);
        }
#pragma unroll
        for (int mi = 0; mi < 2; mi++) {
#pragma unroll
            for (int ni = 0; ni < 4; ni++) {
                float e0 = __expf(c4[mi][ni][0] * SCORE_SCALE);
                float e1 = __expf(c4[mi][ni][1] * SCORE_SCALE);
                float e2 = __expf(c4[mi][ni][2] * SCORE_SCALE);
                float e3 = __expf(c4[mi][ni][3] * SCORE_SCALE);
                rs[mi][0] += e0 + e1;
                rs[mi][1] += e2 + e3;
                int row = i0 + warpM * 32 + mi * 16 + g;
                int col = jt + warpN * 32 + ni * 8 + 2 * t;
                *(__half2*)(Ep + (size_t)row * NS + col) = __floats2half2_rn(e0, e1);
                *(__half2*)(Ep + (size_t)(row + 8) * NS + col) = __floats2half2_rn(e2, e3);
            }
        }
        __syncthreads();
    }

#pragma unroll
    for (int mi = 0; mi < 2; mi++)
#pragma unroll
        for (int hf = 0; hf < 2; hf++) {
            float v = rs[mi][hf];
            v += __shfl_xor_sync(0xffffffffu, v, 1);
            v += __shfl_xor_sync(0xffffffffu, v, 2);
            rs[mi][hf] = v;
        }
    if (t == 0) {
#pragma unroll
        for (int mi = 0; mi < 2; mi++)
#pragma unroll
            for (int hf = 0; hf < 2; hf++) {
                int r = warpM * 32 + mi * 16 + hf * 8 + g;
                rbuf[r * 2 + warpN] = rs[mi][hf];
            }
    }
    __syncthreads();
    if (tid < 128)
        sums[(size_t)plane * NS + i0 + tid] = rbuf[tid * 2] + rbuf[tid * 2 + 1];
}

// ---------------- blend + interleave into [b][i][j][h] (fp16 E reads) ----------------
__global__ void __launch_bounds__(256) blend_kernel(float* __restrict__ outP) {
    __shared__ float sb[12 * 515];
    __shared__ float sIs[12], sPs[12];
    int b = blockIdx.x, i = blockIdx.y;
    int tid = threadIdx.x;
    if (tid < 12) sIs[tid] = 0.5f / g_sumI[(b * 12 + tid) * NS + i];
    else if (tid < 24) sPs[tid - 12] = 0.5f / g_sumP[(tid - 12) * NS + i];
    __syncthreads();
    size_t outBase = ((size_t)(b * NS + i)) * ((size_t)NS * NH);
    for (int jt = 0; jt < NS; jt += 512) {
        // load 12 heads x 512 j as half2 pairs: 3072 half2 over 256 threads
#pragma unroll
        for (int l = 0; l < 12; l++) {
            int e = tid + l * 256;            // 0..3071
            int h = e >> 8, j2 = e & 255;     // j = 2*j2
            size_t idxI = ((size_t)(b * NH + h) * NS + i) * NS + jt + 2 * j2;
            size_t idxP = ((size_t)h * NS + i) * NS + jt + 2 * j2;
            float2 f1 = __half22float2(*(const __half2*)(g_Einp + idxI));
            float2 f2 = __half22float2(*(const __half2*)(g_Epos + idxP));
            float si = sIs[h], sp = sPs[h];
            sb[h * 515 + 2 * j2]     = f1.x * si + f2.x * sp;
            sb[h * 515 + 2 * j2 + 1] = f1.y * si + f2.y * sp;
        }
        __syncthreads();
#pragma unroll
        for (int l = 0; l < 24; l++) {
            int e = tid + l * 256;
            int j = e / 12, h = e - j * 12;
            outP[outBase + (size_t)jt * NH + e] = sb[h * 515 + j];
        }
        __syncthreads();
    }
}

// ---------------- PV (tf32 MMA, fp16 E reads, reg-prefetched): AO = blend(P) @ V ----------------
__global__ void __launch_bounds__(256) pv_mma() {
    __shared__ float As[64 * 36];
    __shared__ float Vs[32 * 68];
    __shared__ float invI[64], invP[64];
    int tid = threadIdx.x;
    int lane = tid & 31, wid = tid >> 5;
    int g = lane >> 2, t = lane & 3;
    int warpM = wid >> 1, warpN = wid & 1;       // 4 x 2, warp tile 16x32
    int i0 = blockIdx.x * 64;
    int b = blockIdx.y, h = blockIdx.z;
    int plane = b * NH + h;

    const __half* Ei = g_Einp + (size_t)plane * NS * NS;
    const __half* Epp = g_Epos + (size_t)h * NS * NS;
    const float* Vb = g_V + (size_t)b * NS * ND + h * NDH;

    if (tid < 64) invI[tid] = 0.5f / g_sumI[(size_t)plane * NS + i0 + tid];
    else if (tid < 128) invP[tid - 64] = 0.5f / g_sumP[(size_t)h * NS + i0 + tid - 64];
    __syncthreads();

    float c4[4][4] = {};
    int ar = tid >> 3, ac = (tid & 7) * 4;

    uint2 pe1[2], pe2[2];   // 4 halves each
    float4 pv[2];
#pragma unroll
    for (int rr = 0; rr < 2; rr++) {
        size_t off = (size_t)(i0 + ar + rr * 32) * NS + ac;
        pe1[rr] = *(const uint2*)(Ei + off);
        pe2[rr] = *(const uint2*)(Epp + off);
    }
#pragma unroll
    for (int l = 0; l < 2; l++) {
        int f = tid + l * 256;
        int r = f >> 4, c = (f & 15) * 4;
        pv[l] = *(const float4*)(Vb + (size_t)r * ND + c);
    }

    for (int k0 = 0; k0 < NS; k0 += 32) {
#pragma unroll
        for (int rr = 0; rr < 2; rr++) {
            int r = ar + rr * 32;
            float si = invI[r], sp = invP[r];
            float2 a0 = __half22float2(*(__half2*)&pe1[rr].x);
            float2 a1 = __half22float2(*(__half2*)&pe1[rr].y);
            float2 b0 = __half22float2(*(__half2*)&pe2[rr].x);
            float2 b1 = __half22float2(*(__half2*)&pe2[rr].y);
            float* d = &As[r * 36 + ac];
            d[0] = f2tff(a0.x * si + b0.x * sp);
            d[1] = f2tff(a0.y * si + b0.y * sp);
            d[2] = f2tff(a1.x * si + b1.x * sp);
            d[3] = f2tff(a1.y * si + b1.y * sp);
        }
#pragma unroll
        for (int l = 0; l < 2; l++) {
            int f = tid + l * 256;
            int r = f >> 4, c = (f & 15) * 4;
            *(float4*)(Vs + r * 68 + c) = pv[l];   // V pre-rounded
        }
        __syncthreads();

        if (k0 + 32 < NS) {
#pragma unroll
            for (int rr = 0; rr < 2; rr++) {
                size_t off = (size_t)(i0 + ar + rr * 32) * NS + k0 + 32 + ac;
                pe1[rr] = *(const uint2*)(Ei + off);
                pe2[rr] = *(const uint2*)(Epp + off);
            }
#pragma unroll
            for (int l = 0; l < 2; l++) {
                int f = tid + l * 256;
                int r = f >> 4, c = (f & 15) * 4;
                pv[l] = *(const float4*)(Vb + (size_t)(k0 + 32 + r) * ND + c);
            }
        }

        const unsigned* Au = (const unsigned*)As;
        const unsigned* Vu = (const unsigned*)Vs;
#pragma unroll
        for (int kk = 0; kk < 4; kk++) {
            int k8 = kk * 8;
            unsigned a[4], bfr[4][2];
            int m = warpM * 16;
            a[0] = Au[(m + g) * 36 + k8 + t];
            a[1] = Au[(m + g + 8) * 36 + k8 + t];
            a[2] = Au[(m + g) * 36 + k8 + t + 4];
            a[3] = Au[(m + g + 8) * 36 + k8 + t + 4];
#pragma unroll
            for (int ni = 0; ni < 4; ni++) {
                int n = warpN * 32 + ni * 8;
                bfr[ni][0] = Vu[(k8 + t) * 68 + n + g];
                bfr[ni][1] = Vu[(k8 + t + 4) * 68 + n + g];
            }
#pragma unroll
            for (int ni = 0; ni < 4; ni++)
                mma8(c4[ni], a, bfr[ni]);
        }
        __syncthreads();
    }
#pragma unroll
    for (int ni = 0; ni < 4; ni++) {
        int row = i0 + warpM * 16 + g;
        int col = warpN * 32 + ni * 8 + 2 * t;
        float* dst = g_AO + (size_t)(b * NS + row) * ND + h * NDH + col;
        *(float2*)dst = make_float2(f2tff(c4[ni][0]), f2tff(c4[ni][1]));
        *(float2*)(dst + (size_t)8 * ND) = make_float2(f2tff(c4[ni][2]), f2tff(c4[ni][3]));
    }
}

// ---------------- launch ----------------
extern "C" void kernel_launch(void* const* d_in, const int* in_sizes, int n_in,
                              void* d_out, int out_size) {
    (void)in_sizes; (void)n_in; (void)out_size;
    const float* inp    = (const float*)d_in[0];
    const float* pos    = (const float*)d_in[1];
    const float* Wq_inp = (const float*)d_in[2];
    const float* Wk_inp = (const float*)d_in[3];
    const float* Wq_pos = (const float*)d_in[4];
    const float* Wk_pos = (const float*)d_in[5];
    const float* Wv     = (const float*)d_in[6];
    const float* Wo     = (const float*)d_in[7];

    float* out      = (float*)d_out;
    float* out_attn = out;
    float* out_prob = out + (size_t)NBAT * NS * ND;

    float *pW5, *pAin, *pPin, *pWoR, *pQ, *pK, *pV, *pQp, *pKp, *pSi, *pSp, *pAO;
    __half *pEi, *pEp;
    cudaGetSymbolAddress((void**)&pW5,  g_W5);
    cudaGetSymbolAddress((void**)&pAin, g_Ain);
    cudaGetSymbolAddress((void**)&pPin, g_Pin);
    cudaGetSymbolAddress((void**)&pWoR, g_WoR);
    cudaGetSymbolAddress((void**)&pQ,   g_Q);
    cudaGetSymbolAddress((void**)&pK,   g_K);
    cudaGetSymbolAddress((void**)&pV,   g_V);
    cudaGetSymbolAddress((void**)&pQp,  g_Qp);
    cudaGetSymbolAddress((void**)&pKp,  g_Kp);
    cudaGetSymbolAddress((void**)&pEi,  g_Einp);
    cudaGetSymbolAddress((void**)&pEp,  g_Epos);
    cudaGetSymbolAddress((void**)&pSi,  g_sumI);
    cudaGetSymbolAddress((void**)&pSp,  g_sumP);
    cudaGetSymbolAddress((void**)&pAO,  g_AO);

    const int WELEM = 768 * 768;

    round_copy<<<(4096 * 768 / 4 + 255) / 256, 256>>>(inp, pAin, 4096 * 768 / 4);
    round_copy<<<(2048 * 768 / 4 + 255) / 256, 256>>>(pos, pPin, 2048 * 768 / 4);
    round_copy<<<(WELEM / 4 + 255) / 256, 256>>>(Wo, pWoR, WELEM / 4);
    {
        dim3 g((WELEM + 255) / 256, 5);
        permW_all<<<g, 256>>>(Wq_inp, Wk_inp, Wq_pos, Wk_pos, Wv, pW5);
    }

    int gemmSmem = (2 * 128 * 36 + 2 * 32 * 132) * (int)sizeof(float);   // 70656
    cudaFuncSetAttribute(gemm_tf32<true>,  cudaFuncAttributeMaxDynamicSharedMemorySize, gemmSmem);
    cudaFuncSetAttribute(gemm_tf32<false>, cudaFuncAttributeMaxDynamicSharedMemorySize, gemmSmem);

    {
        dim3 gI(4096 / 128, 768 / 128);
        gemm_tf32<true><<<gI, 256, gemmSmem>>>(pAin, pW5 + 0 * WELEM, pQ, 4096, 768, 768);
        gemm_tf32<true><<<gI, 256, gemmSmem>>>(pAin, pW5 + 1 * WELEM, pK, 4096, 768, 768);
        gemm_tf32<true><<<gI, 256, gemmSmem>>>(pAin, pW5 + 4 * WELEM, pV, 4096, 768, 768);
        dim3 gP(2048 / 128, 768 / 128);
        gemm_tf32<true><<<gP, 256, gemmSmem>>>(pPin, pW5 + 2 * WELEM, pQp, 2048, 768, 768);
        gemm_tf32<true><<<gP, 256, gemmSmem>>>(pPin, pW5 + 3 * WELEM, pKp, 2048, 768, 768);
    }

    {
        int dynBytes = (128 * 68 + 2 * 64 * 68 + 256) * (int)sizeof(float);   // 70656
        cudaFuncSetAttribute(score_exp, cudaFuncAttributeMaxDynamicSharedMemorySize, dynBytes);
        dim3 gInp(NS / 128, NH, NBAT);
        score_exp<<<gInp, 256, dynBytes>>>(pQ, pK, pEi, pSi);
        dim3 gPos(NS / 128, NH, 1);
        score_exp<<<gPos, 256, dynBytes>>>(pQp, pKp, pEp, pSp);
    }

    {
        dim3 g(NBAT, NS);
        blend_kernel<<<g, 256>>>(out_prob);
    }

    {
        dim3 g(NS / 64, NBAT, NH);
        pv_mma<<<g, 256>>>();
    }

    {
        dim3 g(4096 / 128, 768 / 128);
        gemm_tf32<false><<<g, 256, gemmSmem>>>(pAO, pWoR, out_attn, 4096, 768, 768);
    }
}

// round 12
// speedup vs baseline: 1.6462x; 1.1994x over previous
#include <cuda_runtime.h>
#include <cuda_fp16.h>
#include <math.h>

#define NS   2048
#define NBAT 2
#define ND   768
#define NH   12
#define NDH  64
static const float SCORE_SCALE = 0.125f;   // 1/sqrt(64) * smoothing

// ---------------- scratch ----------------
__device__ __half g_W6[6][768 * 768];                      // [n][k] fp16: 5 perm'd proj weights + Wo^T
__device__ __half g_Ain[4096 * 768];                       // fp16 inp
__device__ __half g_Pin[2048 * 768];                       // fp16 pos_emb
__device__ __half g_Q [4096 * 768];
__device__ __half g_K [4096 * 768];
__device__ __half g_V [4096 * 768];
__device__ __half g_Qp[2048 * 768];
__device__ __half g_Kp[2048 * 768];
__device__ __half g_Einp[(size_t)2 * 12 * 2048 * 2048];    // exp(scores), fp16
__device__ __half g_Epos[(size_t)12 * 2048 * 2048];
__device__ float g_sumI[2 * 12 * 2048];                    // fp32 row sums
__device__ float g_sumP[12 * 2048];
__device__ __half g_AO[4096 * 768];                        // fp16 attn-out pre-Wo

// ---------------- helpers ----------------
__device__ __forceinline__ unsigned f2tf(float x) {
    unsigned r; asm("cvt.rna.tf32.f32 %0, %1;" : "=r"(r) : "f"(x)); return r;
}
__device__ __forceinline__ float f2tff(float x) { return __uint_as_float(f2tf(x)); }
__device__ __forceinline__ void mma8(float c[4], const unsigned a[4], const unsigned b[2]) {
    asm volatile(
        "mma.sync.aligned.m16n8k8.row.col.f32.tf32.tf32.f32 "
        "{%0,%1,%2,%3},{%4,%5,%6,%7},{%8,%9},{%0,%1,%2,%3};"
        : "+f"(c[0]), "+f"(c[1]), "+f"(c[2]), "+f"(c[3])
        : "r"(a[0]), "r"(a[1]), "r"(a[2]), "r"(a[3]), "r"(b[0]), "r"(b[1]));
}
__device__ __forceinline__ void mmah(float c[4], const unsigned a[4], const unsigned b[2]) {
    asm volatile(
        "mma.sync.aligned.m16n8k16.row.col.f32.f16.f16.f32 "
        "{%0,%1,%2,%3},{%4,%5,%6,%7},{%8,%9},{%0,%1,%2,%3};"
        : "+f"(c[0]), "+f"(c[1]), "+f"(c[2]), "+f"(c[3])
        : "r"(a[0]), "r"(a[1]), "r"(a[2]), "r"(a[3]), "r"(b[0]), "r"(b[1]));
}
__device__ __forceinline__ void cpa16(unsigned s, const void* g) {
    asm volatile("cp.async.ca.shared.global [%0], [%1], 16;" :: "r"(s), "l"(g));
}
#define CPA_COMMIT asm volatile("cp.async.commit_group;")
#define CPA_WAIT0  asm volatile("cp.async.wait_group 0;")

// ---------------- float -> fp16 convert-copy ----------------
__global__ void conv_h(const float* __restrict__ src, __half* __restrict__ dst, int n4) {
    int i = blockIdx.x * 256 + threadIdx.x;
    if (i >= n4) return;
    float4 v = ((const float4*)src)[i];
    __half2 h0 = __floats2half2_rn(v.x, v.y);
    __half2 h1 = __floats2half2_rn(v.z, v.w);
    uint2 o = make_uint2(*(unsigned*)&h0, *(unsigned*)&h1);
    ((uint2*)dst)[i] = o;
}

// ---------------- weight prep: transpose (+ head permutation) to [n][k] fp16 ----------------
// z = 0..4: proj weights (source col j = d*12+h -> out row n = h*64+d); z = 5: Wo (identity cols)
__global__ void prep_weights(const float* __restrict__ W0, const float* __restrict__ W1,
                             const float* __restrict__ W2, const float* __restrict__ W3,
                             const float* __restrict__ W4, const float* __restrict__ W5,
                             __half* __restrict__ Wp) {
    __shared__ __half ts[32][33];
    int w = blockIdx.z;
    const float* W = (w == 0) ? W0 : (w == 1) ? W1 : (w == 2) ? W2 : (w == 3) ? W3
                   : (w == 4) ? W4 : W5;
    int k0 = blockIdx.x * 32, j0 = blockIdx.y * 32;
    int tid = threadIdx.x;
    int r = tid >> 5, c = tid & 31;
#pragma unroll
    for (int l = 0; l < 4; l++) {
        int k = k0 + r + l * 8;
        ts[c][r + l * 8] = __float2half_rn(W[(size_t)k * 768 + j0 + c]);
    }
    __syncthreads();
#pragma unroll
    for (int l = 0; l < 4; l++) {
        int j = j0 + r + l * 8;
        int n = (w < 5) ? ((j % 12) * 64 + j / 12) : j;
        g_W6[w][(size_t)n * 768 + k0 + c] = ts[r + l * 8][c];
    }
    (void)Wp;
}

// ---------------- fp16 MMA GEMM, 128x128 CTA tile, cp.async double-buffered ----------------
// C[M,N] = A[M,K] @ B^T where A[M][K], Bt[N][K] both fp16 row-major. BK=32.
// dyn smem: As[2][128*40] + Bs[2][128*40] halves = 40960 B
template <bool HALF_OUT>
__global__ void __launch_bounds__(256, 2) gemm_fp16(const __half* __restrict__ A,
                                                    const __half* __restrict__ Bt,
                                                    void* __restrict__ Cv,
                                                    int M, int N, int K) {
    extern __shared__ __half smh[];
    __half* As = smh;                  // 2 x 128*40
    __half* Bs = smh + 2 * 128 * 40;   // 2 x 128*40
    int tid = threadIdx.x;
    int lane = tid & 31, wid = tid >> 5;
    int g = lane >> 2, t = lane & 3;
    int warpM = wid >> 2, warpN = wid & 3;        // 2 x 4 warps, 64x32 warp tiles
    int row0 = blockIdx.x * 128, col0 = blockIdx.y * 128;

    float c[4][4][4] = {};
    int lr = tid >> 2, lch = (tid & 3) * 8;       // loader: row lr (+64 for l=1), 8-half chunk

    unsigned sA = (unsigned)__cvta_generic_to_shared(As);
    unsigned sB = (unsigned)__cvta_generic_to_shared(Bs);
    const unsigned bufH = 128 * 40;               // halves per buffer

    // prefetch tile 0 into buffer 0
#pragma unroll
    for (int l = 0; l < 2; l++) {
        int r = lr + l * 64;
        cpa16(sA + (r * 40 + lch) * 2, A + (size_t)(row0 + r) * K + lch);
        cpa16(sB + (r * 40 + lch) * 2, Bt + (size_t)(col0 + r) * K + lch);
    }
    CPA_COMMIT;

    int buf = 0;
    for (int k0 = 0; k0 < K; k0 += 32, buf ^= 1) {
        CPA_WAIT0;
        __syncthreads();
        if (k0 + 32 < K) {
            unsigned o = (buf ^ 1) ? bufH * 2 : 0u;
#pragma unroll
            for (int l = 0; l < 2; l++) {
                int r = lr + l * 64;
                cpa16(sA + o + (r * 40 + lch) * 2, A + (size_t)(row0 + r) * K + k0 + 32 + lch);
                cpa16(sB + o + (r * 40 + lch) * 2, Bt + (size_t)(col0 + r) * K + k0 + 32 + lch);
            }
            CPA_COMMIT;
        }
        const unsigned* Au = (const unsigned*)(As + buf * bufH);
        const unsigned* Bu = (const unsigned*)(Bs + buf * bufH);
        // half-index -> unsigned-index: /2
#pragma unroll
        for (int kk = 0; kk < 2; kk++) {
            int kb = kk * 16;
            unsigned a[4][4], b[4][2];
#pragma unroll
            for (int mi = 0; mi < 4; mi++) {
                int m = warpM * 64 + mi * 16;
                a[mi][0] = Au[((m + g) * 40 + kb + 2 * t) >> 1];
                a[mi][1] = Au[((m + g + 8) * 40 + kb + 2 * t) >> 1];
                a[mi][2] = Au[((m + g) * 40 + kb + 2 * t + 8) >> 1];
                a[mi][3] = Au[((m + g + 8) * 40 + kb + 2 * t + 8) >> 1];
            }
#pragma unroll
            for (int ni = 0; ni < 4; ni++) {
                int n = warpN * 32 + ni * 8;
                b[ni][0] = Bu[((n + g) * 40 + kb + 2 * t) >> 1];
                b[ni][1] = Bu[((n + g) * 40 + kb + 2 * t + 8) >> 1];
            }
#pragma unroll
            for (int mi = 0; mi < 4; mi++)
#pragma unroll
                for (int ni = 0; ni < 4; ni++)
                    mmah(c[mi][ni], a[mi], b[ni]);
        }
        __syncthreads();
    }
#pragma unroll
    for (int mi = 0; mi < 4; mi++) {
#pragma unroll
        for (int ni = 0; ni < 4; ni++) {
            int row = row0 + warpM * 64 + mi * 16 + g;
            int col = col0 + warpN * 32 + ni * 8 + 2 * t;
            if (HALF_OUT) {
                __half* C = (__half*)Cv;
                __half2 v0 = __floats2half2_rn(c[mi][ni][0], c[mi][ni][1]);
                __half2 v1 = __floats2half2_rn(c[mi][ni][2], c[mi][ni][3]);
                *(__half2*)(C + (size_t)row * N + col) = v0;
                *(__half2*)(C + (size_t)(row + 8) * N + col) = v1;
            } else {
                float* C = (float*)Cv;
                *(float2*)(C + (size_t)row * N + col) = make_float2(c[mi][ni][0], c[mi][ni][1]);
                *(float2*)(C + (size_t)(row + 8) * N + col) = make_float2(c[mi][ni][2], c[mi][ni][3]);
            }
        }
    }
}

// ---------------- scores: E(fp16) = exp(scale * Q K^T) + fp32 row sums (fp16 MMA) ----------------
// Q/K fp16. dyn smem: Qs[128*72] + Ks[2][64*72] halves + rbuf[256] floats = 37888 B
__global__ void __launch_bounds__(256) score_exp(const __half* __restrict__ Q,
                                                 const __half* __restrict__ Km,
                                                 __half* __restrict__ E,
                                                 float* __restrict__ sums) {
    extern __shared__ __half smh[];
    __half* Qs = smh;                      // 128*72
    __half* Ks = smh + 128 * 72;           // 2 x 64*72
    float* rbuf = (float*)(Ks + 2 * 64 * 72);   // 256 floats
    int tid = threadIdx.x;
    int lane = tid & 31, wid = tid >> 5;
    int g = lane >> 2, t = lane & 3;
    int warpM = wid >> 1, warpN = wid & 1;      // 4 x 2, warp tile 32x32
    int i0 = blockIdx.x * 128;
    int h = blockIdx.y, b = blockIdx.z;
    int plane = b * NH + h;

    const __half* qb = Q + ((size_t)b * NS + i0) * ND + h * NDH;
    const __half* kb = Km + (size_t)b * NS * ND + h * NDH;
    __half* Ep = E + (size_t)plane * NS * NS;

    // Q tile 128x64 halves: 1024 16B-chunks over 256 threads
#pragma unroll
    for (int l = 0; l < 4; l++) {
        int f = tid + l * 256;
        int r = f >> 3, ch = (f & 7) * 8;
        *(uint4*)(Qs + r * 72 + ch) = *(const uint4*)(qb + (size_t)r * ND + ch);
    }

    unsigned sK = (unsigned)__cvta_generic_to_shared(Ks);
    int kr = tid >> 3, kch = (tid & 7) * 8;   // covers 32 rows per 256 threads... f mapping below

    // K tile: 64 rows x 8 chunks = 512 chunks, 2 per thread
#pragma unroll
    for (int l = 0; l < 2; l++) {
        int f = tid + l * 256;
        int r = f >> 3, ch = (f & 7) * 8;
        cpa16(sK + (r * 72 + ch) * 2, kb + (size_t)r * ND + ch);
    }
    CPA_COMMIT;
    (void)kr; (void)kch;

    float rs[2][2] = {};
    int buf = 0;
    for (int jt = 0; jt < NS; jt += 64, buf ^= 1) {
        CPA_WAIT0;
        __syncthreads();
        if (jt + 64 < NS) {
            unsigned o = (buf ^ 1) ? (unsigned)(64 * 72 * 2) : 0u;
#pragma unroll
            for (int l = 0; l < 2; l++) {
                int f = tid + l * 256;
                int r = f >> 3, ch = (f & 7) * 8;
                cpa16(sK + o + (r * 72 + ch) * 2, kb + (size_t)(jt + 64 + r) * ND + ch);
            }
            CPA_COMMIT;
        }

        float c4[2][4][4] = {};
        const unsigned* Qu = (const unsigned*)Qs;
        const unsigned* Ku = (const unsigned*)(Ks + buf * (64 * 72));
#pragma unroll
        for (int kk = 0; kk < 4; kk++) {
            int kb8 = kk * 16;
            unsigned a[2][4], bfr[4][2];
#pragma unroll
            for (int mi = 0; mi < 2; mi++) {
                int m = warpM * 32 + mi * 16;
                a[mi][0] = Qu[((m + g) * 72 + kb8 + 2 * t) >> 1];
                a[mi][1] = Qu[((m + g + 8) * 72 + kb8 + 2 * t) >> 1];
                a[mi][2] = Qu[((m + g) * 72 + kb8 + 2 * t + 8) >> 1];
                a[mi][3] = Qu[((m + g + 8) * 72 + kb8 + 2 * t + 8) >> 1];
            }
#pragma unroll
            for (int ni = 0; ni < 4; ni++) {
                int n = warpN * 32 + ni * 8;
                bfr[ni][0] = Ku[((n + g) * 72 + kb8 + 2 * t) >> 1];
                bfr[ni][1] = Ku[((n + g) * 72 + kb8 + 2 * t + 8) >> 1];
            }
#pragma unroll
            for (int mi = 0; mi < 2; mi++)
#pragma unroll
                for (int ni = 0; ni < 4; ni++)
                    mmah(c4[mi][ni], a[mi], bfr[ni]);
        }
#pragma unroll
        for (int mi = 0; mi < 2; mi++) {
#pragma unroll
            for (int ni = 0; ni < 4; ni++) {
                float e0 = __expf(c4[mi][ni][0] * SCORE_SCALE);
                float e1 = __expf(c4[mi][ni][1] * SCORE_SCALE);
                float e2 = __expf(c4[mi][ni][2] * SCORE_SCALE);
                float e3 = __expf(c4[mi][ni][3] * SCORE_SCALE);
                rs[mi][0] += e0 + e1;
                rs[mi][1] += e2 + e3;
                int row = i0 + warpM * 32 + mi * 16 + g;
                int col = jt + warpN * 32 + ni * 8 + 2 * t;
                *(__half2*)(Ep + (size_t)row * NS + col) = __floats2half2_rn(e0, e1);
                *(__half2*)(Ep + (size_t)(row + 8) * NS + col) = __floats2half2_rn(e2, e3);
            }
        }
        __syncthreads();
    }

#pragma unroll
    for (int mi = 0; mi < 2; mi++)
#pragma unroll
        for (int hf = 0; hf < 2; hf++) {
            float v = rs[mi][hf];
            v += __shfl_xor_sync(0xffffffffu, v, 1);
            v += __shfl_xor_sync(0xffffffffu, v, 2);
            rs[mi][hf] = v;
        }
    if (t == 0) {
#pragma unroll
        for (int mi = 0; mi < 2; mi++)
#pragma unroll
            for (int hf = 0; hf < 2; hf++) {
                int r = warpM * 32 + mi * 16 + hf * 8 + g;
                rbuf[r * 2 + warpN] = rs[mi][hf];
            }
    }
    __syncthreads();
    if (tid < 128)
        sums[(size_t)plane * NS + i0 + tid] = rbuf[tid * 2] + rbuf[tid * 2 + 1];
}

// ---------------- blend + interleave into [b][i][j][h] (fp16 E reads) ----------------
__global__ void __launch_bounds__(256) blend_kernel(float* __restrict__ outP) {
    __shared__ float sb[12 * 515];
    __shared__ float sIs[12], sPs[12];
    int b = blockIdx.x, i = blockIdx.y;
    int tid = threadIdx.x;
    if (tid < 12) sIs[tid] = 0.5f / g_sumI[(b * 12 + tid) * NS + i];
    else if (tid < 24) sPs[tid - 12] = 0.5f / g_sumP[(tid - 12) * NS + i];
    __syncthreads();
    size_t outBase = ((size_t)(b * NS + i)) * ((size_t)NS * NH);
    for (int jt = 0; jt < NS; jt += 512) {
#pragma unroll
        for (int l = 0; l < 12; l++) {
            int e = tid + l * 256;
            int h = e >> 8, j2 = e & 255;
            size_t idxI = ((size_t)(b * NH + h) * NS + i) * NS + jt + 2 * j2;
            size_t idxP = ((size_t)h * NS + i) * NS + jt + 2 * j2;
            float2 f1 = __half22float2(*(const __half2*)(g_Einp + idxI));
            float2 f2 = __half22float2(*(const __half2*)(g_Epos + idxP));
            float si = sIs[h], sp = sPs[h];
            sb[h * 515 + 2 * j2]     = f1.x * si + f2.x * sp;
            sb[h * 515 + 2 * j2 + 1] = f1.y * si + f2.y * sp;
        }
        __syncthreads();
#pragma unroll
        for (int l = 0; l < 24; l++) {
            int e = tid + l * 256;
            int j = e / 12, h = e - j * 12;
            outP[outBase + (size_t)jt * NH + e] = sb[h * 515 + j];
        }
        __syncthreads();
    }
}

// ---------------- PV (tf32 MMA, fp16 E/V reads): AO(fp16) = blend(P) @ V ----------------
__global__ void __launch_bounds__(256) pv_mma() {
    __shared__ float As[64 * 36];
    __shared__ float Vs[32 * 68];
    __shared__ float invI[64], invP[64];
    int tid = threadIdx.x;
    int lane = tid & 31, wid = tid >> 5;
    int g = lane >> 2, t = lane & 3;
    int warpM = wid >> 1, warpN = wid & 1;       // 4 x 2, warp tile 16x32
    int i0 = blockIdx.x * 64;
    int b = blockIdx.y, h = blockIdx.z;
    int plane = b * NH + h;

    const __half* Ei = g_Einp + (size_t)plane * NS * NS;
    const __half* Epp = g_Epos + (size_t)h * NS * NS;
    const __half* Vb = g_V + (size_t)b * NS * ND + h * NDH;

    if (tid < 64) invI[tid] = 0.5f / g_sumI[(size_t)plane * NS + i0 + tid];
    else if (tid < 128) invP[tid - 64] = 0.5f / g_sumP[(size_t)h * NS + i0 + tid - 64];
    __syncthreads();

    float c4[4][4] = {};
    int ar = tid >> 3, ac = (tid & 7) * 4;
    int vr = tid >> 3, vch = (tid & 7) * 8;      // V: 32 rows x 8 chunks = 256, 1/thread

    uint2 pe1[2], pe2[2];
    uint4 pvv;
#pragma unroll
    for (int rr = 0; rr < 2; rr++) {
        size_t off = (size_t)(i0 + ar + rr * 32) * NS + ac;
        pe1[rr] = *(const uint2*)(Ei + off);
        pe2[rr] = *(const uint2*)(Epp + off);
    }
    pvv = *(const uint4*)(Vb + (size_t)vr * ND + vch);

    for (int k0 = 0; k0 < NS; k0 += 32) {
#pragma unroll
        for (int rr = 0; rr < 2; rr++) {
            int r = ar + rr * 32;
            float si = invI[r], sp = invP[r];
            float2 a0 = __half22float2(*(__half2*)&pe1[rr].x);
            float2 a1 = __half22float2(*(__half2*)&pe1[rr].y);
            float2 b0 = __half22float2(*(__half2*)&pe2[rr].x);
            float2 b1 = __half22float2(*(__half2*)&pe2[rr].y);
            float* d = &As[r * 36 + ac];
            d[0] = f2tff(a0.x * si + b0.x * sp);
            d[1] = f2tff(a0.y * si + b0.y * sp);
            d[2] = f2tff(a1.x * si + b1.x * sp);
            d[3] = f2tff(a1.y * si + b1.y * sp);
        }
        {
            // V: fp16 -> fp32 (exact; fp16 mantissa <= tf32)
            __half2* hp = (__half2*)&pvv;
            float* dv = &Vs[vr * 68 + vch];
            float2 v0 = __half22float2(hp[0]);
            float2 v1 = __half22float2(hp[1]);
            float2 v2 = __half22float2(hp[2]);
            float2 v3 = __half22float2(hp[3]);
            dv[0] = v0.x; dv[1] = v0.y; dv[2] = v1.x; dv[3] = v1.y;
            dv[4] = v2.x; dv[5] = v2.y; dv[6] = v3.x; dv[7] = v3.y;
        }
        __syncthreads();

        if (k0 + 32 < NS) {
#pragma unroll
            for (int rr = 0; rr < 2; rr++) {
                size_t off = (size_t)(i0 + ar + rr * 32) * NS + k0 + 32 + ac;
                pe1[rr] = *(const uint2*)(Ei + off);
                pe2[rr] = *(const uint2*)(Epp + off);
            }
            pvv = *(const uint4*)(Vb + (size_t)(k0 + 32 + vr) * ND + vch);
        }

        const unsigned* Au = (const unsigned*)As;
        const unsigned* Vu = (const unsigned*)Vs;
#pragma unroll
        for (int kk = 0; kk < 4; kk++) {
            int k8 = kk * 8;
            unsigned a[4], bfr[4][2];
            int m = warpM * 16;
            a[0] = Au[(m + g) * 36 + k8 + t];
            a[1] = Au[(m + g + 8) * 36 + k8 + t];
            a[2] = Au[(m + g) * 36 + k8 + t + 4];
            a[3] = Au[(m + g + 8) * 36 + k8 + t + 4];
#pragma unroll
            for (int ni = 0; ni < 4; ni++) {
                int n = warpN * 32 + ni * 8;
                bfr[ni][0] = Vu[(k8 + t) * 68 + n + g];
                bfr[ni][1] = Vu[(k8 + t + 4) * 68 + n + g];
            }
#pragma unroll
            for (int ni = 0; ni < 4; ni++)
                mma8(c4[ni], a, bfr[ni]);
        }
        __syncthreads();
    }
#pragma unroll
    for (int ni = 0; ni < 4; ni++) {
        int row = i0 + warpM * 16 + g;
        int col = warpN * 32 + ni * 8 + 2 * t;
        __half* dst = g_AO + (size_t)(b * NS + row) * ND + h * NDH + col;
        *(__half2*)dst = __floats2half2_rn(c4[ni][0], c4[ni][1]);
        *(__half2*)(dst + (size_t)8 * ND) = __floats2half2_rn(c4[ni][2], c4[ni][3]);
    }
}

// ---------------- launch ----------------
extern "C" void kernel_launch(void* const* d_in, const int* in_sizes, int n_in,
                              void* d_out, int out_size) {
    (void)in_sizes; (void)n_in; (void)out_size;
    const float* inp    = (const float*)d_in[0];
    const float* pos    = (const float*)d_in[1];
    const float* Wq_inp = (const float*)d_in[2];
    const float* Wk_inp = (const float*)d_in[3];
    const float* Wq_pos = (const float*)d_in[4];
    const float* Wk_pos = (const float*)d_in[5];
    const float* Wv     = (const float*)d_in[6];
    const float* Wo     = (const float*)d_in[7];

    float* out      = (float*)d_out;
    float* out_attn = out;
    float* out_prob = out + (size_t)NBAT * NS * ND;

    __half *pW6, *pAin, *pPin, *pQ, *pK, *pV, *pQp, *pKp, *pEi, *pEp, *pAO;
    float *pSi, *pSp;
    cudaGetSymbolAddress((void**)&pW6,  g_W6);
    cudaGetSymbolAddress((void**)&pAin, g_Ain);
    cudaGetSymbolAddress((void**)&pPin, g_Pin);
    cudaGetSymbolAddress((void**)&pQ,   g_Q);
    cudaGetSymbolAddress((void**)&pK,   g_K);
    cudaGetSymbolAddress((void**)&pV,   g_V);
    cudaGetSymbolAddress((void**)&pQp,  g_Qp);
    cudaGetSymbolAddress((void**)&pKp,  g_Kp);
    cudaGetSymbolAddress((void**)&pEi,  g_Einp);
    cudaGetSymbolAddress((void**)&pEp,  g_Epos);
    cudaGetSymbolAddress((void**)&pSi,  g_sumI);
    cudaGetSymbolAddress((void**)&pSp,  g_sumP);
    cudaGetSymbolAddress((void**)&pAO,  g_AO);

    const int WELEM = 768 * 768;

    conv_h<<<(4096 * 768 / 4 + 255) / 256, 256>>>(inp, pAin, 4096 * 768 / 4);
    conv_h<<<(2048 * 768 / 4 + 255) / 256, 256>>>(pos, pPin, 2048 * 768 / 4);
    {
        dim3 g(24, 24, 6);
        prep_weights<<<g, 256>>>(Wq_inp, Wk_inp, Wq_pos, Wk_pos, Wv, Wo, pW6);
    }

    int gemmSmem = 2 * 2 * 128 * 40 * (int)sizeof(__half);   // 40960
    cudaFuncSetAttribute(gemm_fp16<true>,  cudaFuncAttributeMaxDynamicSharedMemorySize, gemmSmem);
    cudaFuncSetAttribute(gemm_fp16<false>, cudaFuncAttributeMaxDynamicSharedMemorySize, gemmSmem);

    {
        dim3 gI(4096 / 128, 768 / 128);
        gemm_fp16<true><<<gI, 256, gemmSmem>>>(pAin, pW6 + 0 * WELEM, pQ, 4096, 768, 768);
        gemm_fp16<true><<<gI, 256, gemmSmem>>>(pAin, pW6 + 1 * WELEM, pK, 4096, 768, 768);
        gemm_fp16<true><<<gI, 256, gemmSmem>>>(pAin, pW6 + 4 * WELEM, pV, 4096, 768, 768);
        dim3 gP(2048 / 128, 768 / 128);
        gemm_fp16<true><<<gP, 256, gemmSmem>>>(pPin, pW6 + 2 * WELEM, pQp, 2048, 768, 768);
        gemm_fp16<true><<<gP, 256, gemmSmem>>>(pPin, pW6 + 3 * WELEM, pKp, 2048, 768, 768);
    }

    {
        int dynBytes = (128 * 72 + 2 * 64 * 72) * (int)sizeof(__half) + 256 * (int)sizeof(float);  // 37888
        cudaFuncSetAttribute(score_exp, cudaFuncAttributeMaxDynamicSharedMemorySize, dynBytes);
        dim3 gInp(NS / 128, NH, NBAT);
        score_exp<<<gInp, 256, dynBytes>>>(pQ, pK, pEi, pSi);
        dim3 gPos(NS / 128, NH, 1);
        score_exp<<<gPos, 256, dynBytes>>>(pQp, pKp, pEp, pSp);
    }

    {
        dim3 g(NBAT, NS);
        blend_kernel<<<g, 256>>>(out_prob);
    }

    {
        dim3 g(NS / 64, NBAT, NH);
        pv_mma<<<g, 256>>>();
    }

    {
        dim3 g(4096 / 128, 768 / 128);
        gemm_fp16<false><<<g, 256, gemmSmem>>>(pAO, pW6 + 5 * WELEM, out_attn, 4096, 768, 768);
    }
}

// round 13
// speedup vs baseline: 1.9218x; 1.1675x over previous
#include <cuda_runtime.h>
#include <cuda_fp16.h>
#include <math.h>

#define NS   2048
#define NBAT 2
#define ND   768
#define NH   12
#define NDH  64
static const float SCORE_SCALE = 0.125f;   // 1/sqrt(64) * smoothing

// ---------------- scratch ----------------
__device__ __half g_W6[6][768 * 768];                      // [n][k] fp16: 5 perm'd proj weights + Wo^T
__device__ __half g_Ain[4096 * 768];                       // fp16 inp
__device__ __half g_Pin[2048 * 768];                       // fp16 pos_emb
__device__ __half g_Q [4096 * 768];
__device__ __half g_K [4096 * 768];
__device__ __half g_V [4096 * 768];
__device__ __half g_Qp[2048 * 768];
__device__ __half g_Kp[2048 * 768];
__device__ __half g_Einp[(size_t)2 * 12 * 2048 * 2048];    // exp(scores), fp16
__device__ __half g_Epos[(size_t)12 * 2048 * 2048];
__device__ float g_sumI[2 * 12 * 2048];                    // fp32 row sums
__device__ float g_sumP[12 * 2048];
__device__ __half g_AO[4096 * 768];                        // fp16 attn-out pre-Wo

// ---------------- helpers ----------------
__device__ __forceinline__ void mmah(float c[4], const unsigned a[4], const unsigned b[2]) {
    asm volatile(
        "mma.sync.aligned.m16n8k16.row.col.f32.f16.f16.f32 "
        "{%0,%1,%2,%3},{%4,%5,%6,%7},{%8,%9},{%0,%1,%2,%3};"
        : "+f"(c[0]), "+f"(c[1]), "+f"(c[2]), "+f"(c[3])
        : "r"(a[0]), "r"(a[1]), "r"(a[2]), "r"(a[3]), "r"(b[0]), "r"(b[1]));
}
__device__ __forceinline__ void cpa16(unsigned s, const void* g) {
    asm volatile("cp.async.ca.shared.global [%0], [%1], 16;" :: "r"(s), "l"(g));
}
#define CPA_COMMIT asm volatile("cp.async.commit_group;")
#define CPA_WAIT0  asm volatile("cp.async.wait_group 0;")

// ---------------- float -> fp16 convert-copy ----------------
__global__ void conv_h(const float* __restrict__ src, __half* __restrict__ dst, int n4) {
    int i = blockIdx.x * 256 + threadIdx.x;
    if (i >= n4) return;
    float4 v = ((const float4*)src)[i];
    __half2 h0 = __floats2half2_rn(v.x, v.y);
    __half2 h1 = __floats2half2_rn(v.z, v.w);
    uint2 o = make_uint2(*(unsigned*)&h0, *(unsigned*)&h1);
    ((uint2*)dst)[i] = o;
}

// ---------------- weight prep: transpose (+ head permutation) to [n][k] fp16 ----------------
__global__ void prep_weights(const float* __restrict__ W0, const float* __restrict__ W1,
                             const float* __restrict__ W2, const float* __restrict__ W3,
                             const float* __restrict__ W4, const float* __restrict__ W5) {
    __shared__ __half ts[32][33];
    int w = blockIdx.z;
    const float* W = (w == 0) ? W0 : (w == 1) ? W1 : (w == 2) ? W2 : (w == 3) ? W3
                   : (w == 4) ? W4 : W5;
    int k0 = blockIdx.x * 32, j0 = blockIdx.y * 32;
    int tid = threadIdx.x;
    int r = tid >> 5, c = tid & 31;
#pragma unroll
    for (int l = 0; l < 4; l++) {
        int k = k0 + r + l * 8;
        ts[c][r + l * 8] = __float2half_rn(W[(size_t)k * 768 + j0 + c]);
    }
    __syncthreads();
#pragma unroll
    for (int l = 0; l < 4; l++) {
        int j = j0 + r + l * 8;
        int n = (w < 5) ? ((j % 12) * 64 + j / 12) : j;
        g_W6[w][(size_t)n * 768 + k0 + c] = ts[r + l * 8][c];
    }
}

// ---------------- fp16 MMA GEMM core, 128x128 CTA tile, cp.async double-buffered ----------------
// C[M,N] = A[M,K] @ B^T with A[M][K], Bt[N][K] fp16 row-major. N=K=768, BK=32.
template <bool HALF_OUT>
__device__ __forceinline__ void gemm_core(const __half* __restrict__ A,
                                          const __half* __restrict__ Bt,
                                          void* __restrict__ Cv, int M) {
    const int N = 768, K = 768;
    extern __shared__ __half smh[];
    __half* As = smh;                  // 2 x 128*40
    __half* Bs = smh + 2 * 128 * 40;   // 2 x 128*40
    int tid = threadIdx.x;
    int lane = tid & 31, wid = tid >> 5;
    int g = lane >> 2, t = lane & 3;
    int warpM = wid >> 2, warpN = wid & 3;        // 2 x 4 warps, 64x32 warp tiles
    int row0 = blockIdx.x * 128, col0 = blockIdx.y * 128;

    float c[4][4][4] = {};
    int lr = tid >> 2, lch = (tid & 3) * 8;

    unsigned sA = (unsigned)__cvta_generic_to_shared(As);
    unsigned sB = (unsigned)__cvta_generic_to_shared(Bs);
    const unsigned bufH = 128 * 40;

#pragma unroll
    for (int l = 0; l < 2; l++) {
        int r = lr + l * 64;
        cpa16(sA + (r * 40 + lch) * 2, A + (size_t)(row0 + r) * K + lch);
        cpa16(sB + (r * 40 + lch) * 2, Bt + (size_t)(col0 + r) * K + lch);
    }
    CPA_COMMIT;

    int buf = 0;
    for (int k0 = 0; k0 < K; k0 += 32, buf ^= 1) {
        CPA_WAIT0;
        __syncthreads();
        if (k0 + 32 < K) {
            unsigned o = (buf ^ 1) ? bufH * 2 : 0u;
#pragma unroll
            for (int l = 0; l < 2; l++) {
                int r = lr + l * 64;
                cpa16(sA + o + (r * 40 + lch) * 2, A + (size_t)(row0 + r) * K + k0 + 32 + lch);
                cpa16(sB + o + (r * 40 + lch) * 2, Bt + (size_t)(col0 + r) * K + k0 + 32 + lch);
            }
            CPA_COMMIT;
        }
        const unsigned* Au = (const unsigned*)(As + buf * bufH);
        const unsigned* Bu = (const unsigned*)(Bs + buf * bufH);
#pragma unroll
        for (int kk = 0; kk < 2; kk++) {
            int kb = kk * 16;
            unsigned a[4][4], b[4][2];
#pragma unroll
            for (int mi = 0; mi < 4; mi++) {
                int m = warpM * 64 + mi * 16;
                a[mi][0] = Au[((m + g) * 40 + kb + 2 * t) >> 1];
                a[mi][1] = Au[((m + g + 8) * 40 + kb + 2 * t) >> 1];
                a[mi][2] = Au[((m + g) * 40 + kb + 2 * t + 8) >> 1];
                a[mi][3] = Au[((m + g + 8) * 40 + kb + 2 * t + 8) >> 1];
            }
#pragma unroll
            for (int ni = 0; ni < 4; ni++) {
                int n = warpN * 32 + ni * 8;
                b[ni][0] = Bu[((n + g) * 40 + kb + 2 * t) >> 1];
                b[ni][1] = Bu[((n + g) * 40 + kb + 2 * t + 8) >> 1];
            }
#pragma unroll
            for (int mi = 0; mi < 4; mi++)
#pragma unroll
                for (int ni = 0; ni < 4; ni++)
                    mmah(c[mi][ni], a[mi], b[ni]);
        }
        __syncthreads();
    }
#pragma unroll
    for (int mi = 0; mi < 4; mi++) {
#pragma unroll
        for (int ni = 0; ni < 4; ni++) {
            int row = row0 + warpM * 64 + mi * 16 + g;
            int col = col0 + warpN * 32 + ni * 8 + 2 * t;
            if (HALF_OUT) {
                __half* C = (__half*)Cv;
                *(__half2*)(C + (size_t)row * N + col) = __floats2half2_rn(c[mi][ni][0], c[mi][ni][1]);
                *(__half2*)(C + (size_t)(row + 8) * N + col) = __floats2half2_rn(c[mi][ni][2], c[mi][ni][3]);
            } else {
                float* C = (float*)Cv;
                *(float2*)(C + (size_t)row * N + col) = make_float2(c[mi][ni][0], c[mi][ni][1]);
                *(float2*)(C + (size_t)(row + 8) * N + col) = make_float2(c[mi][ni][2], c[mi][ni][3]);
            }
        }
    }
}

// batched Q/K/V projections (blockIdx.z selects)
__global__ void __launch_bounds__(256, 2) gemm_qkv() {
    int z = blockIdx.z;
    const __half* Bt = g_W6[(z == 2) ? 4 : z];
    __half* C = (z == 0) ? g_Q : (z == 1) ? g_K : g_V;
    gemm_core<true>(g_Ain, Bt, C, 4096);
}
// batched Qp/Kp projections
__global__ void __launch_bounds__(256, 2) gemm_qkp() {
    int z = blockIdx.z;
    gemm_core<true>(g_Pin, g_W6[2 + z], z ? g_Kp : g_Qp, 2048);
}
// Wo GEMM (fp32 out, writes out_attn)
__global__ void __launch_bounds__(256, 2) gemm_wo(float* __restrict__ C) {
    gemm_core<false>(g_AO, g_W6[5], C, 4096);
}

// ---------------- scores: E(fp16) = exp(scale * Q K^T) + fp32 row sums (fp16 MMA) ----------------
__global__ void __launch_bounds__(256) score_exp(const __half* __restrict__ Q,
                                                 const __half* __restrict__ Km,
                                                 __half* __restrict__ E,
                                                 float* __restrict__ sums) {
    extern __shared__ __half smh[];
    __half* Qs = smh;                      // 128*72
    __half* Ks = smh + 128 * 72;           // 2 x 64*72
    float* rbuf = (float*)(Ks + 2 * 64 * 72);   // 256 floats
    int tid = threadIdx.x;
    int lane = tid & 31, wid = tid >> 5;
    int g = lane >> 2, t = lane & 3;
    int warpM = wid >> 1, warpN = wid & 1;      // 4 x 2, warp tile 32x32
    int i0 = blockIdx.x * 128;
    int h = blockIdx.y, b = blockIdx.z;
    int plane = b * NH + h;

    const __half* qb = Q + ((size_t)b * NS + i0) * ND + h * NDH;
    const __half* kb = Km + (size_t)b * NS * ND + h * NDH;
    __half* Ep = E + (size_t)plane * NS * NS;

#pragma unroll
    for (int l = 0; l < 4; l++) {
        int f = tid + l * 256;
        int r = f >> 3, ch = (f & 7) * 8;
        *(uint4*)(Qs + r * 72 + ch) = *(const uint4*)(qb + (size_t)r * ND + ch);
    }

    unsigned sK = (unsigned)__cvta_generic_to_shared(Ks);
#pragma unroll
    for (int l = 0; l < 2; l++) {
        int f = tid + l * 256;
        int r = f >> 3, ch = (f & 7) * 8;
        cpa16(sK + (r * 72 + ch) * 2, kb + (size_t)r * ND + ch);
    }
    CPA_COMMIT;

    float rs[2][2] = {};
    int buf = 0;
    for (int jt = 0; jt < NS; jt += 64, buf ^= 1) {
        CPA_WAIT0;
        __syncthreads();
        if (jt + 64 < NS) {
            unsigned o = (buf ^ 1) ? (unsigned)(64 * 72 * 2) : 0u;
#pragma unroll
            for (int l = 0; l < 2; l++) {
                int f = tid + l * 256;
                int r = f >> 3, ch = (f & 7) * 8;
                cpa16(sK + o + (r * 72 + ch) * 2, kb + (size_t)(jt + 64 + r) * ND + ch);
            }
            CPA_COMMIT;
        }

        float c4[2][4][4] = {};
        const unsigned* Qu = (const unsigned*)Qs;
        const unsigned* Ku = (const unsigned*)(Ks + buf * (64 * 72));
#pragma unroll
        for (int kk = 0; kk < 4; kk++) {
            int kb8 = kk * 16;
            unsigned a[2][4], bfr[4][2];
#pragma unroll
            for (int mi = 0; mi < 2; mi++) {
                int m = warpM * 32 + mi * 16;
                a[mi][0] = Qu[((m + g) * 72 + kb8 + 2 * t) >> 1];
                a[mi][1] = Qu[((m + g + 8) * 72 + kb8 + 2 * t) >> 1];
                a[mi][2] = Qu[((m + g) * 72 + kb8 + 2 * t + 8) >> 1];
                a[mi][3] = Qu[((m + g + 8) * 72 + kb8 + 2 * t + 8) >> 1];
            }
#pragma unroll
            for (int ni = 0; ni < 4; ni++) {
                int n = warpN * 32 + ni * 8;
                bfr[ni][0] = Ku[((n + g) * 72 + kb8 + 2 * t) >> 1];
                bfr[ni][1] = Ku[((n + g) * 72 + kb8 + 2 * t + 8) >> 1];
            }
#pragma unroll
            for (int mi = 0; mi < 2; mi++)
#pragma unroll
                for (int ni = 0; ni < 4; ni++)
                    mmah(c4[mi][ni], a[mi], bfr[ni]);
        }
#pragma unroll
        for (int mi = 0; mi < 2; mi++) {
#pragma unroll
            for (int ni = 0; ni < 4; ni++) {
                float e0 = __expf(c4[mi][ni][0] * SCORE_SCALE);
                float e1 = __expf(c4[mi][ni][1] * SCORE_SCALE);
                float e2 = __expf(c4[mi][ni][2] * SCORE_SCALE);
                float e3 = __expf(c4[mi][ni][3] * SCORE_SCALE);
                rs[mi][0] += e0 + e1;
                rs[mi][1] += e2 + e3;
                int row = i0 + warpM * 32 + mi * 16 + g;
                int col = jt + warpN * 32 + ni * 8 + 2 * t;
                *(__half2*)(Ep + (size_t)row * NS + col) = __floats2half2_rn(e0, e1);
                *(__half2*)(Ep + (size_t)(row + 8) * NS + col) = __floats2half2_rn(e2, e3);
            }
        }
        __syncthreads();
    }

#pragma unroll
    for (int mi = 0; mi < 2; mi++)
#pragma unroll
        for (int hf = 0; hf < 2; hf++) {
            float v = rs[mi][hf];
            v += __shfl_xor_sync(0xffffffffu, v, 1);
            v += __shfl_xor_sync(0xffffffffu, v, 2);
            rs[mi][hf] = v;
        }
    if (t == 0) {
#pragma unroll
        for (int mi = 0; mi < 2; mi++)
#pragma unroll
            for (int hf = 0; hf < 2; hf++) {
                int r = warpM * 32 + mi * 16 + hf * 8 + g;
                rbuf[r * 2 + warpN] = rs[mi][hf];
            }
    }
    __syncthreads();
    if (tid < 128)
        sums[(size_t)plane * NS + i0 + tid] = rbuf[tid * 2] + rbuf[tid * 2 + 1];
}

// ---------------- blend + interleave into [b][i][j][h] (fp16 E reads) ----------------
__global__ void __launch_bounds__(256) blend_kernel(float* __restrict__ outP) {
    __shared__ float sb[12 * 515];
    __shared__ float sIs[12], sPs[12];
    int b = blockIdx.x, i = blockIdx.y;
    int tid = threadIdx.x;
    if (tid < 12) sIs[tid] = 0.5f / g_sumI[(b * 12 + tid) * NS + i];
    else if (tid < 24) sPs[tid - 12] = 0.5f / g_sumP[(tid - 12) * NS + i];
    __syncthreads();
    size_t outBase = ((size_t)(b * NS + i)) * ((size_t)NS * NH);
    for (int jt = 0; jt < NS; jt += 512) {
#pragma unroll
        for (int l = 0; l < 12; l++) {
            int e = tid + l * 256;
            int h = e >> 8, j2 = e & 255;
            size_t idxI = ((size_t)(b * NH + h) * NS + i) * NS + jt + 2 * j2;
            size_t idxP = ((size_t)h * NS + i) * NS + jt + 2 * j2;
            float2 f1 = __half22float2(*(const __half2*)(g_Einp + idxI));
            float2 f2 = __half22float2(*(const __half2*)(g_Epos + idxP));
            float si = sIs[h], sp = sPs[h];
            sb[h * 515 + 2 * j2]     = f1.x * si + f2.x * sp;
            sb[h * 515 + 2 * j2 + 1] = f1.y * si + f2.y * sp;
        }
        __syncthreads();
#pragma unroll
        for (int l = 0; l < 24; l++) {
            int e = tid + l * 256;
            int j = e / 12, h = e - j * 12;
            outP[outBase + (size_t)jt * NH + e] = sb[h * 515 + j];
        }
        __syncthreads();
    }
}

// ---------------- PV (fp16 MMA): AO(fp16) = blend(P) @ V ----------------
// grid: (NS/64, NBAT, NH). CTA tile 64(i) x 64(d), k loop 32.
__global__ void __launch_bounds__(256) pv_mma() {
    __shared__ __half As[64 * 40];    // blended P, [i][j]
    __shared__ __half Vt[64 * 34];    // V^T tile, [d][j], stride 34
    __shared__ float invI[64], invP[64];
    int tid = threadIdx.x;
    int lane = tid & 31, wid = tid >> 5;
    int g = lane >> 2, t = lane & 3;
    int warpM = wid >> 1, warpN = wid & 1;       // 4 x 2, warp tile 16(m)x32(n)
    int i0 = blockIdx.x * 64;
    int b = blockIdx.y, h = blockIdx.z;
    int plane = b * NH + h;

    const __half* Ei = g_Einp + (size_t)plane * NS * NS;
    const __half* Epp = g_Epos + (size_t)h * NS * NS;
    const __half* Vb = g_V + (size_t)b * NS * ND + h * NDH;

    if (tid < 64) invI[tid] = 0.5f / g_sumI[(size_t)plane * NS + i0 + tid];
    else if (tid < 128) invP[tid - 64] = 0.5f / g_sumP[(size_t)h * NS + i0 + tid - 64];
    __syncthreads();

    float c4[4][4] = {};
    int ar = tid >> 3, ac = (tid & 7) * 4;       // E: rows ar, ar+32; 4 halves at col ac
    int vr = tid >> 3, vch = (tid & 7) * 8;      // V: row vr, 8 halves at col vch

    uint2 pe1[2], pe2[2];
    uint4 pvv;
#pragma unroll
    for (int rr = 0; rr < 2; rr++) {
        size_t off = (size_t)(i0 + ar + rr * 32) * NS + ac;
        pe1[rr] = *(const uint2*)(Ei + off);
        pe2[rr] = *(const uint2*)(Epp + off);
    }
    pvv = *(const uint4*)(Vb + (size_t)vr * ND + vch);

    for (int k0 = 0; k0 < NS; k0 += 32) {
        // blend -> half, store to As
#pragma unroll
        for (int rr = 0; rr < 2; rr++) {
            int r = ar + rr * 32;
            float si = invI[r], sp = invP[r];
            float2 a0 = __half22float2(*(__half2*)&pe1[rr].x);
            float2 a1 = __half22float2(*(__half2*)&pe1[rr].y);
            float2 b0 = __half22float2(*(__half2*)&pe2[rr].x);
            float2 b1 = __half22float2(*(__half2*)&pe2[rr].y);
            __half2 h0 = __floats2half2_rn(a0.x * si + b0.x * sp, a0.y * si + b0.y * sp);
            __half2 h1 = __floats2half2_rn(a1.x * si + b1.x * sp, a1.y * si + b1.y * sp);
            *(uint2*)(As + r * 40 + ac) = make_uint2(*(unsigned*)&h0, *(unsigned*)&h1);
        }
        // V tile transpose: [j][d] -> Vt[d][j]
        {
            const __half* hp = (const __half*)&pvv;
#pragma unroll
            for (int i = 0; i < 8; i++)
                Vt[(vch + i) * 34 + vr] = hp[i];
        }
        __syncthreads();

        if (k0 + 32 < NS) {
#pragma unroll
            for (int rr = 0; rr < 2; rr++) {
                size_t off = (size_t)(i0 + ar + rr * 32) * NS + k0 + 32 + ac;
                pe1[rr] = *(const uint2*)(Ei + off);
                pe2[rr] = *(const uint2*)(Epp + off);
            }
            pvv = *(const uint4*)(Vb + (size_t)(k0 + 32 + vr) * ND + vch);
        }

        const unsigned* Au = (const unsigned*)As;
        const unsigned* Vu = (const unsigned*)Vt;
#pragma unroll
        for (int kk = 0; kk < 2; kk++) {
            int kb = kk * 16;
            unsigned a[4], bfr[4][2];
            int m = warpM * 16;
            a[0] = Au[((m + g) * 40 + kb + 2 * t) >> 1];
            a[1] = Au[((m + g + 8) * 40 + kb + 2 * t) >> 1];
            a[2] = Au[((m + g) * 40 + kb + 2 * t + 8) >> 1];
            a[3] = Au[((m + g + 8) * 40 + kb + 2 * t + 8) >> 1];
#pragma unroll
            for (int ni = 0; ni < 4; ni++) {
                int n = warpN * 32 + ni * 8;
                bfr[ni][0] = Vu[((n + g) * 34 + kb + 2 * t) >> 1];
                bfr[ni][1] = Vu[((n + g) * 34 + kb + 2 * t + 8) >> 1];
            }
#pragma unroll
            for (int ni = 0; ni < 4; ni++)
                mmah(c4[ni], a, bfr[ni]);
        }
        __syncthreads();
    }
#pragma unroll
    for (int ni = 0; ni < 4; ni++) {
        int row = i0 + warpM * 16 + g;
        int col = warpN * 32 + ni * 8 + 2 * t;
        __half* dst = g_AO + (size_t)(b * NS + row) * ND + h * NDH + col;
        *(__half2*)dst = __floats2half2_rn(c4[ni][0], c4[ni][1]);
        *(__half2*)(dst + (size_t)8 * ND) = __floats2half2_rn(c4[ni][2], c4[ni][3]);
    }
}

// ---------------- launch ----------------
extern "C" void kernel_launch(void* const* d_in, const int* in_sizes, int n_in,
                              void* d_out, int out_size) {
    (void)in_sizes; (void)n_in; (void)out_size;
    const float* inp    = (const float*)d_in[0];
    const float* pos    = (const float*)d_in[1];
    const float* Wq_inp = (const float*)d_in[2];
    const float* Wk_inp = (const float*)d_in[3];
    const float* Wq_pos = (const float*)d_in[4];
    const float* Wk_pos = (const float*)d_in[5];
    const float* Wv     = (const float*)d_in[6];
    const float* Wo     = (const float*)d_in[7];

    float* out      = (float*)d_out;
    float* out_attn = out;
    float* out_prob = out + (size_t)NBAT * NS * ND;

    __half *pAin, *pPin, *pQ, *pK, *pQp, *pKp, *pEi, *pEp;
    float *pSi, *pSp;
    cudaGetSymbolAddress((void**)&pAin, g_Ain);
    cudaGetSymbolAddress((void**)&pPin, g_Pin);
    cudaGetSymbolAddress((void**)&pQ,   g_Q);
    cudaGetSymbolAddress((void**)&pK,   g_K);
    cudaGetSymbolAddress((void**)&pQp,  g_Qp);
    cudaGetSymbolAddress((void**)&pKp,  g_Kp);
    cudaGetSymbolAddress((void**)&pEi,  g_Einp);
    cudaGetSymbolAddress((void**)&pEp,  g_Epos);
    cudaGetSymbolAddress((void**)&pSi,  g_sumI);
    cudaGetSymbolAddress((void**)&pSp,  g_sumP);

    conv_h<<<(4096 * 768 / 4 + 255) / 256, 256>>>(inp, pAin, 4096 * 768 / 4);
    conv_h<<<(2048 * 768 / 4 + 255) / 256, 256>>>(pos, pPin, 2048 * 768 / 4);
    {
        dim3 g(24, 24, 6);
        prep_weights<<<g, 256>>>(Wq_inp, Wk_inp, Wq_pos, Wk_pos, Wv, Wo);
    }

    int gemmSmem = 2 * 2 * 128 * 40 * (int)sizeof(__half);   // 40960
    cudaFuncSetAttribute(gemm_qkv, cudaFuncAttributeMaxDynamicSharedMemorySize, gemmSmem);
    cudaFuncSetAttribute(gemm_qkp, cudaFuncAttributeMaxDynamicSharedMemorySize, gemmSmem);
    cudaFuncSetAttribute(gemm_wo,  cudaFuncAttributeMaxDynamicSharedMemorySize, gemmSmem);

    gemm_qkv<<<dim3(4096 / 128, 768 / 128, 3), 256, gemmSmem>>>();
    gemm_qkp<<<dim3(2048 / 128, 768 / 128, 2), 256, gemmSmem>>>();

    {
        int dynBytes = (128 * 72 + 2 * 64 * 72) * (int)sizeof(__half) + 256 * (int)sizeof(float);
        cudaFuncSetAttribute(score_exp, cudaFuncAttributeMaxDynamicSharedMemorySize, dynBytes);
        dim3 gInp(NS / 128, NH, NBAT);
        score_exp<<<gInp, 256, dynBytes>>>(pQ, pK, pEi, pSi);
        dim3 gPos(NS / 128, NH, 1);
        score_exp<<<gPos, 256, dynBytes>>>(pQp, pKp, pEp, pSp);
    }

    {
        dim3 g(NBAT, NS);
        blend_kernel<<<g, 256>>>(out_prob);
    }

    {
        dim3 g(NS / 64, NBAT, NH);
        pv_mma<<<g, 256>>>();
    }

    gemm_wo<<<dim3(4096 / 128, 768 / 128, 1), 256, gemmSmem>>>(out_attn);
}

// round 14
// speedup vs baseline: 2.1867x; 1.1378x over previous
#include <cuda_runtime.h>
#include <cuda_fp16.h>
#include <math.h>

#define NS   2048
#define NBAT 2
#define ND   768
#define NH   12
#define NDH  64
static const float SCORE_SCALE = 0.125f;   // 1/sqrt(64) * smoothing

// ---------------- scratch ----------------
__device__ __half g_W6[6][768 * 768];                      // [n][k] fp16: 5 perm'd proj weights + Wo^T
__device__ __half g_Ain[4096 * 768];                       // fp16 inp
__device__ __half g_Pin[2048 * 768];                       // fp16 pos_emb
__device__ __half g_Q [4096 * 768];
__device__ __half g_K [4096 * 768];
__device__ __half g_V [4096 * 768];
__device__ __half g_Qp[2048 * 768];
__device__ __half g_Kp[2048 * 768];
__device__ __half g_Einp[(size_t)2 * 12 * 2048 * 2048];    // exp(scores), fp16
__device__ __half g_Epos[(size_t)12 * 2048 * 2048];
__device__ float g_sumI[2 * 12 * 2048];                    // fp32 row sums
__device__ float g_sumP[12 * 2048];
__device__ __half g_AO[4096 * 768];                        // fp16 attn-out pre-Wo

// ---------------- helpers ----------------
__device__ __forceinline__ void mmah(float c[4], const unsigned a[4], const unsigned b[2]) {
    asm volatile(
        "mma.sync.aligned.m16n8k16.row.col.f32.f16.f16.f32 "
        "{%0,%1,%2,%3},{%4,%5,%6,%7},{%8,%9},{%0,%1,%2,%3};"
        : "+f"(c[0]), "+f"(c[1]), "+f"(c[2]), "+f"(c[3])
        : "r"(a[0]), "r"(a[1]), "r"(a[2]), "r"(a[3]), "r"(b[0]), "r"(b[1]));
}
__device__ __forceinline__ void ldsm4(unsigned r[4], unsigned addr) {
    asm volatile("ldmatrix.sync.aligned.m8n8.x4.shared.b16 {%0,%1,%2,%3}, [%4];"
        : "=r"(r[0]), "=r"(r[1]), "=r"(r[2]), "=r"(r[3]) : "r"(addr));
}
__device__ __forceinline__ void cpa16(unsigned s, const void* g) {
    asm volatile("cp.async.ca.shared.global [%0], [%1], 16;" :: "r"(s), "l"(g));
}
#define CPA_COMMIT asm volatile("cp.async.commit_group;")
#define CPA_WAIT0  asm volatile("cp.async.wait_group 0;")

// ---------------- float -> fp16 convert-copy ----------------
__global__ void conv_h(const float* __restrict__ src, __half* __restrict__ dst, int n4) {
    int i = blockIdx.x * 256 + threadIdx.x;
    if (i >= n4) return;
    float4 v = ((const float4*)src)[i];
    __half2 h0 = __floats2half2_rn(v.x, v.y);
    __half2 h1 = __floats2half2_rn(v.z, v.w);
    uint2 o = make_uint2(*(unsigned*)&h0, *(unsigned*)&h1);
    ((uint2*)dst)[i] = o;
}

// ---------------- weight prep: transpose (+ head permutation) to [n][k] fp16 ----------------
__global__ void prep_weights(const float* __restrict__ W0, const float* __restrict__ W1,
                             const float* __restrict__ W2, const float* __restrict__ W3,
                             const float* __restrict__ W4, const float* __restrict__ W5) {
    __shared__ __half ts[32][33];
    int w = blockIdx.z;
    const float* W = (w == 0) ? W0 : (w == 1) ? W1 : (w == 2) ? W2 : (w == 3) ? W3
                   : (w == 4) ? W4 : W5;
    int k0 = blockIdx.x * 32, j0 = blockIdx.y * 32;
    int tid = threadIdx.x;
    int r = tid >> 5, c = tid & 31;
#pragma unroll
    for (int l = 0; l < 4; l++) {
        int k = k0 + r + l * 8;
        ts[c][r + l * 8] = __float2half_rn(W[(size_t)k * 768 + j0 + c]);
    }
    __syncthreads();
#pragma unroll
    for (int l = 0; l < 4; l++) {
        int j = j0 + r + l * 8;
        int n = (w < 5) ? ((j % 12) * 64 + j / 12) : j;
        g_W6[w][(size_t)n * 768 + k0 + c] = ts[r + l * 8][c];
    }
}

// ---------------- fp16 MMA GEMM core, 128x128 CTA tile, cp.async + ldmatrix ----------------
// C[M,N] = A[M,K] @ B^T with A[M][K], Bt[N][K] fp16 row-major. N=K=768, BK=32.
template <bool HALF_OUT>
__device__ __forceinline__ void gemm_core(const __half* __restrict__ A,
                                          const __half* __restrict__ Bt,
                                          void* __restrict__ Cv, int M) {
    const int N = 768, K = 768;
    extern __shared__ __half smh[];
    __half* As = smh;                  // 2 x 128*40
    __half* Bs = smh + 2 * 128 * 40;   // 2 x 128*40
    int tid = threadIdx.x;
    int lane = tid & 31, wid = tid >> 5;
    int g = lane >> 2, t = lane & 3;
    int warpM = wid >> 2, warpN = wid & 3;        // 2 x 4 warps, 64x32 warp tiles
    int row0 = blockIdx.x * 128, col0 = blockIdx.y * 128;

    float c[4][4][4] = {};
    int lr = tid >> 2, lch = (tid & 3) * 8;

    unsigned sA = (unsigned)__cvta_generic_to_shared(As);
    unsigned sB = (unsigned)__cvta_generic_to_shared(Bs);
    const unsigned bufH = 128 * 40;               // halves per buffer

    // ldmatrix relative addresses (bytes within a buffer)
    int lane16 = lane & 15, laneHi = lane >> 4;
    unsigned aRel[4], bRel[2];
#pragma unroll
    for (int mi = 0; mi < 4; mi++)
        aRel[mi] = ((warpM * 64 + mi * 16 + lane16) * 40 + laneHi * 8) * 2;
#pragma unroll
    for (int pi = 0; pi < 2; pi++)
        bRel[pi] = ((warpN * 32 + pi * 16 + lane16) * 40 + laneHi * 8) * 2;

#pragma unroll
    for (int l = 0; l < 2; l++) {
        int r = lr + l * 64;
        cpa16(sA + (r * 40 + lch) * 2, A + (size_t)(row0 + r) * K + lch);
        cpa16(sB + (r * 40 + lch) * 2, Bt + (size_t)(col0 + r) * K + lch);
    }
    CPA_COMMIT;

    int buf = 0;
    for (int k0 = 0; k0 < K; k0 += 32, buf ^= 1) {
        CPA_WAIT0;
        __syncthreads();
        if (k0 + 32 < K) {
            unsigned o = (buf ^ 1) ? bufH * 2 : 0u;
#pragma unroll
            for (int l = 0; l < 2; l++) {
                int r = lr + l * 64;
                cpa16(sA + o + (r * 40 + lch) * 2, A + (size_t)(row0 + r) * K + k0 + 32 + lch);
                cpa16(sB + o + (r * 40 + lch) * 2, Bt + (size_t)(col0 + r) * K + k0 + 32 + lch);
            }
            CPA_COMMIT;
        }
        unsigned aBase = sA + (buf ? bufH * 2 : 0u);
        unsigned bBase = sB + (buf ? bufH * 2 : 0u);
#pragma unroll
        for (int kk = 0; kk < 2; kk++) {
            unsigned kbOff = kk * 32;   // 16 halves
            unsigned a[4][4], bfr[4][2];
#pragma unroll
            for (int mi = 0; mi < 4; mi++)
                ldsm4(a[mi], aBase + aRel[mi] + kbOff);
#pragma unroll
            for (int pi = 0; pi < 2; pi++) {
                unsigned r4[4];
                ldsm4(r4, bBase + bRel[pi] + kbOff);
                bfr[2 * pi][0] = r4[0]; bfr[2 * pi + 1][0] = r4[1];
                bfr[2 * pi][1] = r4[2]; bfr[2 * pi + 1][1] = r4[3];
            }
#pragma unroll
            for (int mi = 0; mi < 4; mi++)
#pragma unroll
                for (int ni = 0; ni < 4; ni++)
                    mmah(c[mi][ni], a[mi], bfr[ni]);
        }
        __syncthreads();
    }
#pragma unroll
    for (int mi = 0; mi < 4; mi++) {
#pragma unroll
        for (int ni = 0; ni < 4; ni++) {
            int row = row0 + warpM * 64 + mi * 16 + g;
            int col = col0 + warpN * 32 + ni * 8 + 2 * t;
            if (HALF_OUT) {
                __half* C = (__half*)Cv;
                *(__half2*)(C + (size_t)row * N + col) = __floats2half2_rn(c[mi][ni][0], c[mi][ni][1]);
                *(__half2*)(C + (size_t)(row + 8) * N + col) = __floats2half2_rn(c[mi][ni][2], c[mi][ni][3]);
            } else {
                float* C = (float*)Cv;
                *(float2*)(C + (size_t)row * N + col) = make_float2(c[mi][ni][0], c[mi][ni][1]);
                *(float2*)(C + (size_t)(row + 8) * N + col) = make_float2(c[mi][ni][2], c[mi][ni][3]);
            }
        }
    }
}

// all 5 projections in one launch; pos streams (z>=3) use M=2048 (early-exit x>=16)
__global__ void __launch_bounds__(256, 2) gemm_proj() {
    int z = blockIdx.z;
    if (z < 3) {
        const __half* Bt = g_W6[(z == 2) ? 4 : z];
        __half* C = (z == 0) ? g_Q : (z == 1) ? g_K : g_V;
        gemm_core<true>(g_Ain, Bt, C, 4096);
    } else {
        if (blockIdx.x >= 16) return;
        gemm_core<true>(g_Pin, g_W6[2 + (z - 3)], (z == 3) ? g_Qp : g_Kp, 2048);
    }
}
// Wo GEMM (fp32 out, writes out_attn)
__global__ void __launch_bounds__(256, 2) gemm_wo(float* __restrict__ C) {
    gemm_core<false>(g_AO, g_W6[5], C, 4096);
}

// ---------------- scores: E(fp16) = exp(scale * Q K^T) + fp32 row sums ----------------
// blockIdx.z: 0,1 = inp batch; 2 = pos stream. ldmatrix fragment loads.
__global__ void __launch_bounds__(256) score_exp() {
    extern __shared__ __half smh[];
    __half* Qs = smh;                      // 128*72
    __half* Ks = smh + 128 * 72;           // 2 x 64*72
    float* rbuf = (float*)(Ks + 2 * 64 * 72);   // 256 floats
    int tid = threadIdx.x;
    int lane = tid & 31, wid = tid >> 5;
    int g = lane >> 2, t = lane & 3;
    int warpM = wid >> 1, warpN = wid & 1;      // 4 x 2, warp tile 32x32
    int i0 = blockIdx.x * 128;
    int h = blockIdx.y;
    int z = blockIdx.z;

    const __half *Qg, *Kg;
    __half* E;
    float* sums;
    int plane;
    if (z < 2) {
        Qg = g_Q + (size_t)z * NS * ND;  Kg = g_K + (size_t)z * NS * ND;
        E = g_Einp; sums = g_sumI; plane = z * NH + h;
    } else {
        Qg = g_Qp; Kg = g_Kp;
        E = g_Epos; sums = g_sumP; plane = h;
    }
    const __half* qb = Qg + (size_t)i0 * ND + h * NDH;
    const __half* kb = Kg + h * NDH;
    __half* Ep = E + (size_t)plane * NS * NS;

#pragma unroll
    for (int l = 0; l < 4; l++) {
        int f = tid + l * 256;
        int r = f >> 3, ch = (f & 7) * 8;
        *(uint4*)(Qs + r * 72 + ch) = *(const uint4*)(qb + (size_t)r * ND + ch);
    }

    unsigned sQ = (unsigned)__cvta_generic_to_shared(Qs);
    unsigned sK = (unsigned)__cvta_generic_to_shared(Ks);
    int lane16 = lane & 15, laneHi = lane >> 4;
    unsigned aRel[2], bRel[2];
#pragma unroll
    for (int mi = 0; mi < 2; mi++)
        aRel[mi] = ((warpM * 32 + mi * 16 + lane16) * 72 + laneHi * 8) * 2;
#pragma unroll
    for (int pi = 0; pi < 2; pi++)
        bRel[pi] = ((warpN * 32 + pi * 16 + lane16) * 72 + laneHi * 8) * 2;

#pragma unroll
    for (int l = 0; l < 2; l++) {
        int f = tid + l * 256;
        int r = f >> 3, ch = (f & 7) * 8;
        cpa16(sK + (r * 72 + ch) * 2, kb + (size_t)r * ND + ch);
    }
    CPA_COMMIT;

    float rs[2][2] = {};
    int buf = 0;
    for (int jt = 0; jt < NS; jt += 64, buf ^= 1) {
        CPA_WAIT0;
        __syncthreads();
        if (jt + 64 < NS) {
            unsigned o = (buf ^ 1) ? (unsigned)(64 * 72 * 2) : 0u;
#pragma unroll
            for (int l = 0; l < 2; l++) {
                int f = tid + l * 256;
                int r = f >> 3, ch = (f & 7) * 8;
                cpa16(sK + o + (r * 72 + ch) * 2, kb + (size_t)(jt + 64 + r) * ND + ch);
            }
            CPA_COMMIT;
        }

        float c4[2][4][4] = {};
        unsigned kBase = sK + (buf ? (unsigned)(64 * 72 * 2) : 0u);
#pragma unroll
        for (int kk = 0; kk < 4; kk++) {
            unsigned kbOff = kk * 32;
            unsigned a[2][4], bfr[4][2];
#pragma unroll
            for (int mi = 0; mi < 2; mi++)
                ldsm4(a[mi], sQ + aRel[mi] + kbOff);
#pragma unroll
            for (int pi = 0; pi < 2; pi++) {
                unsigned r4[4];
                ldsm4(r4, kBase + bRel[pi] + kbOff);
                bfr[2 * pi][0] = r4[0]; bfr[2 * pi + 1][0] = r4[1];
                bfr[2 * pi][1] = r4[2]; bfr[2 * pi + 1][1] = r4[3];
            }
#pragma unroll
            for (int mi = 0; mi < 2; mi++)
#pragma unroll
                for (int ni = 0; ni < 4; ni++)
                    mmah(c4[mi][ni], a[mi], bfr[ni]);
        }
#pragma unroll
        for (int mi = 0; mi < 2; mi++) {
#pragma unroll
            for (int ni = 0; ni < 4; ni++) {
                float e0 = __expf(c4[mi][ni][0] * SCORE_SCALE);
                float e1 = __expf(c4[mi][ni][1] * SCORE_SCALE);
                float e2 = __expf(c4[mi][ni][2] * SCORE_SCALE);
                float e3 = __expf(c4[mi][ni][3] * SCORE_SCALE);
                rs[mi][0] += e0 + e1;
                rs[mi][1] += e2 + e3;
                int row = i0 + warpM * 32 + mi * 16 + g;
                int col = jt + warpN * 32 + ni * 8 + 2 * t;
                *(__half2*)(Ep + (size_t)row * NS + col) = __floats2half2_rn(e0, e1);
                *(__half2*)(Ep + (size_t)(row + 8) * NS + col) = __floats2half2_rn(e2, e3);
            }
        }
        __syncthreads();
    }

#pragma unroll
    for (int mi = 0; mi < 2; mi++)
#pragma unroll
        for (int hf = 0; hf < 2; hf++) {
            float v = rs[mi][hf];
            v += __shfl_xor_sync(0xffffffffu, v, 1);
            v += __shfl_xor_sync(0xffffffffu, v, 2);
            rs[mi][hf] = v;
        }
    if (t == 0) {
#pragma unroll
        for (int mi = 0; mi < 2; mi++)
#pragma unroll
            for (int hf = 0; hf < 2; hf++) {
                int r = warpM * 32 + mi * 16 + hf * 8 + g;
                rbuf[r * 2 + warpN] = rs[mi][hf];
            }
    }
    __syncthreads();
    if (tid < 128)
        sums[(size_t)plane * NS + i0 + tid] = rbuf[tid * 2] + rbuf[tid * 2 + 1];
}

// ---------------- blend + interleave into [b][i][j][h] (fp16 E reads) ----------------
__global__ void __launch_bounds__(256) blend_kernel(float* __restrict__ outP) {
    __shared__ float sb[12 * 515];
    __shared__ float sIs[12], sPs[12];
    int b = blockIdx.x, i = blockIdx.y;
    int tid = threadIdx.x;
    if (tid < 12) sIs[tid] = 0.5f / g_sumI[(b * 12 + tid) * NS + i];
    else if (tid < 24) sPs[tid - 12] = 0.5f / g_sumP[(tid - 12) * NS + i];
    __syncthreads();
    size_t outBase = ((size_t)(b * NS + i)) * ((size_t)NS * NH);
    for (int jt = 0; jt < NS; jt += 512) {
#pragma unroll
        for (int l = 0; l < 12; l++) {
            int e = tid + l * 256;
            int h = e >> 8, j2 = e & 255;
            size_t idxI = ((size_t)(b * NH + h) * NS + i) * NS + jt + 2 * j2;
            size_t idxP = ((size_t)h * NS + i) * NS + jt + 2 * j2;
            float2 f1 = __half22float2(*(const __half2*)(g_Einp + idxI));
            float2 f2 = __half22float2(*(const __half2*)(g_Epos + idxP));
            float si = sIs[h], sp = sPs[h];
            sb[h * 515 + 2 * j2]     = f1.x * si + f2.x * sp;
            sb[h * 515 + 2 * j2 + 1] = f1.y * si + f2.y * sp;
        }
        __syncthreads();
#pragma unroll
        for (int l = 0; l < 24; l++) {
            int e = tid + l * 256;
            int j = e / 12, h = e - j * 12;
            outP[outBase + (size_t)jt * NH + e] = sb[h * 515 + j];
        }
        __syncthreads();
    }
}

// ---------------- PV (fp16 MMA): AO(fp16) = blend(P) @ V ----------------
__global__ void __launch_bounds__(256) pv_mma() {
    __shared__ __half As[64 * 40];    // blended P, [i][j]
    __shared__ __half Vt[64 * 34];    // V^T tile, [d][j], stride 34
    __shared__ float invI[64], invP[64];
    int tid = threadIdx.x;
    int lane = tid & 31, wid = tid >> 5;
    int g = lane >> 2, t = lane & 3;
    int warpM = wid >> 1, warpN = wid & 1;       // 4 x 2, warp tile 16(m)x32(n)
    int i0 = blockIdx.x * 64;
    int b = blockIdx.y, h = blockIdx.z;
    int plane = b * NH + h;

    const __half* Ei = g_Einp + (size_t)plane * NS * NS;
    const __half* Epp = g_Epos + (size_t)h * NS * NS;
    const __half* Vb = g_V + (size_t)b * NS * ND + h * NDH;

    if (tid < 64) invI[tid] = 0.5f / g_sumI[(size_t)plane * NS + i0 + tid];
    else if (tid < 128) invP[tid - 64] = 0.5f / g_sumP[(size_t)h * NS + i0 + tid - 64];
    __syncthreads();

    float c4[4][4] = {};
    int ar = tid >> 3, ac = (tid & 7) * 4;
    int vr = tid >> 3, vch = (tid & 7) * 8;

    uint2 pe1[2], pe2[2];
    uint4 pvv;
#pragma unroll
    for (int rr = 0; rr < 2; rr++) {
        size_t off = (size_t)(i0 + ar + rr * 32) * NS + ac;
        pe1[rr] = *(const uint2*)(Ei + off);
        pe2[rr] = *(const uint2*)(Epp + off);
    }
    pvv = *(const uint4*)(Vb + (size_t)vr * ND + vch);

    for (int k0 = 0; k0 < NS; k0 += 32) {
#pragma unroll
        for (int rr = 0; rr < 2; rr++) {
            int r = ar + rr * 32;
            float si = invI[r], sp = invP[r];
            float2 a0 = __half22float2(*(__half2*)&pe1[rr].x);
            float2 a1 = __half22float2(*(__half2*)&pe1[rr].y);
            float2 b0 = __half22float2(*(__half2*)&pe2[rr].x);
            float2 b1 = __half22float2(*(__half2*)&pe2[rr].y);
            __half2 h0 = __floats2half2_rn(a0.x * si + b0.x * sp, a0.y * si + b0.y * sp);
            __half2 h1 = __floats2half2_rn(a1.x * si + b1.x * sp, a1.y * si + b1.y * sp);
            *(uint2*)(As + r * 40 + ac) = make_uint2(*(unsigned*)&h0, *(unsigned*)&h1);
        }
        {
            const __half* hp = (const __half*)&pvv;
#pragma unroll
            for (int i = 0; i < 8; i++)
                Vt[(vch + i) * 34 + vr] = hp[i];
        }
        __syncthreads();

        if (k0 + 32 < NS) {
#pragma unroll
            for (int rr = 0; rr < 2; rr++) {
                size_t off = (size_t)(i0 + ar + rr * 32) * NS + k0 + 32 + ac;
                pe1[rr] = *(const uint2*)(Ei + off);
                pe2[rr] = *(const uint2*)(Epp + off);
            }
            pvv = *(const uint4*)(Vb + (size_t)(k0 + 32 + vr) * ND + vch);
        }

        const unsigned* Au = (const unsigned*)As;
        const unsigned* Vu = (const unsigned*)Vt;
#pragma unroll
        for (int kk = 0; kk < 2; kk++) {
            int kb = kk * 16;
            unsigned a[4], bfr[4][2];
            int m = warpM * 16;
            a[0] = Au[((m + g) * 40 + kb + 2 * t) >> 1];
            a[1] = Au[((m + g + 8) * 40 + kb + 2 * t) >> 1];
            a[2] = Au[((m + g) * 40 + kb + 2 * t + 8) >> 1];
            a[3] = Au[((m + g + 8) * 40 + kb + 2 * t + 8) >> 1];
#pragma unroll
            for (int ni = 0; ni < 4; ni++) {
                int n = warpN * 32 + ni * 8;
                bfr[ni][0] = Vu[((n + g) * 34 + kb + 2 * t) >> 1];
                bfr[ni][1] = Vu[((n + g) * 34 + kb + 2 * t + 8) >> 1];
            }
#pragma unroll
            for (int ni = 0; ni < 4; ni++)
                mmah(c4[ni], a, bfr[ni]);
        }
        __syncthreads();
    }
#pragma unroll
    for (int ni = 0; ni < 4; ni++) {
        int row = i0 + warpM * 16 + g;
        int col = warpN * 32 + ni * 8 + 2 * t;
        __half* dst = g_AO + (size_t)(b * NS + row) * ND + h * NDH + col;
        *(__half2*)dst = __floats2half2_rn(c4[ni][0], c4[ni][1]);
        *(__half2*)(dst + (size_t)8 * ND) = __floats2half2_rn(c4[ni][2], c4[ni][3]);
    }
}

// ---------------- launch ----------------
extern "C" void kernel_launch(void* const* d_in, const int* in_sizes, int n_in,
                              void* d_out, int out_size) {
    (void)in_sizes; (void)n_in; (void)out_size;
    const float* inp    = (const float*)d_in[0];
    const float* pos    = (const float*)d_in[1];
    const float* Wq_inp = (const float*)d_in[2];
    const float* Wk_inp = (const float*)d_in[3];
    const float* Wq_pos = (const float*)d_in[4];
    const float* Wk_pos = (const float*)d_in[5];
    const float* Wv     = (const float*)d_in[6];
    const float* Wo     = (const float*)d_in[7];

    float* out      = (float*)d_out;
    float* out_attn = out;
    float* out_prob = out + (size_t)NBAT * NS * ND;

    __half *pAin, *pPin;
    cudaGetSymbolAddress((void**)&pAin, g_Ain);
    cudaGetSymbolAddress((void**)&pPin, g_Pin);

    conv_h<<<(4096 * 768 / 4 + 255) / 256, 256>>>(inp, pAin, 4096 * 768 / 4);
    conv_h<<<(2048 * 768 / 4 + 255) / 256, 256>>>(pos, pPin, 2048 * 768 / 4);
    {
        dim3 g(24, 24, 6);
        prep_weights<<<g, 256>>>(Wq_inp, Wk_inp, Wq_pos, Wk_pos, Wv, Wo);
    }

    int gemmSmem = 2 * 2 * 128 * 40 * (int)sizeof(__half);   // 40960
    cudaFuncSetAttribute(gemm_proj, cudaFuncAttributeMaxDynamicSharedMemorySize, gemmSmem);
    cudaFuncSetAttribute(gemm_wo,   cudaFuncAttributeMaxDynamicSharedMemorySize, gemmSmem);

    gemm_proj<<<dim3(32, 6, 5), 256, gemmSmem>>>();

    {
        int dynBytes = (128 * 72 + 2 * 64 * 72) * (int)sizeof(__half) + 256 * (int)sizeof(float);
        cudaFuncSetAttribute(score_exp, cudaFuncAttributeMaxDynamicSharedMemorySize, dynBytes);
        score_exp<<<dim3(NS / 128, NH, 3), 256, dynBytes>>>();
    }

    {
        dim3 g(NBAT, NS);
        blend_kernel<<<g, 256>>>(out_prob);
    }

    {
        dim3 g(NS / 64, NBAT, NH);
        pv_mma<<<g, 256>>>();
    }

    gemm_wo<<<dim3(4096 / 128, 768 / 128, 1), 256, gemmSmem>>>(out_attn);
}

// round 15
// speedup vs baseline: 2.2709x; 1.0385x over previous
#include <cuda_runtime.h>
#include <cuda_fp16.h>
#include <math.h>

#define NS   2048
#define NBAT 2
#define ND   768
#define NH   12
#define NDH  64
static const float SCORE_SCALE = 0.125f;   // 1/sqrt(64) * smoothing

// ---------------- scratch ----------------
__device__ __half g_W6[6][768 * 768];                      // [n][k] fp16: 5 perm'd proj weights + Wo^T
__device__ __half g_Ain[4096 * 768];                       // fp16 inp
__device__ __half g_Pin[2048 * 768];                       // fp16 pos_emb
__device__ __half g_Q [4096 * 768];
__device__ __half g_K [4096 * 768];
__device__ __half g_V [4096 * 768];
__device__ __half g_Qp[2048 * 768];
__device__ __half g_Kp[2048 * 768];
__device__ __half g_Einp[(size_t)2 * 12 * 2048 * 2048];    // exp(scores), fp16
__device__ __half g_Epos[(size_t)12 * 2048 * 2048];
__device__ float g_sumI[2 * 12 * 2048];                    // fp32 row sums
__device__ float g_sumP[12 * 2048];
__device__ __half g_AO[4096 * 768];                        // fp16 attn-out pre-Wo

// ---------------- helpers ----------------
__device__ __forceinline__ void mmah(float c[4], const unsigned a[4], const unsigned b[2]) {
    asm volatile(
        "mma.sync.aligned.m16n8k16.row.col.f32.f16.f16.f32 "
        "{%0,%1,%2,%3},{%4,%5,%6,%7},{%8,%9},{%0,%1,%2,%3};"
        : "+f"(c[0]), "+f"(c[1]), "+f"(c[2]), "+f"(c[3])
        : "r"(a[0]), "r"(a[1]), "r"(a[2]), "r"(a[3]), "r"(b[0]), "r"(b[1]));
}
__device__ __forceinline__ void ldsm4(unsigned r[4], unsigned addr) {
    asm volatile("ldmatrix.sync.aligned.m8n8.x4.shared.b16 {%0,%1,%2,%3}, [%4];"
        : "=r"(r[0]), "=r"(r[1]), "=r"(r[2]), "=r"(r[3]) : "r"(addr));
}
__device__ __forceinline__ void cpa16(unsigned s, const void* g) {
    asm volatile("cp.async.ca.shared.global [%0], [%1], 16;" :: "r"(s), "l"(g));
}
#define CPA_COMMIT asm volatile("cp.async.commit_group;")
#define CPA_WAIT0  asm volatile("cp.async.wait_group 0;")

// ---------------- float -> fp16 convert-copy ----------------
__global__ void conv_h(const float* __restrict__ src, __half* __restrict__ dst, int n4) {
    int i = blockIdx.x * 256 + threadIdx.x;
    if (i >= n4) return;
    float4 v = ((const float4*)src)[i];
    __half2 h0 = __floats2half2_rn(v.x, v.y);
    __half2 h1 = __floats2half2_rn(v.z, v.w);
    uint2 o = make_uint2(*(unsigned*)&h0, *(unsigned*)&h1);
    ((uint2*)dst)[i] = o;
}

// ---------------- weight prep: transpose (+ head permutation) to [n][k] fp16 ----------------
__global__ void prep_weights(const float* __restrict__ W0, const float* __restrict__ W1,
                             const float* __restrict__ W2, const float* __restrict__ W3,
                             const float* __restrict__ W4, const float* __restrict__ W5) {
    __shared__ __half ts[32][33];
    int w = blockIdx.z;
    const float* W = (w == 0) ? W0 : (w == 1) ? W1 : (w == 2) ? W2 : (w == 3) ? W3
                   : (w == 4) ? W4 : W5;
    int k0 = blockIdx.x * 32, j0 = blockIdx.y * 32;
    int tid = threadIdx.x;
    int r = tid >> 5, c = tid & 31;
#pragma unroll
    for (int l = 0; l < 4; l++) {
        int k = k0 + r + l * 8;
        ts[c][r + l * 8] = __float2half_rn(W[(size_t)k * 768 + j0 + c]);
    }
    __syncthreads();
#pragma unroll
    for (int l = 0; l < 4; l++) {
        int j = j0 + r + l * 8;
        int n = (w < 5) ? ((j % 12) * 64 + j / 12) : j;
        g_W6[w][(size_t)n * 768 + k0 + c] = ts[r + l * 8][c];
    }
}

// ---------------- fp16 MMA GEMM core, 128x128 CTA tile, cp.async + ldmatrix ----------------
template <bool HALF_OUT>
__device__ __forceinline__ void gemm_core(const __half* __restrict__ A,
                                          const __half* __restrict__ Bt,
                                          void* __restrict__ Cv, int M) {
    const int N = 768, K = 768;
    extern __shared__ __half smh[];
    __half* As = smh;                  // 2 x 128*40
    __half* Bs = smh + 2 * 128 * 40;   // 2 x 128*40
    int tid = threadIdx.x;
    int lane = tid & 31, wid = tid >> 5;
    int g = lane >> 2, t = lane & 3;
    int warpM = wid >> 2, warpN = wid & 3;        // 2 x 4 warps, 64x32 warp tiles
    int row0 = blockIdx.x * 128, col0 = blockIdx.y * 128;

    float c[4][4][4] = {};
    int lr = tid >> 2, lch = (tid & 3) * 8;

    unsigned sA = (unsigned)__cvta_generic_to_shared(As);
    unsigned sB = (unsigned)__cvta_generic_to_shared(Bs);
    const unsigned bufH = 128 * 40;

    int lane16 = lane & 15, laneHi = lane >> 4;
    unsigned aRel[4], bRel[2];
#pragma unroll
    for (int mi = 0; mi < 4; mi++)
        aRel[mi] = ((warpM * 64 + mi * 16 + lane16) * 40 + laneHi * 8) * 2;
#pragma unroll
    for (int pi = 0; pi < 2; pi++)
        bRel[pi] = ((warpN * 32 + pi * 16 + lane16) * 40 + laneHi * 8) * 2;

#pragma unroll
    for (int l = 0; l < 2; l++) {
        int r = lr + l * 64;
        cpa16(sA + (r * 40 + lch) * 2, A + (size_t)(row0 + r) * K + lch);
        cpa16(sB + (r * 40 + lch) * 2, Bt + (size_t)(col0 + r) * K + lch);
    }
    CPA_COMMIT;

    int buf = 0;
    for (int k0 = 0; k0 < K; k0 += 32, buf ^= 1) {
        CPA_WAIT0;
        __syncthreads();
        if (k0 + 32 < K) {
            unsigned o = (buf ^ 1) ? bufH * 2 : 0u;
#pragma unroll
            for (int l = 0; l < 2; l++) {
                int r = lr + l * 64;
                cpa16(sA + o + (r * 40 + lch) * 2, A + (size_t)(row0 + r) * K + k0 + 32 + lch);
                cpa16(sB + o + (r * 40 + lch) * 2, Bt + (size_t)(col0 + r) * K + k0 + 32 + lch);
            }
            CPA_COMMIT;
        }
        unsigned aBase = sA + (buf ? bufH * 2 : 0u);
        unsigned bBase = sB + (buf ? bufH * 2 : 0u);
#pragma unroll
        for (int kk = 0; kk < 2; kk++) {
            unsigned kbOff = kk * 32;
            unsigned a[4][4], bfr[4][2];
#pragma unroll
            for (int mi = 0; mi < 4; mi++)
                ldsm4(a[mi], aBase + aRel[mi] + kbOff);
#pragma unroll
            for (int pi = 0; pi < 2; pi++) {
                unsigned r4[4];
                ldsm4(r4, bBase + bRel[pi] + kbOff);
                bfr[2 * pi][0] = r4[0]; bfr[2 * pi + 1][0] = r4[1];
                bfr[2 * pi][1] = r4[2]; bfr[2 * pi + 1][1] = r4[3];
            }
#pragma unroll
            for (int mi = 0; mi < 4; mi++)
#pragma unroll
                for (int ni = 0; ni < 4; ni++)
                    mmah(c[mi][ni], a[mi], bfr[ni]);
        }
        __syncthreads();
    }
#pragma unroll
    for (int mi = 0; mi < 4; mi++) {
#pragma unroll
        for (int ni = 0; ni < 4; ni++) {
            int row = row0 + warpM * 64 + mi * 16 + g;
            int col = col0 + warpN * 32 + ni * 8 + 2 * t;
            if (HALF_OUT) {
                __half* C = (__half*)Cv;
                *(__half2*)(C + (size_t)row * N + col) = __floats2half2_rn(c[mi][ni][0], c[mi][ni][1]);
                *(__half2*)(C + (size_t)(row + 8) * N + col) = __floats2half2_rn(c[mi][ni][2], c[mi][ni][3]);
            } else {
                float* C = (float*)Cv;
                *(float2*)(C + (size_t)row * N + col) = make_float2(c[mi][ni][0], c[mi][ni][1]);
                *(float2*)(C + (size_t)(row + 8) * N + col) = make_float2(c[mi][ni][2], c[mi][ni][3]);
            }
        }
    }
}

__global__ void __launch_bounds__(256, 2) gemm_proj() {
    int z = blockIdx.z;
    if (z < 3) {
        const __half* Bt = g_W6[(z == 2) ? 4 : z];
        __half* C = (z == 0) ? g_Q : (z == 1) ? g_K : g_V;
        gemm_core<true>(g_Ain, Bt, C, 4096);
    } else {
        if (blockIdx.x >= 16) return;
        gemm_core<true>(g_Pin, g_W6[2 + (z - 3)], (z == 3) ? g_Qp : g_Kp, 2048);
    }
}
__global__ void __launch_bounds__(256, 2) gemm_wo(float* __restrict__ C) {
    gemm_core<false>(g_AO, g_W6[5], C, 4096);
}

// ---------------- scores: E(fp16) = exp(scale * Q K^T) + fp32 row sums ----------------
__global__ void __launch_bounds__(256) score_exp() {
    extern __shared__ __half smh[];
    __half* Qs = smh;                      // 128*72
    __half* Ks = smh + 128 * 72;           // 2 x 64*72
    float* rbuf = (float*)(Ks + 2 * 64 * 72);
    int tid = threadIdx.x;
    int lane = tid & 31, wid = tid >> 5;
    int g = lane >> 2, t = lane & 3;
    int warpM = wid >> 1, warpN = wid & 1;
    int i0 = blockIdx.x * 128;
    int h = blockIdx.y;
    int z = blockIdx.z;

    const __half *Qg, *Kg;
    __half* E;
    float* sums;
    int plane;
    if (z < 2) {
        Qg = g_Q + (size_t)z * NS * ND;  Kg = g_K + (size_t)z * NS * ND;
        E = g_Einp; sums = g_sumI; plane = z * NH + h;
    } else {
        Qg = g_Qp; Kg = g_Kp;
        E = g_Epos; sums = g_sumP; plane = h;
    }
    const __half* qb = Qg + (size_t)i0 * ND + h * NDH;
    const __half* kb = Kg + h * NDH;
    __half* Ep = E + (size_t)plane * NS * NS;

#pragma unroll
    for (int l = 0; l < 4; l++) {
        int f = tid + l * 256;
        int r = f >> 3, ch = (f & 7) * 8;
        *(uint4*)(Qs + r * 72 + ch) = *(const uint4*)(qb + (size_t)r * ND + ch);
    }

    unsigned sQ = (unsigned)__cvta_generic_to_shared(Qs);
    unsigned sK = (unsigned)__cvta_generic_to_shared(Ks);
    int lane16 = lane & 15, laneHi = lane >> 4;
    unsigned aRel[2], bRel[2];
#pragma unroll
    for (int mi = 0; mi < 2; mi++)
        aRel[mi] = ((warpM * 32 + mi * 16 + lane16) * 72 + laneHi * 8) * 2;
#pragma unroll
    for (int pi = 0; pi < 2; pi++)
        bRel[pi] = ((warpN * 32 + pi * 16 + lane16) * 72 + laneHi * 8) * 2;

#pragma unroll
    for (int l = 0; l < 2; l++) {
        int f = tid + l * 256;
        int r = f >> 3, ch = (f & 7) * 8;
        cpa16(sK + (r * 72 + ch) * 2, kb + (size_t)r * ND + ch);
    }
    CPA_COMMIT;

    float rs[2][2] = {};
    int buf = 0;
    for (int jt = 0; jt < NS; jt += 64, buf ^= 1) {
        CPA_WAIT0;
        __syncthreads();
        if (jt + 64 < NS) {
            unsigned o = (buf ^ 1) ? (unsigned)(64 * 72 * 2) : 0u;
#pragma unroll
            for (int l = 0; l < 2; l++) {
                int f = tid + l * 256;
                int r = f >> 3, ch = (f & 7) * 8;
                cpa16(sK + o + (r * 72 + ch) * 2, kb + (size_t)(jt + 64 + r) * ND + ch);
            }
            CPA_COMMIT;
        }

        float c4[2][4][4] = {};
        unsigned kBase = sK + (buf ? (unsigned)(64 * 72 * 2) : 0u);
#pragma unroll
        for (int kk = 0; kk < 4; kk++) {
            unsigned kbOff = kk * 32;
            unsigned a[2][4], bfr[4][2];
#pragma unroll
            for (int mi = 0; mi < 2; mi++)
                ldsm4(a[mi], sQ + aRel[mi] + kbOff);
#pragma unroll
            for (int pi = 0; pi < 2; pi++) {
                unsigned r4[4];
                ldsm4(r4, kBase + bRel[pi] + kbOff);
                bfr[2 * pi][0] = r4[0]; bfr[2 * pi + 1][0] = r4[1];
                bfr[2 * pi][1] = r4[2]; bfr[2 * pi + 1][1] = r4[3];
            }
#pragma unroll
            for (int mi = 0; mi < 2; mi++)
#pragma unroll
                for (int ni = 0; ni < 4; ni++)
                    mmah(c4[mi][ni], a[mi], bfr[ni]);
        }
#pragma unroll
        for (int mi = 0; mi < 2; mi++) {
#pragma unroll
            for (int ni = 0; ni < 4; ni++) {
                float e0 = __expf(c4[mi][ni][0] * SCORE_SCALE);
                float e1 = __expf(c4[mi][ni][1] * SCORE_SCALE);
                float e2 = __expf(c4[mi][ni][2] * SCORE_SCALE);
                float e3 = __expf(c4[mi][ni][3] * SCORE_SCALE);
                rs[mi][0] += e0 + e1;
                rs[mi][1] += e2 + e3;
                int row = i0 + warpM * 32 + mi * 16 + g;
                int col = jt + warpN * 32 + ni * 8 + 2 * t;
                *(__half2*)(Ep + (size_t)row * NS + col) = __floats2half2_rn(e0, e1);
                *(__half2*)(Ep + (size_t)(row + 8) * NS + col) = __floats2half2_rn(e2, e3);
            }
        }
        __syncthreads();
    }

#pragma unroll
    for (int mi = 0; mi < 2; mi++)
#pragma unroll
        for (int hf = 0; hf < 2; hf++) {
            float v = rs[mi][hf];
            v += __shfl_xor_sync(0xffffffffu, v, 1);
            v += __shfl_xor_sync(0xffffffffu, v, 2);
            rs[mi][hf] = v;
        }
    if (t == 0) {
#pragma unroll
        for (int mi = 0; mi < 2; mi++)
#pragma unroll
            for (int hf = 0; hf < 2; hf++) {
                int r = warpM * 32 + mi * 16 + hf * 8 + g;
                rbuf[r * 2 + warpN] = rs[mi][hf];
            }
    }
    __syncthreads();
    if (tid < 128)
        sums[(size_t)plane * NS + i0 + tid] = rbuf[tid * 2] + rbuf[tid * 2 + 1];
}

// ---------------- blend + interleave into [b][i][j][h] (fp16 E reads) ----------------
__global__ void __launch_bounds__(256) blend_kernel(float* __restrict__ outP) {
    __shared__ float sb[12 * 515];
    __shared__ float sIs[12], sPs[12];
    int b = blockIdx.x, i = blockIdx.y;
    int tid = threadIdx.x;
    if (tid < 12) sIs[tid] = 0.5f / g_sumI[(b * 12 + tid) * NS + i];
    else if (tid < 24) sPs[tid - 12] = 0.5f / g_sumP[(tid - 12) * NS + i];
    __syncthreads();
    size_t outBase = ((size_t)(b * NS + i)) * ((size_t)NS * NH);
    for (int jt = 0; jt < NS; jt += 512) {
#pragma unroll
        for (int l = 0; l < 12; l++) {
            int e = tid + l * 256;
            int h = e >> 8, j2 = e & 255;
            size_t idxI = ((size_t)(b * NH + h) * NS + i) * NS + jt + 2 * j2;
            size_t idxP = ((size_t)h * NS + i) * NS + jt + 2 * j2;
            float2 f1 = __half22float2(*(const __half2*)(g_Einp + idxI));
            float2 f2 = __half22float2(*(const __half2*)(g_Epos + idxP));
            float si = sIs[h], sp = sPs[h];
            sb[h * 515 + 2 * j2]     = f1.x * si + f2.x * sp;
            sb[h * 515 + 2 * j2 + 1] = f1.y * si + f2.y * sp;
        }
        __syncthreads();
#pragma unroll
        for (int l = 0; l < 24; l++) {
            int e = tid + l * 256;
            int j = e / 12, h = e - j * 12;
            outP[outBase + (size_t)jt * NH + e] = sb[h * 515 + j];
        }
        __syncthreads();
    }
}

// ---------------- PV (fp16 MMA): AO(fp16) = blend(P) @ V ----------------
__global__ void __launch_bounds__(256) pv_mma() {
    __shared__ __half As[64 * 40];
    __shared__ __half Vt[64 * 34];
    __shared__ float invI[64], invP[64];
    int tid = threadIdx.x;
    int lane = tid & 31, wid = tid >> 5;
    int g = lane >> 2, t = lane & 3;
    int warpM = wid >> 1, warpN = wid & 1;
    int i0 = blockIdx.x * 64;
    int b = blockIdx.y, h = blockIdx.z;
    int plane = b * NH + h;

    const __half* Ei = g_Einp + (size_t)plane * NS * NS;
    const __half* Epp = g_Epos + (size_t)h * NS * NS;
    const __half* Vb = g_V + (size_t)b * NS * ND + h * NDH;

    if (tid < 64) invI[tid] = 0.5f / g_sumI[(size_t)plane * NS + i0 + tid];
    else if (tid < 128) invP[tid - 64] = 0.5f / g_sumP[(size_t)h * NS + i0 + tid - 64];
    __syncthreads();

    float c4[4][4] = {};
    int ar = tid >> 3, ac = (tid & 7) * 4;
    int vr = tid >> 3, vch = (tid & 7) * 8;

    uint2 pe1[2], pe2[2];
    uint4 pvv;
#pragma unroll
    for (int rr = 0; rr < 2; rr++) {
        size_t off = (size_t)(i0 + ar + rr * 32) * NS + ac;
        pe1[rr] = *(const uint2*)(Ei + off);
        pe2[rr] = *(const uint2*)(Epp + off);
    }
    pvv = *(const uint4*)(Vb + (size_t)vr * ND + vch);

    for (int k0 = 0; k0 < NS; k0 += 32) {
#pragma unroll
        for (int rr = 0; rr < 2; rr++) {
            int r = ar + rr * 32;
            float si = invI[r], sp = invP[r];
            float2 a0 = __half22float2(*(__half2*)&pe1[rr].x);
            float2 a1 = __half22float2(*(__half2*)&pe1[rr].y);
            float2 b0 = __half22float2(*(__half2*)&pe2[rr].x);
            float2 b1 = __half22float2(*(__half2*)&pe2[rr].y);
            __half2 h0 = __floats2half2_rn(a0.x * si + b0.x * sp, a0.y * si + b0.y * sp);
            __half2 h1 = __floats2half2_rn(a1.x * si + b1.x * sp, a1.y * si + b1.y * sp);
            *(uint2*)(As + r * 40 + ac) = make_uint2(*(unsigned*)&h0, *(unsigned*)&h1);
        }
        {
            const __half* hp = (const __half*)&pvv;
#pragma unroll
            for (int i = 0; i < 8; i++)
                Vt[(vch + i) * 34 + vr] = hp[i];
        }
        __syncthreads();

        if (k0 + 32 < NS) {
#pragma unroll
            for (int rr = 0; rr < 2; rr++) {
                size_t off = (size_t)(i0 + ar + rr * 32) * NS + k0 + 32 + ac;
                pe1[rr] = *(const uint2*)(Ei + off);
                pe2[rr] = *(const uint2*)(Epp + off);
            }
            pvv = *(const uint4*)(Vb + (size_t)(k0 + 32 + vr) * ND + vch);
        }

        const unsigned* Au = (const unsigned*)As;
        const unsigned* Vu = (const unsigned*)Vt;
#pragma unroll
        for (int kk = 0; kk < 2; kk++) {
            int kb = kk * 16;
            unsigned a[4], bfr[4][2];
            int m = warpM * 16;
            a[0] = Au[((m + g) * 40 + kb + 2 * t) >> 1];
            a[1] = Au[((m + g + 8) * 40 + kb + 2 * t) >> 1];
            a[2] = Au[((m + g) * 40 + kb + 2 * t + 8) >> 1];
            a[3] = Au[((m + g + 8) * 40 + kb + 2 * t + 8) >> 1];
#pragma unroll
            for (int ni = 0; ni < 4; ni++) {
                int n = warpN * 32 + ni * 8;
                bfr[ni][0] = Vu[((n + g) * 34 + kb + 2 * t) >> 1];
                bfr[ni][1] = Vu[((n + g) * 34 + kb + 2 * t + 8) >> 1];
            }
#pragma unroll
            for (int ni = 0; ni < 4; ni++)
                mmah(c4[ni], a, bfr[ni]);
        }
        __syncthreads();
    }
#pragma unroll
    for (int ni = 0; ni < 4; ni++) {
        int row = i0 + warpM * 16 + g;
        int col = warpN * 32 + ni * 8 + 2 * t;
        __half* dst = g_AO + (size_t)(b * NS + row) * ND + h * NDH + col;
        *(__half2*)dst = __floats2half2_rn(c4[ni][0], c4[ni][1]);
        *(__half2*)(dst + (size_t)8 * ND) = __floats2half2_rn(c4[ni][2], c4[ni][3]);
    }
}

// ---------------- launch ----------------
extern "C" void kernel_launch(void* const* d_in, const int* in_sizes, int n_in,
                              void* d_out, int out_size) {
    (void)in_sizes; (void)n_in; (void)out_size;
    const float* inp    = (const float*)d_in[0];
    const float* pos    = (const float*)d_in[1];
    const float* Wq_inp = (const float*)d_in[2];
    const float* Wk_inp = (const float*)d_in[3];
    const float* Wq_pos = (const float*)d_in[4];
    const float* Wk_pos = (const float*)d_in[5];
    const float* Wv     = (const float*)d_in[6];
    const float* Wo     = (const float*)d_in[7];

    float* out      = (float*)d_out;
    float* out_attn = out;
    float* out_prob = out + (size_t)NBAT * NS * ND;

    __half *pAin, *pPin;
    cudaGetSymbolAddress((void**)&pAin, g_Ain);
    cudaGetSymbolAddress((void**)&pPin, g_Pin);

    // side stream + fork/join events (host resources; created once, work per call identical)
    static cudaStream_t s2 = nullptr;
    static cudaEvent_t evFork = nullptr, evJoin = nullptr;
    if (s2 == nullptr) {
        cudaStreamCreateWithFlags(&s2, cudaStreamNonBlocking);
        cudaEventCreateWithFlags(&evFork, cudaEventDisableTiming);
        cudaEventCreateWithFlags(&evJoin, cudaEventDisableTiming);
    }

    conv_h<<<(4096 * 768 / 4 + 255) / 256, 256>>>(inp, pAin, 4096 * 768 / 4);
    conv_h<<<(2048 * 768 / 4 + 255) / 256, 256>>>(pos, pPin, 2048 * 768 / 4);
    {
        dim3 g(24, 24, 6);
        prep_weights<<<g, 256>>>(Wq_inp, Wk_inp, Wq_pos, Wk_pos, Wv, Wo);
    }

    int gemmSmem = 2 * 2 * 128 * 40 * (int)sizeof(__half);   // 40960
    cudaFuncSetAttribute(gemm_proj, cudaFuncAttributeMaxDynamicSharedMemorySize, gemmSmem);
    cudaFuncSetAttribute(gemm_wo,   cudaFuncAttributeMaxDynamicSharedMemorySize, gemmSmem);

    gemm_proj<<<dim3(32, 6, 5), 256, gemmSmem>>>();

    {
        int dynBytes = (128 * 72 + 2 * 64 * 72) * (int)sizeof(__half) + 256 * (int)sizeof(float);
        cudaFuncSetAttribute(score_exp, cudaFuncAttributeMaxDynamicSharedMemorySize, dynBytes);
        score_exp<<<dim3(NS / 128, NH, 3), 256, dynBytes>>>();
    }

    // fork: pv_mma on s2 runs concurrently with blend_kernel on the main stream
    cudaEventRecord(evFork, 0);
    cudaStreamWaitEvent(s2, evFork, 0);

    {
        dim3 g(NS / 64, NBAT, NH);
        pv_mma<<<g, 256, 0, s2>>>();
    }
    {
        dim3 g(NBAT, NS);
        blend_kernel<<<g, 256>>>(out_prob);
    }

    // join: gemm_wo (needs AO from pv_mma) back on main stream
    cudaEventRecord(evJoin, s2);
    cudaStreamWaitEvent(0, evJoin, 0);

    gemm_wo<<<dim3(4096 / 128, 768 / 128, 1), 256, gemmSmem>>>(out_attn);
}

// round 16
// speedup vs baseline: 2.2919x; 1.0093x over previous
#include <cuda_runtime.h>
#include <cuda_fp16.h>
#include <math.h>

#define NS   2048
#define NBAT 2
#define ND   768
#define NH   12
#define NDH  64
static const float SCORE_SCALE = 0.125f;   // 1/sqrt(64) * smoothing

// ---------------- scratch ----------------
__device__ __half g_W6[6][768 * 768];                      // [n][k] fp16: 5 perm'd proj weights + Wo^T
__device__ __half g_Ain[4096 * 768];                       // fp16 inp
__device__ __half g_Pin[2048 * 768];                       // fp16 pos_emb
__device__ __half g_Q [4096 * 768];
__device__ __half g_K [4096 * 768];
__device__ __half g_V [4096 * 768];
__device__ __half g_Qp[2048 * 768];
__device__ __half g_Kp[2048 * 768];
__device__ __half g_Einp[(size_t)2 * 12 * 2048 * 2048];    // exp(scores), fp16
__device__ __half g_Epos[(size_t)12 * 2048 * 2048];
__device__ float g_sumI[2 * 12 * 2048];                    // fp32 row sums
__device__ float g_sumP[12 * 2048];
__device__ __half g_AO[4096 * 768];                        // fp16 attn-out pre-Wo

// ---------------- helpers ----------------
__device__ __forceinline__ void mmah(float c[4], const unsigned a[4], const unsigned b[2]) {
    asm volatile(
        "mma.sync.aligned.m16n8k16.row.col.f32.f16.f16.f32 "
        "{%0,%1,%2,%3},{%4,%5,%6,%7},{%8,%9},{%0,%1,%2,%3};"
        : "+f"(c[0]), "+f"(c[1]), "+f"(c[2]), "+f"(c[3])
        : "r"(a[0]), "r"(a[1]), "r"(a[2]), "r"(a[3]), "r"(b[0]), "r"(b[1]));
}
__device__ __forceinline__ void ldsm4(unsigned r[4], unsigned addr) {
    asm volatile("ldmatrix.sync.aligned.m8n8.x4.shared.b16 {%0,%1,%2,%3}, [%4];"
        : "=r"(r[0]), "=r"(r[1]), "=r"(r[2]), "=r"(r[3]) : "r"(addr));
}
__device__ __forceinline__ void cpa16(unsigned s, const void* g) {
    asm volatile("cp.async.ca.shared.global [%0], [%1], 16;" :: "r"(s), "l"(g));
}
#define CPA_COMMIT asm volatile("cp.async.commit_group;")
#define CPA_WAIT0  asm volatile("cp.async.wait_group 0;")

// ---------------- float -> fp16 convert-copy ----------------
__global__ void conv_h(const float* __restrict__ src, __half* __restrict__ dst, int n4) {
    int i = blockIdx.x * 256 + threadIdx.x;
    if (i >= n4) return;
    float4 v = ((const float4*)src)[i];
    __half2 h0 = __floats2half2_rn(v.x, v.y);
    __half2 h1 = __floats2half2_rn(v.z, v.w);
    uint2 o = make_uint2(*(unsigned*)&h0, *(unsigned*)&h1);
    ((uint2*)dst)[i] = o;
}

// ---------------- weight prep: transpose (+ head permutation) to [n][k] fp16 ----------------
__global__ void prep_weights(const float* __restrict__ W0, const float* __restrict__ W1,
                             const float* __restrict__ W2, const float* __restrict__ W3,
                             const float* __restrict__ W4, const float* __restrict__ W5) {
    __shared__ __half ts[32][33];
    int w = blockIdx.z;
    const float* W = (w == 0) ? W0 : (w == 1) ? W1 : (w == 2) ? W2 : (w == 3) ? W3
                   : (w == 4) ? W4 : W5;
    int k0 = blockIdx.x * 32, j0 = blockIdx.y * 32;
    int tid = threadIdx.x;
    int r = tid >> 5, c = tid & 31;
#pragma unroll
    for (int l = 0; l < 4; l++) {
        int k = k0 + r + l * 8;
        ts[c][r + l * 8] = __float2half_rn(W[(size_t)k * 768 + j0 + c]);
    }
    __syncthreads();
#pragma unroll
    for (int l = 0; l < 4; l++) {
        int j = j0 + r + l * 8;
        int n = (w < 5) ? ((j % 12) * 64 + j / 12) : j;
        g_W6[w][(size_t)n * 768 + k0 + c] = ts[r + l * 8][c];
    }
}

// ---------------- fp16 MMA GEMM core, 128x128 CTA tile, cp.async + ldmatrix ----------------
template <bool HALF_OUT>
__device__ __forceinline__ void gemm_core(const __half* __restrict__ A,
                                          const __half* __restrict__ Bt,
                                          void* __restrict__ Cv, int M) {
    const int N = 768, K = 768;
    extern __shared__ __half smh[];
    __half* As = smh;                  // 2 x 128*40
    __half* Bs = smh + 2 * 128 * 40;   // 2 x 128*40
    int tid = threadIdx.x;
    int lane = tid & 31, wid = tid >> 5;
    int g = lane >> 2, t = lane & 3;
    int warpM = wid >> 2, warpN = wid & 3;        // 2 x 4 warps, 64x32 warp tiles
    int row0 = blockIdx.x * 128, col0 = blockIdx.y * 128;

    float c[4][4][4] = {};
    int lr = tid >> 2, lch = (tid & 3) * 8;

    unsigned sA = (unsigned)__cvta_generic_to_shared(As);
    unsigned sB = (unsigned)__cvta_generic_to_shared(Bs);
    const unsigned bufH = 128 * 40;

    int lane16 = lane & 15, laneHi = lane >> 4;
    unsigned aRel[4], bRel[2];
#pragma unroll
    for (int mi = 0; mi < 4; mi++)
        aRel[mi] = ((warpM * 64 + mi * 16 + lane16) * 40 + laneHi * 8) * 2;
#pragma unroll
    for (int pi = 0; pi < 2; pi++)
        bRel[pi] = ((warpN * 32 + pi * 16 + lane16) * 40 + laneHi * 8) * 2;

#pragma unroll
    for (int l = 0; l < 2; l++) {
        int r = lr + l * 64;
        cpa16(sA + (r * 40 + lch) * 2, A + (size_t)(row0 + r) * K + lch);
        cpa16(sB + (r * 40 + lch) * 2, Bt + (size_t)(col0 + r) * K + lch);
    }
    CPA_COMMIT;

    int buf = 0;
    for (int k0 = 0; k0 < K; k0 += 32, buf ^= 1) {
        CPA_WAIT0;
        __syncthreads();
        if (k0 + 32 < K) {
            unsigned o = (buf ^ 1) ? bufH * 2 : 0u;
#pragma unroll
            for (int l = 0; l < 2; l++) {
                int r = lr + l * 64;
                cpa16(sA + o + (r * 40 + lch) * 2, A + (size_t)(row0 + r) * K + k0 + 32 + lch);
                cpa16(sB + o + (r * 40 + lch) * 2, Bt + (size_t)(col0 + r) * K + k0 + 32 + lch);
            }
            CPA_COMMIT;
        }
        unsigned aBase = sA + (buf ? bufH * 2 : 0u);
        unsigned bBase = sB + (buf ? bufH * 2 : 0u);
#pragma unroll
        for (int kk = 0; kk < 2; kk++) {
            unsigned kbOff = kk * 32;
            unsigned a[4][4], bfr[4][2];
#pragma unroll
            for (int mi = 0; mi < 4; mi++)
                ldsm4(a[mi], aBase + aRel[mi] + kbOff);
#pragma unroll
            for (int pi = 0; pi < 2; pi++) {
                unsigned r4[4];
                ldsm4(r4, bBase + bRel[pi] + kbOff);
                bfr[2 * pi][0] = r4[0]; bfr[2 * pi + 1][0] = r4[1];
                bfr[2 * pi][1] = r4[2]; bfr[2 * pi + 1][1] = r4[3];
            }
#pragma unroll
            for (int mi = 0; mi < 4; mi++)
#pragma unroll
                for (int ni = 0; ni < 4; ni++)
                    mmah(c[mi][ni], a[mi], bfr[ni]);
        }
        __syncthreads();
    }
#pragma unroll
    for (int mi = 0; mi < 4; mi++) {
#pragma unroll
        for (int ni = 0; ni < 4; ni++) {
            int row = row0 + warpM * 64 + mi * 16 + g;
            int col = col0 + warpN * 32 + ni * 8 + 2 * t;
            if (HALF_OUT) {
                __half* C = (__half*)Cv;
                *(__half2*)(C + (size_t)row * N + col) = __floats2half2_rn(c[mi][ni][0], c[mi][ni][1]);
                *(__half2*)(C + (size_t)(row + 8) * N + col) = __floats2half2_rn(c[mi][ni][2], c[mi][ni][3]);
            } else {
                float* C = (float*)Cv;
                *(float2*)(C + (size_t)row * N + col) = make_float2(c[mi][ni][0], c[mi][ni][1]);
                *(float2*)(C + (size_t)(row + 8) * N + col) = make_float2(c[mi][ni][2], c[mi][ni][3]);
            }
        }
    }
}

// Q/K/Qp/Kp projections (z: 0=Q, 1=K, 2=Qp, 3=Kp); pos streams early-exit x>=16
__global__ void __launch_bounds__(256, 2) gemm_projQK() {
    int z = blockIdx.z;
    if (z < 2) {
        gemm_core<true>(g_Ain, g_W6[z], z ? (void*)g_K : (void*)g_Q, 4096);
    } else {
        if (blockIdx.x >= 16) return;
        gemm_core<true>(g_Pin, g_W6[z], (z == 2) ? (void*)g_Qp : (void*)g_Kp, 2048);
    }
}
// V projection (side stream)
__global__ void __launch_bounds__(256, 2) gemm_projV() {
    gemm_core<true>(g_Ain, g_W6[4], g_V, 4096);
}
// Wo GEMM (fp32 out, writes out_attn)
__global__ void __launch_bounds__(256, 2) gemm_wo(float* __restrict__ C) {
    gemm_core<false>(g_AO, g_W6[5], C, 4096);
}

// ---------------- scores: E(fp16) = exp(scale * Q K^T) + fp32 row sums ----------------
__global__ void __launch_bounds__(256) score_exp() {
    extern __shared__ __half smh[];
    __half* Qs = smh;                      // 128*72
    __half* Ks = smh + 128 * 72;           // 2 x 64*72
    float* rbuf = (float*)(Ks + 2 * 64 * 72);
    int tid = threadIdx.x;
    int lane = tid & 31, wid = tid >> 5;
    int g = lane >> 2, t = lane & 3;
    int warpM = wid >> 1, warpN = wid & 1;
    int i0 = blockIdx.x * 128;
    int h = blockIdx.y;
    int z = blockIdx.z;

    const __half *Qg, *Kg;
    __half* E;
    float* sums;
    int plane;
    if (z < 2) {
        Qg = g_Q + (size_t)z * NS * ND;  Kg = g_K + (size_t)z * NS * ND;
        E = g_Einp; sums = g_sumI; plane = z * NH + h;
    } else {
        Qg = g_Qp; Kg = g_Kp;
        E = g_Epos; sums = g_sumP; plane = h;
    }
    const __half* qb = Qg + (size_t)i0 * ND + h * NDH;
    const __half* kb = Kg + h * NDH;
    __half* Ep = E + (size_t)plane * NS * NS;

#pragma unroll
    for (int l = 0; l < 4; l++) {
        int f = tid + l * 256;
        int r = f >> 3, ch = (f & 7) * 8;
        *(uint4*)(Qs + r * 72 + ch) = *(const uint4*)(qb + (size_t)r * ND + ch);
    }

    unsigned sQ = (unsigned)__cvta_generic_to_shared(Qs);
    unsigned sK = (unsigned)__cvta_generic_to_shared(Ks);
    int lane16 = lane & 15, laneHi = lane >> 4;
    unsigned aRel[2], bRel[2];
#pragma unroll
    for (int mi = 0; mi < 2; mi++)
        aRel[mi] = ((warpM * 32 + mi * 16 + lane16) * 72 + laneHi * 8) * 2;
#pragma unroll
    for (int pi = 0; pi < 2; pi++)
        bRel[pi] = ((warpN * 32 + pi * 16 + lane16) * 72 + laneHi * 8) * 2;

#pragma unroll
    for (int l = 0; l < 2; l++) {
        int f = tid + l * 256;
        int r = f >> 3, ch = (f & 7) * 8;
        cpa16(sK + (r * 72 + ch) * 2, kb + (size_t)r * ND + ch);
    }
    CPA_COMMIT;

    float rs[2][2] = {};
    int buf = 0;
    for (int jt = 0; jt < NS; jt += 64, buf ^= 1) {
        CPA_WAIT0;
        __syncthreads();
        if (jt + 64 < NS) {
            unsigned o = (buf ^ 1) ? (unsigned)(64 * 72 * 2) : 0u;
#pragma unroll
            for (int l = 0; l < 2; l++) {
                int f = tid + l * 256;
                int r = f >> 3, ch = (f & 7) * 8;
                cpa16(sK + o + (r * 72 + ch) * 2, kb + (size_t)(jt + 64 + r) * ND + ch);
            }
            CPA_COMMIT;
        }

        float c4[2][4][4] = {};
        unsigned kBase = sK + (buf ? (unsigned)(64 * 72 * 2) : 0u);
#pragma unroll
        for (int kk = 0; kk < 4; kk++) {
            unsigned kbOff = kk * 32;
            unsigned a[2][4], bfr[4][2];
#pragma unroll
            for (int mi = 0; mi < 2; mi++)
                ldsm4(a[mi], sQ + aRel[mi] + kbOff);
#pragma unroll
            for (int pi = 0; pi < 2; pi++) {
                unsigned r4[4];
                ldsm4(r4, kBase + bRel[pi] + kbOff);
                bfr[2 * pi][0] = r4[0]; bfr[2 * pi + 1][0] = r4[1];
                bfr[2 * pi][1] = r4[2]; bfr[2 * pi + 1][1] = r4[3];
            }
#pragma unroll
            for (int mi = 0; mi < 2; mi++)
#pragma unroll
                for (int ni = 0; ni < 4; ni++)
                    mmah(c4[mi][ni], a[mi], bfr[ni]);
        }
#pragma unroll
        for (int mi = 0; mi < 2; mi++) {
#pragma unroll
            for (int ni = 0; ni < 4; ni++) {
                float e0 = __expf(c4[mi][ni][0] * SCORE_SCALE);
                float e1 = __expf(c4[mi][ni][1] * SCORE_SCALE);
                float e2 = __expf(c4[mi][ni][2] * SCORE_SCALE);
                float e3 = __expf(c4[mi][ni][3] * SCORE_SCALE);
                rs[mi][0] += e0 + e1;
                rs[mi][1] += e2 + e3;
                int row = i0 + warpM * 32 + mi * 16 + g;
                int col = jt + warpN * 32 + ni * 8 + 2 * t;
                *(__half2*)(Ep + (size_t)row * NS + col) = __floats2half2_rn(e0, e1);
                *(__half2*)(Ep + (size_t)(row + 8) * NS + col) = __floats2half2_rn(e2, e3);
            }
        }
        __syncthreads();
    }

#pragma unroll
    for (int mi = 0; mi < 2; mi++)
#pragma unroll
        for (int hf = 0; hf < 2; hf++) {
            float v = rs[mi][hf];
            v += __shfl_xor_sync(0xffffffffu, v, 1);
            v += __shfl_xor_sync(0xffffffffu, v, 2);
            rs[mi][hf] = v;
        }
    if (t == 0) {
#pragma unroll
        for (int mi = 0; mi < 2; mi++)
#pragma unroll
            for (int hf = 0; hf < 2; hf++) {
                int r = warpM * 32 + mi * 16 + hf * 8 + g;
                rbuf[r * 2 + warpN] = rs[mi][hf];
            }
    }
    __syncthreads();
    if (tid < 128)
        sums[(size_t)plane * NS + i0 + tid] = rbuf[tid * 2] + rbuf[tid * 2 + 1];
}

// ---------------- blend + interleave into [b][i][j][h] (fp16 E reads) ----------------
__global__ void __launch_bounds__(256) blend_kernel(float* __restrict__ outP) {
    __shared__ float sb[12 * 515];
    __shared__ float sIs[12], sPs[12];
    int b = blockIdx.x, i = blockIdx.y;
    int tid = threadIdx.x;
    if (tid < 12) sIs[tid] = 0.5f / g_sumI[(b * 12 + tid) * NS + i];
    else if (tid < 24) sPs[tid - 12] = 0.5f / g_sumP[(tid - 12) * NS + i];
    __syncthreads();
    size_t outBase = ((size_t)(b * NS + i)) * ((size_t)NS * NH);
    for (int jt = 0; jt < NS; jt += 512) {
#pragma unroll
        for (int l = 0; l < 12; l++) {
            int e = tid + l * 256;
            int h = e >> 8, j2 = e & 255;
            size_t idxI = ((size_t)(b * NH + h) * NS + i) * NS + jt + 2 * j2;
            size_t idxP = ((size_t)h * NS + i) * NS + jt + 2 * j2;
            float2 f1 = __half22float2(*(const __half2*)(g_Einp + idxI));
            float2 f2 = __half22float2(*(const __half2*)(g_Epos + idxP));
            float si = sIs[h], sp = sPs[h];
            sb[h * 515 + 2 * j2]     = f1.x * si + f2.x * sp;
            sb[h * 515 + 2 * j2 + 1] = f1.y * si + f2.y * sp;
        }
        __syncthreads();
#pragma unroll
        for (int l = 0; l < 24; l++) {
            int e = tid + l * 256;
            int j = e / 12, h = e - j * 12;
            outP[outBase + (size_t)jt * NH + e] = sb[h * 515 + j];
        }
        __syncthreads();
    }
}

// ---------------- PV (fp16 MMA): AO(fp16) = blend(P) @ V ----------------
__global__ void __launch_bounds__(256) pv_mma() {
    __shared__ __half As[64 * 40];
    __shared__ __half Vt[64 * 34];
    __shared__ float invI[64], invP[64];
    int tid = threadIdx.x;
    int lane = tid & 31, wid = tid >> 5;
    int g = lane >> 2, t = lane & 3;
    int warpM = wid >> 1, warpN = wid & 1;
    int i0 = blockIdx.x * 64;
    int b = blockIdx.y, h = blockIdx.z;
    int plane = b * NH + h;

    const __half* Ei = g_Einp + (size_t)plane * NS * NS;
    const __half* Epp = g_Epos + (size_t)h * NS * NS;
    const __half* Vb = g_V + (size_t)b * NS * ND + h * NDH;

    if (tid < 64) invI[tid] = 0.5f / g_sumI[(size_t)plane * NS + i0 + tid];
    else if (tid < 128) invP[tid - 64] = 0.5f / g_sumP[(size_t)h * NS + i0 + tid - 64];
    __syncthreads();

    float c4[4][4] = {};
    int ar = tid >> 3, ac = (tid & 7) * 4;
    int vr = tid >> 3, vch = (tid & 7) * 8;

    uint2 pe1[2], pe2[2];
    uint4 pvv;
#pragma unroll
    for (int rr = 0; rr < 2; rr++) {
        size_t off = (size_t)(i0 + ar + rr * 32) * NS + ac;
        pe1[rr] = *(const uint2*)(Ei + off);
        pe2[rr] = *(const uint2*)(Epp + off);
    }
    pvv = *(const uint4*)(Vb + (size_t)vr * ND + vch);

    for (int k0 = 0; k0 < NS; k0 += 32) {
#pragma unroll
        for (int rr = 0; rr < 2; rr++) {
            int r = ar + rr * 32;
            float si = invI[r], sp = invP[r];
            float2 a0 = __half22float2(*(__half2*)&pe1[rr].x);
            float2 a1 = __half22float2(*(__half2*)&pe1[rr].y);
            float2 b0 = __half22float2(*(__half2*)&pe2[rr].x);
            float2 b1 = __half22float2(*(__half2*)&pe2[rr].y);
            __half2 h0 = __floats2half2_rn(a0.x * si + b0.x * sp, a0.y * si + b0.y * sp);
            __half2 h1 = __floats2half2_rn(a1.x * si + b1.x * sp, a1.y * si + b1.y * sp);
            *(uint2*)(As + r * 40 + ac) = make_uint2(*(unsigned*)&h0, *(unsigned*)&h1);
        }
        {
            const __half* hp = (const __half*)&pvv;
#pragma unroll
            for (int i = 0; i < 8; i++)
                Vt[(vch + i) * 34 + vr] = hp[i];
        }
        __syncthreads();

        if (k0 + 32 < NS) {
#pragma unroll
            for (int rr = 0; rr < 2; rr++) {
                size_t off = (size_t)(i0 + ar + rr * 32) * NS + k0 + 32 + ac;
                pe1[rr] = *(const uint2*)(Ei + off);
                pe2[rr] = *(const uint2*)(Epp + off);
            }
            pvv = *(const uint4*)(Vb + (size_t)(k0 + 32 + vr) * ND + vch);
        }

        const unsigned* Au = (const unsigned*)As;
        const unsigned* Vu = (const unsigned*)Vt;
#pragma unroll
        for (int kk = 0; kk < 2; kk++) {
            int kb = kk * 16;
            unsigned a[4], bfr[4][2];
            int m = warpM * 16;
            a[0] = Au[((m + g) * 40 + kb + 2 * t) >> 1];
            a[1] = Au[((m + g + 8) * 40 + kb + 2 * t) >> 1];
            a[2] = Au[((m + g) * 40 + kb + 2 * t + 8) >> 1];
            a[3] = Au[((m + g + 8) * 40 + kb + 2 * t + 8) >> 1];
#pragma unroll
            for (int ni = 0; ni < 4; ni++) {
                int n = warpN * 32 + ni * 8;
                bfr[ni][0] = Vu[((n + g) * 34 + kb + 2 * t) >> 1];
                bfr[ni][1] = Vu[((n + g) * 34 + kb + 2 * t + 8) >> 1];
            }
#pragma unroll
            for (int ni = 0; ni < 4; ni++)
                mmah(c4[ni], a, bfr[ni]);
        }
        __syncthreads();
    }
#pragma unroll
    for (int ni = 0; ni < 4; ni++) {
        int row = i0 + warpM * 16 + g;
        int col = warpN * 32 + ni * 8 + 2 * t;
        __half* dst = g_AO + (size_t)(b * NS + row) * ND + h * NDH + col;
        *(__half2*)dst = __floats2half2_rn(c4[ni][0], c4[ni][1]);
        *(__half2*)(dst + (size_t)8 * ND) = __floats2half2_rn(c4[ni][2], c4[ni][3]);
    }
}

// ---------------- launch ----------------
extern "C" void kernel_launch(void* const* d_in, const int* in_sizes, int n_in,
                              void* d_out, int out_size) {
    (void)in_sizes; (void)n_in; (void)out_size;
    const float* inp    = (const float*)d_in[0];
    const float* pos    = (const float*)d_in[1];
    const float* Wq_inp = (const float*)d_in[2];
    const float* Wk_inp = (const float*)d_in[3];
    const float* Wq_pos = (const float*)d_in[4];
    const float* Wk_pos = (const float*)d_in[5];
    const float* Wv     = (const float*)d_in[6];
    const float* Wo     = (const float*)d_in[7];

    float* out      = (float*)d_out;
    float* out_attn = out;
    float* out_prob = out + (size_t)NBAT * NS * ND;

    __half *pAin, *pPin;
    cudaGetSymbolAddress((void**)&pAin, g_Ain);
    cudaGetSymbolAddress((void**)&pPin, g_Pin);

    // side stream + events (host resources; created once, per-call work identical)
    static cudaStream_t s2 = nullptr;
    static cudaEvent_t evPrep = nullptr, evScore = nullptr, evJoin = nullptr;
    if (s2 == nullptr) {
        cudaStreamCreateWithFlags(&s2, cudaStreamNonBlocking);
        cudaEventCreateWithFlags(&evPrep,  cudaEventDisableTiming);
        cudaEventCreateWithFlags(&evScore, cudaEventDisableTiming);
        cudaEventCreateWithFlags(&evJoin,  cudaEventDisableTiming);
    }

    conv_h<<<(4096 * 768 / 4 + 255) / 256, 256>>>(inp, pAin, 4096 * 768 / 4);
    conv_h<<<(2048 * 768 / 4 + 255) / 256, 256>>>(pos, pPin, 2048 * 768 / 4);
    {
        dim3 g(24, 24, 6);
        prep_weights<<<g, 256>>>(Wq_inp, Wk_inp, Wq_pos, Wk_pos, Wv, Wo);
    }

    int gemmSmem = 2 * 2 * 128 * 40 * (int)sizeof(__half);   // 40960
    cudaFuncSetAttribute(gemm_projQK, cudaFuncAttributeMaxDynamicSharedMemorySize, gemmSmem);
    cudaFuncSetAttribute(gemm_projV,  cudaFuncAttributeMaxDynamicSharedMemorySize, gemmSmem);
    cudaFuncSetAttribute(gemm_wo,     cudaFuncAttributeMaxDynamicSharedMemorySize, gemmSmem);

    // fork 1: V projection on s2, concurrent with QK projections + score
    cudaEventRecord(evPrep, 0);
    cudaStreamWaitEvent(s2, evPrep, 0);
    gemm_projV<<<dim3(32, 6, 1), 256, gemmSmem, s2>>>();

    gemm_projQK<<<dim3(32, 6, 4), 256, gemmSmem>>>();

    {
        int dynBytes = (128 * 72 + 2 * 64 * 72) * (int)sizeof(__half) + 256 * (int)sizeof(float);
        cudaFuncSetAttribute(score_exp, cudaFuncAttributeMaxDynamicSharedMemorySize, dynBytes);
        score_exp<<<dim3(NS / 128, NH, 3), 256, dynBytes>>>();
    }

    // fork 2: pv + wo chain on s2 (after score), concurrent with blend on main
    cudaEventRecord(evScore, 0);
    cudaStreamWaitEvent(s2, evScore, 0);

    {
        dim3 g(NS / 64, NBAT, NH);
        pv_mma<<<g, 256, 0, s2>>>();
    }
    gemm_wo<<<dim3(4096 / 128, 768 / 128, 1), 256, gemmSmem, s2>>>(out_attn);

    {
        dim3 g(NBAT, NS);
        blend_kernel<<<g, 256>>>(out_prob);
    }

    // join
    cudaEventRecord(evJoin, s2);
    cudaStreamWaitEvent(0, evJoin, 0);
}

// round 17
// speedup vs baseline: 2.3439x; 1.0227x over previous
#include <cuda_runtime.h>
#include <cuda_fp16.h>
#include <math.h>

#define NS   2048
#define NBAT 2
#define ND   768
#define NH   12
#define NDH  64
static const float SCORE_SCALE = 0.125f;   // 1/sqrt(64) * smoothing

// ---------------- scratch ----------------
__device__ __half g_W6[6][768 * 768];                      // [n][k] fp16: 5 perm'd proj weights + Wo^T
__device__ __half g_Ain[4096 * 768];                       // fp16 inp
__device__ __half g_Pin[2048 * 768];                       // fp16 pos_emb
__device__ __half g_Q [4096 * 768];
__device__ __half g_K [4096 * 768];
__device__ __half g_V [4096 * 768];
__device__ __half g_Qp[2048 * 768];
__device__ __half g_Kp[2048 * 768];
__device__ __half g_Einp[(size_t)2 * 12 * 2048 * 2048];    // exp(scores), fp16
__device__ __half g_Epos[(size_t)12 * 2048 * 2048];
__device__ float g_sumI[2 * 12 * 2048];                    // fp32 row sums
__device__ float g_sumP[12 * 2048];
__device__ __half g_AO[4096 * 768];                        // fp16 attn-out pre-Wo

// ---------------- helpers ----------------
__device__ __forceinline__ void mmah(float c[4], const unsigned a[4], const unsigned b[2]) {
    asm volatile(
        "mma.sync.aligned.m16n8k16.row.col.f32.f16.f16.f32 "
        "{%0,%1,%2,%3},{%4,%5,%6,%7},{%8,%9},{%0,%1,%2,%3};"
        : "+f"(c[0]), "+f"(c[1]), "+f"(c[2]), "+f"(c[3])
        : "r"(a[0]), "r"(a[1]), "r"(a[2]), "r"(a[3]), "r"(b[0]), "r"(b[1]));
}
__device__ __forceinline__ void ldsm4(unsigned r[4], unsigned addr) {
    asm volatile("ldmatrix.sync.aligned.m8n8.x4.shared.b16 {%0,%1,%2,%3}, [%4];"
        : "=r"(r[0]), "=r"(r[1]), "=r"(r[2]), "=r"(r[3]) : "r"(addr));
}
__device__ __forceinline__ void cpa16(unsigned s, const void* g) {
    asm volatile("cp.async.ca.shared.global [%0], [%1], 16;" :: "r"(s), "l"(g));
}
#define CPA_COMMIT asm volatile("cp.async.commit_group;")
#define CPA_WAIT0  asm volatile("cp.async.wait_group 0;")

// ---------------- float -> fp16 convert-copy ----------------
__global__ void conv_h(const float* __restrict__ src, __half* __restrict__ dst, int n4) {
    int i = blockIdx.x * 256 + threadIdx.x;
    if (i >= n4) return;
    float4 v = ((const float4*)src)[i];
    __half2 h0 = __floats2half2_rn(v.x, v.y);
    __half2 h1 = __floats2half2_rn(v.z, v.w);
    uint2 o = make_uint2(*(unsigned*)&h0, *(unsigned*)&h1);
    ((uint2*)dst)[i] = o;
}

// ---------------- weight prep: transpose (+ head permutation) to [n][k] fp16 ----------------
__global__ void prep_weights(const float* __restrict__ W0, const float* __restrict__ W1,
                             const float* __restrict__ W2, const float* __restrict__ W3,
                             const float* __restrict__ W4, const float* __restrict__ W5) {
    __shared__ __half ts[32][33];
    int w = blockIdx.z;
    const float* W = (w == 0) ? W0 : (w == 1) ? W1 : (w == 2) ? W2 : (w == 3) ? W3
                   : (w == 4) ? W4 : W5;
    int k0 = blockIdx.x * 32, j0 = blockIdx.y * 32;
    int tid = threadIdx.x;
    int r = tid >> 5, c = tid & 31;
#pragma unroll
    for (int l = 0; l < 4; l++) {
        int k = k0 + r + l * 8;
        ts[c][r + l * 8] = __float2half_rn(W[(size_t)k * 768 + j0 + c]);
    }
    __syncthreads();
#pragma unroll
    for (int l = 0; l < 4; l++) {
        int j = j0 + r + l * 8;
        int n = (w < 5) ? ((j % 12) * 64 + j / 12) : j;
        g_W6[w][(size_t)n * 768 + k0 + c] = ts[r + l * 8][c];
    }
}

// ---------------- fp16 MMA GEMM core, 128x128 CTA tile, cp.async + ldmatrix ----------------
template <bool HALF_OUT>
__device__ __forceinline__ void gemm_core(const __half* __restrict__ A,
                                          const __half* __restrict__ Bt,
                                          void* __restrict__ Cv, int M) {
    const int N = 768, K = 768;
    extern __shared__ __half smh[];
    __half* As = smh;                  // 2 x 128*40
    __half* Bs = smh + 2 * 128 * 40;   // 2 x 128*40
    int tid = threadIdx.x;
    int lane = tid & 31, wid = tid >> 5;
    int g = lane >> 2, t = lane & 3;
    int warpM = wid >> 2, warpN = wid & 3;        // 2 x 4 warps, 64x32 warp tiles
    int row0 = blockIdx.x * 128, col0 = blockIdx.y * 128;

    float c[4][4][4] = {};
    int lr = tid >> 2, lch = (tid & 3) * 8;

    unsigned sA = (unsigned)__cvta_generic_to_shared(As);
    unsigned sB = (unsigned)__cvta_generic_to_shared(Bs);
    const unsigned bufH = 128 * 40;

    int lane16 = lane & 15, laneHi = lane >> 4;
    unsigned aRel[4], bRel[2];
#pragma unroll
    for (int mi = 0; mi < 4; mi++)
        aRel[mi] = ((warpM * 64 + mi * 16 + lane16) * 40 + laneHi * 8) * 2;
#pragma unroll
    for (int pi = 0; pi < 2; pi++)
        bRel[pi] = ((warpN * 32 + pi * 16 + lane16) * 40 + laneHi * 8) * 2;

#pragma unroll
    for (int l = 0; l < 2; l++) {
        int r = lr + l * 64;
        cpa16(sA + (r * 40 + lch) * 2, A + (size_t)(row0 + r) * K + lch);
        cpa16(sB + (r * 40 + lch) * 2, Bt + (size_t)(col0 + r) * K + lch);
    }
    CPA_COMMIT;

    int buf = 0;
    for (int k0 = 0; k0 < K; k0 += 32, buf ^= 1) {
        CPA_WAIT0;
        __syncthreads();
        if (k0 + 32 < K) {
            unsigned o = (buf ^ 1) ? bufH * 2 : 0u;
#pragma unroll
            for (int l = 0; l < 2; l++) {
                int r = lr + l * 64;
                cpa16(sA + o + (r * 40 + lch) * 2, A + (size_t)(row0 + r) * K + k0 + 32 + lch);
                cpa16(sB + o + (r * 40 + lch) * 2, Bt + (size_t)(col0 + r) * K + k0 + 32 + lch);
            }
            CPA_COMMIT;
        }
        unsigned aBase = sA + (buf ? bufH * 2 : 0u);
        unsigned bBase = sB + (buf ? bufH * 2 : 0u);
#pragma unroll
        for (int kk = 0; kk < 2; kk++) {
            unsigned kbOff = kk * 32;
            unsigned a[4][4], bfr[4][2];
#pragma unroll
            for (int mi = 0; mi < 4; mi++)
                ldsm4(a[mi], aBase + aRel[mi] + kbOff);
#pragma unroll
            for (int pi = 0; pi < 2; pi++) {
                unsigned r4[4];
                ldsm4(r4, bBase + bRel[pi] + kbOff);
                bfr[2 * pi][0] = r4[0]; bfr[2 * pi + 1][0] = r4[1];
                bfr[2 * pi][1] = r4[2]; bfr[2 * pi + 1][1] = r4[3];
            }
#pragma unroll
            for (int mi = 0; mi < 4; mi++)
#pragma unroll
                for (int ni = 0; ni < 4; ni++)
                    mmah(c[mi][ni], a[mi], bfr[ni]);
        }
        __syncthreads();
    }
#pragma unroll
    for (int mi = 0; mi < 4; mi++) {
#pragma unroll
        for (int ni = 0; ni < 4; ni++) {
            int row = row0 + warpM * 64 + mi * 16 + g;
            int col = col0 + warpN * 32 + ni * 8 + 2 * t;
            if (HALF_OUT) {
                __half* C = (__half*)Cv;
                *(__half2*)(C + (size_t)row * N + col) = __floats2half2_rn(c[mi][ni][0], c[mi][ni][1]);
                *(__half2*)(C + (size_t)(row + 8) * N + col) = __floats2half2_rn(c[mi][ni][2], c[mi][ni][3]);
            } else {
                float* C = (float*)Cv;
                *(float2*)(C + (size_t)row * N + col) = make_float2(c[mi][ni][0], c[mi][ni][1]);
                *(float2*)(C + (size_t)(row + 8) * N + col) = make_float2(c[mi][ni][2], c[mi][ni][3]);
            }
        }
    }
}

// Q/K/Qp/Kp projections (z: 0=Q, 1=K, 2=Qp, 3=Kp); pos streams early-exit x>=16
__global__ void __launch_bounds__(256, 2) gemm_projQK() {
    int z = blockIdx.z;
    if (z < 2) {
        gemm_core<true>(g_Ain, g_W6[z], z ? (void*)g_K : (void*)g_Q, 4096);
    } else {
        if (blockIdx.x >= 16) return;
        gemm_core<true>(g_Pin, g_W6[z], (z == 2) ? (void*)g_Qp : (void*)g_Kp, 2048);
    }
}
__global__ void __launch_bounds__(256, 2) gemm_projV() {
    gemm_core<true>(g_Ain, g_W6[4], g_V, 4096);
}
__global__ void __launch_bounds__(256, 2) gemm_wo(float* __restrict__ C) {
    gemm_core<false>(g_AO, g_W6[5], C, 4096);
}

// ---------------- scores: E(fp16) = exp(scale * Q K^T) + fp32 row sums ----------------
__global__ void __launch_bounds__(256) score_exp(int iBase) {
    extern __shared__ __half smh[];
    __half* Qs = smh;                      // 128*72
    __half* Ks = smh + 128 * 72;           // 2 x 64*72
    float* rbuf = (float*)(Ks + 2 * 64 * 72);
    int tid = threadIdx.x;
    int lane = tid & 31, wid = tid >> 5;
    int g = lane >> 2, t = lane & 3;
    int warpM = wid >> 1, warpN = wid & 1;
    int i0 = iBase + blockIdx.x * 128;
    int h = blockIdx.y;
    int z = blockIdx.z;

    const __half *Qg, *Kg;
    __half* E;
    float* sums;
    int plane;
    if (z < 2) {
        Qg = g_Q + (size_t)z * NS * ND;  Kg = g_K + (size_t)z * NS * ND;
        E = g_Einp; sums = g_sumI; plane = z * NH + h;
    } else {
        Qg = g_Qp; Kg = g_Kp;
        E = g_Epos; sums = g_sumP; plane = h;
    }
    const __half* qb = Qg + (size_t)i0 * ND + h * NDH;
    const __half* kb = Kg + h * NDH;
    __half* Ep = E + (size_t)plane * NS * NS;

#pragma unroll
    for (int l = 0; l < 4; l++) {
        int f = tid + l * 256;
        int r = f >> 3, ch = (f & 7) * 8;
        *(uint4*)(Qs + r * 72 + ch) = *(const uint4*)(qb + (size_t)r * ND + ch);
    }

    unsigned sQ = (unsigned)__cvta_generic_to_shared(Qs);
    unsigned sK = (unsigned)__cvta_generic_to_shared(Ks);
    int lane16 = lane & 15, laneHi = lane >> 4;
    unsigned aRel[2], bRel[2];
#pragma unroll
    for (int mi = 0; mi < 2; mi++)
        aRel[mi] = ((warpM * 32 + mi * 16 + lane16) * 72 + laneHi * 8) * 2;
#pragma unroll
    for (int pi = 0; pi < 2; pi++)
        bRel[pi] = ((warpN * 32 + pi * 16 + lane16) * 72 + laneHi * 8) * 2;

#pragma unroll
    for (int l = 0; l < 2; l++) {
        int f = tid + l * 256;
        int r = f >> 3, ch = (f & 7) * 8;
        cpa16(sK + (r * 72 + ch) * 2, kb + (size_t)r * ND + ch);
    }
    CPA_COMMIT;

    float rs[2][2] = {};
    int buf = 0;
    for (int jt = 0; jt < NS; jt += 64, buf ^= 1) {
        CPA_WAIT0;
        __syncthreads();
        if (jt + 64 < NS) {
            unsigned o = (buf ^ 1) ? (unsigned)(64 * 72 * 2) : 0u;
#pragma unroll
            for (int l = 0; l < 2; l++) {
                int f = tid + l * 256;
                int r = f >> 3, ch = (f & 7) * 8;
                cpa16(sK + o + (r * 72 + ch) * 2, kb + (size_t)(jt + 64 + r) * ND + ch);
            }
            CPA_COMMIT;
        }

        float c4[2][4][4] = {};
        unsigned kBase = sK + (buf ? (unsigned)(64 * 72 * 2) : 0u);
#pragma unroll
        for (int kk = 0; kk < 4; kk++) {
            unsigned kbOff = kk * 32;
            unsigned a[2][4], bfr[4][2];
#pragma unroll
            for (int mi = 0; mi < 2; mi++)
                ldsm4(a[mi], sQ + aRel[mi] + kbOff);
#pragma unroll
            for (int pi = 0; pi < 2; pi++) {
                unsigned r4[4];
                ldsm4(r4, kBase + bRel[pi] + kbOff);
                bfr[2 * pi][0] = r4[0]; bfr[2 * pi + 1][0] = r4[1];
                bfr[2 * pi][1] = r4[2]; bfr[2 * pi + 1][1] = r4[3];
            }
#pragma unroll
            for (int mi = 0; mi < 2; mi++)
#pragma unroll
                for (int ni = 0; ni < 4; ni++)
                    mmah(c4[mi][ni], a[mi], bfr[ni]);
        }
#pragma unroll
        for (int mi = 0; mi < 2; mi++) {
#pragma unroll
            for (int ni = 0; ni < 4; ni++) {
                float e0 = __expf(c4[mi][ni][0] * SCORE_SCALE);
                float e1 = __expf(c4[mi][ni][1] * SCORE_SCALE);
                float e2 = __expf(c4[mi][ni][2] * SCORE_SCALE);
                float e3 = __expf(c4[mi][ni][3] * SCORE_SCALE);
                rs[mi][0] += e0 + e1;
                rs[mi][1] += e2 + e3;
                int row = i0 + warpM * 32 + mi * 16 + g;
                int col = jt + warpN * 32 + ni * 8 + 2 * t;
                *(__half2*)(Ep + (size_t)row * NS + col) = __floats2half2_rn(e0, e1);
                *(__half2*)(Ep + (size_t)(row + 8) * NS + col) = __floats2half2_rn(e2, e3);
            }
        }
        __syncthreads();
    }

#pragma unroll
    for (int mi = 0; mi < 2; mi++)
#pragma unroll
        for (int hf = 0; hf < 2; hf++) {
            float v = rs[mi][hf];
            v += __shfl_xor_sync(0xffffffffu, v, 1);
            v += __shfl_xor_sync(0xffffffffu, v, 2);
            rs[mi][hf] = v;
        }
    if (t == 0) {
#pragma unroll
        for (int mi = 0; mi < 2; mi++)
#pragma unroll
            for (int hf = 0; hf < 2; hf++) {
                int r = warpM * 32 + mi * 16 + hf * 8 + g;
                rbuf[r * 2 + warpN] = rs[mi][hf];
            }
    }
    __syncthreads();
    if (tid < 128)
        sums[(size_t)plane * NS + i0 + tid] = rbuf[tid * 2] + rbuf[tid * 2 + 1];
}

// ---------------- blend + interleave into [b][i][j][h] (fp16 E reads) ----------------
__global__ void __launch_bounds__(256) blend_kernel(float* __restrict__ outP, int iBase) {
    __shared__ float sb[12 * 515];
    __shared__ float sIs[12], sPs[12];
    int b = blockIdx.x, i = iBase + blockIdx.y;
    int tid = threadIdx.x;
    if (tid < 12) sIs[tid] = 0.5f / g_sumI[(b * 12 + tid) * NS + i];
    else if (tid < 24) sPs[tid - 12] = 0.5f / g_sumP[(tid - 12) * NS + i];
    __syncthreads();
    size_t outBase = ((size_t)(b * NS + i)) * ((size_t)NS * NH);
    for (int jt = 0; jt < NS; jt += 512) {
#pragma unroll
        for (int l = 0; l < 12; l++) {
            int e = tid + l * 256;
            int h = e >> 8, j2 = e & 255;
            size_t idxI = ((size_t)(b * NH + h) * NS + i) * NS + jt + 2 * j2;
            size_t idxP = ((size_t)h * NS + i) * NS + jt + 2 * j2;
            float2 f1 = __half22float2(*(const __half2*)(g_Einp + idxI));
            float2 f2 = __half22float2(*(const __half2*)(g_Epos + idxP));
            float si = sIs[h], sp = sPs[h];
            sb[h * 515 + 2 * j2]     = f1.x * si + f2.x * sp;
            sb[h * 515 + 2 * j2 + 1] = f1.y * si + f2.y * sp;
        }
        __syncthreads();
#pragma unroll
        for (int l = 0; l < 24; l++) {
            int e = tid + l * 256;
            int j = e / 12, h = e - j * 12;
            outP[outBase + (size_t)jt * NH + e] = sb[h * 515 + j];
        }
        __syncthreads();
    }
}

// ---------------- PV (fp16 MMA): AO(fp16) = blend(P) @ V ----------------
__global__ void __launch_bounds__(256) pv_mma(int iBase) {
    __shared__ __half As[64 * 40];
    __shared__ __half Vt[64 * 34];
    __shared__ float invI[64], invP[64];
    int tid = threadIdx.x;
    int lane = tid & 31, wid = tid >> 5;
    int g = lane >> 2, t = lane & 3;
    int warpM = wid >> 1, warpN = wid & 1;
    int i0 = iBase + blockIdx.x * 64;
    int b = blockIdx.y, h = blockIdx.z;
    int plane = b * NH + h;

    const __half* Ei = g_Einp + (size_t)plane * NS * NS;
    const __half* Epp = g_Epos + (size_t)h * NS * NS;
    const __half* Vb = g_V + (size_t)b * NS * ND + h * NDH;

    if (tid < 64) invI[tid] = 0.5f / g_sumI[(size_t)plane * NS + i0 + tid];
    else if (tid < 128) invP[tid - 64] = 0.5f / g_sumP[(size_t)h * NS + i0 + tid - 64];
    __syncthreads();

    float c4[4][4] = {};
    int ar = tid >> 3, ac = (tid & 7) * 4;
    int vr = tid >> 3, vch = (tid & 7) * 8;

    uint2 pe1[2], pe2[2];
    uint4 pvv;
#pragma unroll
    for (int rr = 0; rr < 2; rr++) {
        size_t off = (size_t)(i0 + ar + rr * 32) * NS + ac;
        pe1[rr] = *(const uint2*)(Ei + off);
        pe2[rr] = *(const uint2*)(Epp + off);
    }
    pvv = *(const uint4*)(Vb + (size_t)vr * ND + vch);

    for (int k0 = 0; k0 < NS; k0 += 32) {
#pragma unroll
        for (int rr = 0; rr < 2; rr++) {
            int r = ar + rr * 32;
            float si = invI[r], sp = invP[r];
            float2 a0 = __half22float2(*(__half2*)&pe1[rr].x);
            float2 a1 = __half22float2(*(__half2*)&pe1[rr].y);
            float2 b0 = __half22float2(*(__half2*)&pe2[rr].x);
            float2 b1 = __half22float2(*(__half2*)&pe2[rr].y);
            __half2 h0 = __floats2half2_rn(a0.x * si + b0.x * sp, a0.y * si + b0.y * sp);
            __half2 h1 = __floats2half2_rn(a1.x * si + b1.x * sp, a1.y * si + b1.y * sp);
            *(uint2*)(As + r * 40 + ac) = make_uint2(*(unsigned*)&h0, *(unsigned*)&h1);
        }
        {
            const __half* hp = (const __half*)&pvv;
#pragma unroll
            for (int i = 0; i < 8; i++)
                Vt[(vch + i) * 34 + vr] = hp[i];
        }
        __syncthreads();

        if (k0 + 32 < NS) {
#pragma unroll
            for (int rr = 0; rr < 2; rr++) {
                size_t off = (size_t)(i0 + ar + rr * 32) * NS + k0 + 32 + ac;
                pe1[rr] = *(const uint2*)(Ei + off);
                pe2[rr] = *(const uint2*)(Epp + off);
            }
            pvv = *(const uint4*)(Vb + (size_t)(k0 + 32 + vr) * ND + vch);
        }

        const unsigned* Au = (const unsigned*)As;
        const unsigned* Vu = (const unsigned*)Vt;
#pragma unroll
        for (int kk = 0; kk < 2; kk++) {
            int kb = kk * 16;
            unsigned a[4], bfr[4][2];
            int m = warpM * 16;
            a[0] = Au[((m + g) * 40 + kb + 2 * t) >> 1];
            a[1] = Au[((m + g + 8) * 40 + kb + 2 * t) >> 1];
            a[2] = Au[((m + g) * 40 + kb + 2 * t + 8) >> 1];
            a[3] = Au[((m + g + 8) * 40 + kb + 2 * t + 8) >> 1];
#pragma unroll
            for (int ni = 0; ni < 4; ni++) {
                int n = warpN * 32 + ni * 8;
                bfr[ni][0] = Vu[((n + g) * 34 + kb + 2 * t) >> 1];
                bfr[ni][1] = Vu[((n + g) * 34 + kb + 2 * t + 8) >> 1];
            }
#pragma unroll
            for (int ni = 0; ni < 4; ni++)
                mmah(c4[ni], a, bfr[ni]);
        }
        __syncthreads();
    }
#pragma unroll
    for (int ni = 0; ni < 4; ni++) {
        int row = i0 + warpM * 16 + g;
        int col = warpN * 32 + ni * 8 + 2 * t;
        __half* dst = g_AO + (size_t)(b * NS + row) * ND + h * NDH + col;
        *(__half2*)dst = __floats2half2_rn(c4[ni][0], c4[ni][1]);
        *(__half2*)(dst + (size_t)8 * ND) = __floats2half2_rn(c4[ni][2], c4[ni][3]);
    }
}

// ---------------- launch ----------------
extern "C" void kernel_launch(void* const* d_in, const int* in_sizes, int n_in,
                              void* d_out, int out_size) {
    (void)in_sizes; (void)n_in; (void)out_size;
    const float* inp    = (const float*)d_in[0];
    const float* pos    = (const float*)d_in[1];
    const float* Wq_inp = (const float*)d_in[2];
    const float* Wk_inp = (const float*)d_in[3];
    const float* Wq_pos = (const float*)d_in[4];
    const float* Wk_pos = (const float*)d_in[5];
    const float* Wv     = (const float*)d_in[6];
    const float* Wo     = (const float*)d_in[7];

    float* out      = (float*)d_out;
    float* out_attn = out;
    float* out_prob = out + (size_t)NBAT * NS * ND;

    __half *pAin, *pPin;
    cudaGetSymbolAddress((void**)&pAin, g_Ain);
    cudaGetSymbolAddress((void**)&pPin, g_Pin);

    // streams + events (host resources; created once, per-call work identical)
    static cudaStream_t s2 = nullptr, s3 = nullptr;
    static cudaEvent_t evPrep = nullptr, ev1 = nullptr, ev2 = nullptr,
                       evJ2 = nullptr, evJ3 = nullptr;
    if (s2 == nullptr) {
        cudaStreamCreateWithFlags(&s2, cudaStreamNonBlocking);
        cudaStreamCreateWithFlags(&s3, cudaStreamNonBlocking);
        cudaEventCreateWithFlags(&evPrep, cudaEventDisableTiming);
        cudaEventCreateWithFlags(&ev1,    cudaEventDisableTiming);
        cudaEventCreateWithFlags(&ev2,    cudaEventDisableTiming);
        cudaEventCreateWithFlags(&evJ2,   cudaEventDisableTiming);
        cudaEventCreateWithFlags(&evJ3,   cudaEventDisableTiming);
    }

    conv_h<<<(4096 * 768 / 4 + 255) / 256, 256>>>(inp, pAin, 4096 * 768 / 4);
    conv_h<<<(2048 * 768 / 4 + 255) / 256, 256>>>(pos, pPin, 2048 * 768 / 4);
    {
        dim3 g(24, 24, 6);
        prep_weights<<<g, 256>>>(Wq_inp, Wk_inp, Wq_pos, Wk_pos, Wv, Wo);
    }

    int gemmSmem = 2 * 2 * 128 * 40 * (int)sizeof(__half);   // 40960
    cudaFuncSetAttribute(gemm_projQK, cudaFuncAttributeMaxDynamicSharedMemorySize, gemmSmem);
    cudaFuncSetAttribute(gemm_projV,  cudaFuncAttributeMaxDynamicSharedMemorySize, gemmSmem);
    cudaFuncSetAttribute(gemm_wo,     cudaFuncAttributeMaxDynamicSharedMemorySize, gemmSmem);

    // V projection on s2 (after prep), concurrent with QK projections + score
    cudaEventRecord(evPrep, 0);
    cudaStreamWaitEvent(s2, evPrep, 0);
    gemm_projV<<<dim3(32, 6, 1), 256, gemmSmem, s2>>>();

    gemm_projQK<<<dim3(32, 6, 4), 256, gemmSmem>>>();

    int scoreSmem = (128 * 72 + 2 * 64 * 72) * (int)sizeof(__half) + 256 * (int)sizeof(float);
    cudaFuncSetAttribute(score_exp, cudaFuncAttributeMaxDynamicSharedMemorySize, scoreSmem);

    // score half 1 (i in [0,1024))
    score_exp<<<dim3(8, NH, 3), 256, scoreSmem>>>(0);
    cudaEventRecord(ev1, 0);
    // score half 2 (i in [1024,2048))
    score_exp<<<dim3(8, NH, 3), 256, scoreSmem>>>(1024);
    cudaEventRecord(ev2, 0);

    // s2: pv halves then wo
    cudaStreamWaitEvent(s2, ev1, 0);
    pv_mma<<<dim3(16, NBAT, NH), 256, 0, s2>>>(0);
    cudaStreamWaitEvent(s2, ev2, 0);
    pv_mma<<<dim3(16, NBAT, NH), 256, 0, s2>>>(1024);
    gemm_wo<<<dim3(4096 / 128, 768 / 128, 1), 256, gemmSmem, s2>>>(out_attn);
    cudaEventRecord(evJ2, s2);

    // s3: blend halves
    cudaStreamWaitEvent(s3, ev1, 0);
    blend_kernel<<<dim3(NBAT, 1024), 256, 0, s3>>>(out_prob, 0);
    cudaStreamWaitEvent(s3, ev2, 0);
    blend_kernel<<<dim3(NBAT, 1024), 256, 0, s3>>>(out_prob, 1024);
    cudaEventRecord(evJ3, s3);

    // join both side streams back to main
    cudaStreamWaitEvent(0, evJ2, 0);
    cudaStreamWaitEvent(0, evJ3, 0);
}